// round 3
// baseline (speedup 1.0000x reference)
#include <cuda_runtime.h>
#include <cstdint>

// Problem constants (fixed shapes)
#define BATCH 16
#define SEQ   2048
#define DIM   256
#define ATTN_SCALE 0.0625f   // 1/sqrt(256)

// GEMM tiling
#define BM 128
#define BN 128
#define BK 16
#define SKA 17    // As row stride in float2 units (BK + 1 pad)
#define SNB 130   // Bs row stride in float2 units (BN + 2 pad)

__device__ __forceinline__ unsigned f2u(float x) { return __float_as_uint(x); }

// Round f32 -> tf32 (RNA), result is an f32 bit pattern with low mantissa zeroed.
__device__ __forceinline__ float tf32_rna(float x) {
    unsigned r;
    asm("cvt.rna.tf32.f32 %0, %1;" : "=r"(r) : "f"(x));
    return __uint_as_float(r);
}

// Split x into (hi, lo) tf32 pair: x ~= hi + lo, each exactly representable in tf32.
__device__ __forceinline__ float2 split_tf32(float x) {
    float hi = tf32_rna(x);
    float lo = tf32_rna(x - hi);
    return make_float2(hi, lo);
}

// m16n8k8 tf32 mma: C += A * B
__device__ __forceinline__ void mma_tf32(float c[4],
                                         unsigned a0, unsigned a1, unsigned a2, unsigned a3,
                                         unsigned b0, unsigned b1) {
    asm("mma.sync.aligned.m16n8k8.row.col.f32.tf32.tf32.f32 "
        "{%0,%1,%2,%3}, {%4,%5,%6,%7}, {%8,%9}, {%0,%1,%2,%3};"
        : "+f"(c[0]), "+f"(c[1]), "+f"(c[2]), "+f"(c[3])
        : "r"(a0), "r"(a1), "r"(a2), "r"(a3), "r"(b0), "r"(b1));
}

// ---------------------------------------------------------------------------
// Kernel 1: scores = scale * Q @ K^T, masked with -1e30 where mask==0.
// Writes raw masked scores into the attn_weights region of d_out (scratch).
// Grid: (SEQ/BN, SEQ/BM, BATCH), 256 threads.
// ---------------------------------------------------------------------------
__global__ __launch_bounds__(256)
void scores_kernel(const float* __restrict__ q, const float* __restrict__ k,
                   const int* __restrict__ mask, float* __restrict__ s)
{
    __shared__ float2 As[BM * SKA];   // [m][k] (hi,lo)
    __shared__ float2 Bs[BK * SNB];   // [k][n] (hi,lo)  (operand layout)

    const int b  = blockIdx.z;
    const int m0 = blockIdx.y * BM;
    const int n0 = blockIdx.x * BN;
    const int tid  = threadIdx.x;
    const int lane = tid & 31;
    const int wid  = tid >> 5;
    const int wm = wid & 1;      // 0..1 : warp row (64 rows each)
    const int wn = wid >> 1;     // 0..3 : warp col (32 cols each)
    const int g  = lane >> 2;    // 0..7
    const int tq = lane & 3;     // 0..3

    const float* qb = q + (size_t)b * SEQ * DIM;
    const float* kb = k + (size_t)b * SEQ * DIM;

    float acc[4][4][4];
#pragma unroll
    for (int im = 0; im < 4; im++)
#pragma unroll
        for (int in = 0; in < 4; in++)
#pragma unroll
            for (int c = 0; c < 4; c++) acc[im][in][c] = 0.0f;

    const int lrow = tid >> 2;        // 0..63
    const int lc4  = (tid & 3) * 4;   // 0,4,8,12

    for (int k0 = 0; k0 < DIM; k0 += BK) {
        // Load + split Q tile (BM x BK)
#pragma unroll
        for (int r = 0; r < 2; r++) {
            int row = lrow + r * 64;
            float4 v = *(const float4*)(qb + (size_t)(m0 + row) * DIM + k0 + lc4);
            As[row * SKA + lc4 + 0] = split_tf32(v.x);
            As[row * SKA + lc4 + 1] = split_tf32(v.y);
            As[row * SKA + lc4 + 2] = split_tf32(v.z);
            As[row * SKA + lc4 + 3] = split_tf32(v.w);
        }
        // Load + split + transpose K tile (BN keys x BK) -> Bs[k][n]
#pragma unroll
        for (int r = 0; r < 2; r++) {
            int row = lrow + r * 64;  // key index within tile
            float4 v = *(const float4*)(kb + (size_t)(n0 + row) * DIM + k0 + lc4);
            Bs[(lc4 + 0) * SNB + row] = split_tf32(v.x);
            Bs[(lc4 + 1) * SNB + row] = split_tf32(v.y);
            Bs[(lc4 + 2) * SNB + row] = split_tf32(v.z);
            Bs[(lc4 + 3) * SNB + row] = split_tf32(v.w);
        }
        __syncthreads();

#pragma unroll
        for (int kk = 0; kk < BK; kk += 8) {
            float2 af[4][4];
#pragma unroll
            for (int im = 0; im < 4; im++) {
                int R = wm * 64 + im * 16;
                af[im][0] = As[(R + g) * SKA + kk + tq];
                af[im][1] = As[(R + g + 8) * SKA + kk + tq];
                af[im][2] = As[(R + g) * SKA + kk + tq + 4];
                af[im][3] = As[(R + g + 8) * SKA + kk + tq + 4];
            }
            float2 bf[4][2];
#pragma unroll
            for (int in = 0; in < 4; in++) {
                int Cn = wn * 32 + in * 8;
                bf[in][0] = Bs[(kk + tq) * SNB + Cn + g];
                bf[in][1] = Bs[(kk + tq + 4) * SNB + Cn + g];
            }
#pragma unroll
            for (int im = 0; im < 4; im++)
#pragma unroll
                for (int in = 0; in < 4; in++) {
                    // hi*hi
                    mma_tf32(acc[im][in],
                             f2u(af[im][0].x), f2u(af[im][1].x), f2u(af[im][2].x), f2u(af[im][3].x),
                             f2u(bf[in][0].x), f2u(bf[in][1].x));
                    // hi*lo
                    mma_tf32(acc[im][in],
                             f2u(af[im][0].x), f2u(af[im][1].x), f2u(af[im][2].x), f2u(af[im][3].x),
                             f2u(bf[in][0].y), f2u(bf[in][1].y));
                    // lo*hi
                    mma_tf32(acc[im][in],
                             f2u(af[im][0].y), f2u(af[im][1].y), f2u(af[im][2].y), f2u(af[im][3].y),
                             f2u(bf[in][0].x), f2u(bf[in][1].x));
                }
        }
        __syncthreads();
    }

    // Epilogue: scale + mask, write masked scores
    float* sb = s + (size_t)b * SEQ * SEQ;
#pragma unroll
    for (int im = 0; im < 4; im++) {
        int Rbase = m0 + wm * 64 + im * 16;
#pragma unroll
        for (int in = 0; in < 4; in++) {
            int Cbase = n0 + wn * 32 + in * 8 + 2 * tq;
            int i0 = Rbase + g;
            int i1 = Rbase + g + 8;
            int2 mv0 = *(const int2*)(mask + (size_t)i0 * SEQ + Cbase);
            int2 mv1 = *(const int2*)(mask + (size_t)i1 * SEQ + Cbase);
            float2 o0, o1;
            o0.x = mv0.x ? acc[im][in][0] * ATTN_SCALE : -1e30f;
            o0.y = mv0.y ? acc[im][in][1] * ATTN_SCALE : -1e30f;
            o1.x = mv1.x ? acc[im][in][2] * ATTN_SCALE : -1e30f;
            o1.y = mv1.y ? acc[im][in][3] * ATTN_SCALE : -1e30f;
            *(float2*)(sb + (size_t)i0 * SEQ + Cbase) = o0;
            *(float2*)(sb + (size_t)i1 * SEQ + Cbase) = o1;
        }
    }
}

// ---------------------------------------------------------------------------
// Kernel 2: row softmax in place. Grid: BATCH*SEQ blocks, 256 threads.
// Each thread owns 8 elements (two float4s at positions tid and tid+256).
// ---------------------------------------------------------------------------
__global__ __launch_bounds__(256)
void softmax_kernel(float* __restrict__ s)
{
    __shared__ float red[8];
    float* p = s + (size_t)blockIdx.x * SEQ;
    const int tid = threadIdx.x;

    float4 v0 = *((const float4*)p + tid);
    float4 v1 = *((const float4*)p + tid + 256);

    float m = fmaxf(fmaxf(fmaxf(v0.x, v0.y), fmaxf(v0.z, v0.w)),
                    fmaxf(fmaxf(v1.x, v1.y), fmaxf(v1.z, v1.w)));
#pragma unroll
    for (int o = 16; o > 0; o >>= 1) m = fmaxf(m, __shfl_xor_sync(0xFFFFFFFFu, m, o));
    if ((tid & 31) == 0) red[tid >> 5] = m;
    __syncthreads();
    m = red[0];
#pragma unroll
    for (int w = 1; w < 8; w++) m = fmaxf(m, red[w]);
    __syncthreads();   // before reusing red for the sum

    float4 e0, e1;
    e0.x = __expf(v0.x - m); e0.y = __expf(v0.y - m);
    e0.z = __expf(v0.z - m); e0.w = __expf(v0.w - m);
    e1.x = __expf(v1.x - m); e1.y = __expf(v1.y - m);
    e1.z = __expf(v1.z - m); e1.w = __expf(v1.w - m);

    float sum = (e0.x + e0.y) + (e0.z + e0.w) + (e1.x + e1.y) + (e1.z + e1.w);
#pragma unroll
    for (int o = 16; o > 0; o >>= 1) sum += __shfl_xor_sync(0xFFFFFFFFu, sum, o);
    if ((tid & 31) == 0) red[tid >> 5] = sum;
    __syncthreads();
    float tot = red[0];
#pragma unroll
    for (int w = 1; w < 8; w++) tot += red[w];

    float inv = 1.0f / tot;
    e0.x *= inv; e0.y *= inv; e0.z *= inv; e0.w *= inv;
    e1.x *= inv; e1.y *= inv; e1.z *= inv; e1.w *= inv;
    *((float4*)p + tid) = e0;
    *((float4*)p + tid + 256) = e1;
}

// ---------------------------------------------------------------------------
// Kernel 3: output = P @ V.   Grid: (DIM/BN, SEQ/BM, BATCH), 256 threads.
// P: [SEQ, SEQ] (attn weights), V: [SEQ, DIM]. B operand(k,n) = V[k][n] direct.
// ---------------------------------------------------------------------------
__global__ __launch_bounds__(256)
void out_kernel(const float* __restrict__ p, const float* __restrict__ v,
                float* __restrict__ o)
{
    __shared__ float2 As[BM * SKA];
    __shared__ float2 Bs[BK * SNB];

    const int b  = blockIdx.z;
    const int m0 = blockIdx.y * BM;
    const int n0 = blockIdx.x * BN;
    const int tid  = threadIdx.x;
    const int lane = tid & 31;
    const int wid  = tid >> 5;
    const int wm = wid & 1;
    const int wn = wid >> 1;
    const int g  = lane >> 2;
    const int tq = lane & 3;

    const float* pb = p + (size_t)b * SEQ * SEQ;
    const float* vb = v + (size_t)b * SEQ * DIM;

    float acc[4][4][4];
#pragma unroll
    for (int im = 0; im < 4; im++)
#pragma unroll
        for (int in = 0; in < 4; in++)
#pragma unroll
            for (int c = 0; c < 4; c++) acc[im][in][c] = 0.0f;

    const int lrow = tid >> 2;
    const int lc4  = (tid & 3) * 4;
    const int bkr  = tid >> 5;          // 0..7
    const int bc   = (tid & 31) * 4;    // 0..124

    for (int k0 = 0; k0 < SEQ; k0 += BK) {
        // A tile: P[BM x BK]
#pragma unroll
        for (int r = 0; r < 2; r++) {
            int row = lrow + r * 64;
            float4 w = *(const float4*)(pb + (size_t)(m0 + row) * SEQ + k0 + lc4);
            As[row * SKA + lc4 + 0] = split_tf32(w.x);
            As[row * SKA + lc4 + 1] = split_tf32(w.y);
            As[row * SKA + lc4 + 2] = split_tf32(w.z);
            As[row * SKA + lc4 + 3] = split_tf32(w.w);
        }
        // B tile: V[BK x BN], already operand layout [k][n]
#pragma unroll
        for (int r = 0; r < 2; r++) {
            int kr = bkr + r * 8;
            float4 w = *(const float4*)(vb + (size_t)(k0 + kr) * DIM + n0 + bc);
            Bs[kr * SNB + bc + 0] = split_tf32(w.x);
            Bs[kr * SNB + bc + 1] = split_tf32(w.y);
            Bs[kr * SNB + bc + 2] = split_tf32(w.z);
            Bs[kr * SNB + bc + 3] = split_tf32(w.w);
        }
        __syncthreads();

#pragma unroll
        for (int kk = 0; kk < BK; kk += 8) {
            float2 af[4][4];
#pragma unroll
            for (int im = 0; im < 4; im++) {
                int R = wm * 64 + im * 16;
                af[im][0] = As[(R + g) * SKA + kk + tq];
                af[im][1] = As[(R + g + 8) * SKA + kk + tq];
                af[im][2] = As[(R + g) * SKA + kk + tq + 4];
                af[im][3] = As[(R + g + 8) * SKA + kk + tq + 4];
            }
            float2 bf[4][2];
#pragma unroll
            for (int in = 0; in < 4; in++) {
                int Cn = wn * 32 + in * 8;
                bf[in][0] = Bs[(kk + tq) * SNB + Cn + g];
                bf[in][1] = Bs[(kk + tq + 4) * SNB + Cn + g];
            }
#pragma unroll
            for (int im = 0; im < 4; im++)
#pragma unroll
                for (int in = 0; in < 4; in++) {
                    mma_tf32(acc[im][in],
                             f2u(af[im][0].x), f2u(af[im][1].x), f2u(af[im][2].x), f2u(af[im][3].x),
                             f2u(bf[in][0].x), f2u(bf[in][1].x));
                    mma_tf32(acc[im][in],
                             f2u(af[im][0].x), f2u(af[im][1].x), f2u(af[im][2].x), f2u(af[im][3].x),
                             f2u(bf[in][0].y), f2u(bf[in][1].y));
                    mma_tf32(acc[im][in],
                             f2u(af[im][0].y), f2u(af[im][1].y), f2u(af[im][2].y), f2u(af[im][3].y),
                             f2u(bf[in][0].x), f2u(bf[in][1].x));
                }
        }
        __syncthreads();
    }

    float* ob = o + (size_t)b * SEQ * DIM;
#pragma unroll
    for (int im = 0; im < 4; im++) {
        int Rbase = m0 + wm * 64 + im * 16;
#pragma unroll
        for (int in = 0; in < 4; in++) {
            int Cbase = n0 + wn * 32 + in * 8 + 2 * tq;
            int i0 = Rbase + g;
            int i1 = Rbase + g + 8;
            *(float2*)(ob + (size_t)i0 * DIM + Cbase) =
                make_float2(acc[im][in][0], acc[im][in][1]);
            *(float2*)(ob + (size_t)i1 * DIM + Cbase) =
                make_float2(acc[im][in][2], acc[im][in][3]);
        }
    }
}

// ---------------------------------------------------------------------------
extern "C" void kernel_launch(void* const* d_in, const int* in_sizes, int n_in,
                              void* d_out, int out_size)
{
    const float* q    = (const float*)d_in[0];
    const float* k    = (const float*)d_in[1];
    const float* v    = (const float*)d_in[2];
    const int*   mask = (const int*)d_in[3];

    float* out  = (float*)d_out;                          // [B, S, D]
    float* attn = out + (size_t)BATCH * SEQ * DIM;        // [B, S, S]

    dim3 blk(256);
    scores_kernel<<<dim3(SEQ / BN, SEQ / BM, BATCH), blk>>>(q, k, mask, attn);
    softmax_kernel<<<BATCH * SEQ, blk>>>(attn);
    out_kernel<<<dim3(DIM / BN, SEQ / BM, BATCH), blk>>>(attn, v, out);
}

// round 4
// speedup vs baseline: 1.0013x; 1.0013x over previous
#include <cuda_runtime.h>
#include <cstdint>

// Problem constants (fixed shapes)
#define BATCH 16
#define SEQ   2048
#define DIM   256
#define ATTN_SCALE 0.0625f   // 1/sqrt(256)

// GEMM tiling
#define BM 128
#define BN 128
#define BK 16
#define SKA 17    // As row stride in float2 units (BK + 1 pad)
#define SNB 130   // Bs row stride in float2 units (BN + 2 pad)

__device__ __forceinline__ unsigned f2u(float x) { return __float_as_uint(x); }

// Round f32 -> tf32 (RNA), result is an f32 bit pattern with low mantissa zeroed.
__device__ __forceinline__ float tf32_rna(float x) {
    unsigned r;
    asm("cvt.rna.tf32.f32 %0, %1;" : "=r"(r) : "f"(x));
    return __uint_as_float(r);
}

// Split x into (hi, lo) tf32 pair: x ~= hi + lo, each exactly representable in tf32.
__device__ __forceinline__ float2 split_tf32(float x) {
    float hi = tf32_rna(x);
    float lo = tf32_rna(x - hi);
    return make_float2(hi, lo);
}

// m16n8k8 tf32 mma: C += A * B
__device__ __forceinline__ void mma_tf32(float c[4],
                                         unsigned a0, unsigned a1, unsigned a2, unsigned a3,
                                         unsigned b0, unsigned b1) {
    asm("mma.sync.aligned.m16n8k8.row.col.f32.tf32.tf32.f32 "
        "{%0,%1,%2,%3}, {%4,%5,%6,%7}, {%8,%9}, {%0,%1,%2,%3};"
        : "+f"(c[0]), "+f"(c[1]), "+f"(c[2]), "+f"(c[3])
        : "r"(a0), "r"(a1), "r"(a2), "r"(a3), "r"(b0), "r"(b1));
}

// ---------------------------------------------------------------------------
// Kernel 1: scores = scale * Q @ K^T, masked with -1e30 where mask==0.
// Writes raw masked scores into the attn_weights region of d_out (scratch).
// Grid: (SEQ/BN, SEQ/BM, BATCH), 256 threads.
// ---------------------------------------------------------------------------
__global__ __launch_bounds__(256)
void scores_kernel(const float* __restrict__ q, const float* __restrict__ k,
                   const int* __restrict__ mask, float* __restrict__ s)
{
    __shared__ float2 As[BM * SKA];   // [m][k] (hi,lo)
    __shared__ float2 Bs[BK * SNB];   // [k][n] (hi,lo)  (operand layout)

    const int b  = blockIdx.z;
    const int m0 = blockIdx.y * BM;
    const int n0 = blockIdx.x * BN;
    const int tid  = threadIdx.x;
    const int lane = tid & 31;
    const int wid  = tid >> 5;
    const int wm = wid & 1;      // 0..1 : warp row (64 rows each)
    const int wn = wid >> 1;     // 0..3 : warp col (32 cols each)
    const int g  = lane >> 2;    // 0..7
    const int tq = lane & 3;     // 0..3

    const float* qb = q + (size_t)b * SEQ * DIM;
    const float* kb = k + (size_t)b * SEQ * DIM;

    float acc[4][4][4];
#pragma unroll
    for (int im = 0; im < 4; im++)
#pragma unroll
        for (int in = 0; in < 4; in++)
#pragma unroll
            for (int c = 0; c < 4; c++) acc[im][in][c] = 0.0f;

    const int lrow = tid >> 2;        // 0..63
    const int lc4  = (tid & 3) * 4;   // 0,4,8,12

    for (int k0 = 0; k0 < DIM; k0 += BK) {
        // Load + split Q tile (BM x BK)
#pragma unroll
        for (int r = 0; r < 2; r++) {
            int row = lrow + r * 64;
            float4 v = *(const float4*)(qb + (size_t)(m0 + row) * DIM + k0 + lc4);
            As[row * SKA + lc4 + 0] = split_tf32(v.x);
            As[row * SKA + lc4 + 1] = split_tf32(v.y);
            As[row * SKA + lc4 + 2] = split_tf32(v.z);
            As[row * SKA + lc4 + 3] = split_tf32(v.w);
        }
        // Load + split + transpose K tile (BN keys x BK) -> Bs[k][n]
#pragma unroll
        for (int r = 0; r < 2; r++) {
            int row = lrow + r * 64;  // key index within tile
            float4 v = *(const float4*)(kb + (size_t)(n0 + row) * DIM + k0 + lc4);
            Bs[(lc4 + 0) * SNB + row] = split_tf32(v.x);
            Bs[(lc4 + 1) * SNB + row] = split_tf32(v.y);
            Bs[(lc4 + 2) * SNB + row] = split_tf32(v.z);
            Bs[(lc4 + 3) * SNB + row] = split_tf32(v.w);
        }
        __syncthreads();

#pragma unroll
        for (int kk = 0; kk < BK; kk += 8) {
            float2 af[4][4];
#pragma unroll
            for (int im = 0; im < 4; im++) {
                int R = wm * 64 + im * 16;
                af[im][0] = As[(R + g) * SKA + kk + tq];
                af[im][1] = As[(R + g + 8) * SKA + kk + tq];
                af[im][2] = As[(R + g) * SKA + kk + tq + 4];
                af[im][3] = As[(R + g + 8) * SKA + kk + tq + 4];
            }
            float2 bf[4][2];
#pragma unroll
            for (int in = 0; in < 4; in++) {
                int Cn = wn * 32 + in * 8;
                bf[in][0] = Bs[(kk + tq) * SNB + Cn + g];
                bf[in][1] = Bs[(kk + tq + 4) * SNB + Cn + g];
            }
#pragma unroll
            for (int im = 0; im < 4; im++)
#pragma unroll
                for (int in = 0; in < 4; in++) {
                    // hi*hi
                    mma_tf32(acc[im][in],
                             f2u(af[im][0].x), f2u(af[im][1].x), f2u(af[im][2].x), f2u(af[im][3].x),
                             f2u(bf[in][0].x), f2u(bf[in][1].x));
                    // hi*lo
                    mma_tf32(acc[im][in],
                             f2u(af[im][0].x), f2u(af[im][1].x), f2u(af[im][2].x), f2u(af[im][3].x),
                             f2u(bf[in][0].y), f2u(bf[in][1].y));
                    // lo*hi
                    mma_tf32(acc[im][in],
                             f2u(af[im][0].y), f2u(af[im][1].y), f2u(af[im][2].y), f2u(af[im][3].y),
                             f2u(bf[in][0].x), f2u(bf[in][1].x));
                }
        }
        __syncthreads();
    }

    // Epilogue: scale + mask, write masked scores
    float* sb = s + (size_t)b * SEQ * SEQ;
#pragma unroll
    for (int im = 0; im < 4; im++) {
        int Rbase = m0 + wm * 64 + im * 16;
#pragma unroll
        for (int in = 0; in < 4; in++) {
            int Cbase = n0 + wn * 32 + in * 8 + 2 * tq;
            int i0 = Rbase + g;
            int i1 = Rbase + g + 8;
            int2 mv0 = *(const int2*)(mask + (size_t)i0 * SEQ + Cbase);
            int2 mv1 = *(const int2*)(mask + (size_t)i1 * SEQ + Cbase);
            float2 o0, o1;
            o0.x = mv0.x ? acc[im][in][0] * ATTN_SCALE : -1e30f;
            o0.y = mv0.y ? acc[im][in][1] * ATTN_SCALE : -1e30f;
            o1.x = mv1.x ? acc[im][in][2] * ATTN_SCALE : -1e30f;
            o1.y = mv1.y ? acc[im][in][3] * ATTN_SCALE : -1e30f;
            *(float2*)(sb + (size_t)i0 * SEQ + Cbase) = o0;
            *(float2*)(sb + (size_t)i1 * SEQ + Cbase) = o1;
        }
    }
}

// ---------------------------------------------------------------------------
// Kernel 2: row softmax in place. Grid: BATCH*SEQ blocks, 256 threads.
// Each thread owns 8 elements (two float4s at positions tid and tid+256).
// ---------------------------------------------------------------------------
__global__ __launch_bounds__(256)
void softmax_kernel(float* __restrict__ s)
{
    __shared__ float red[8];
    float* p = s + (size_t)blockIdx.x * SEQ;
    const int tid = threadIdx.x;

    float4 v0 = *((const float4*)p + tid);
    float4 v1 = *((const float4*)p + tid + 256);

    float m = fmaxf(fmaxf(fmaxf(v0.x, v0.y), fmaxf(v0.z, v0.w)),
                    fmaxf(fmaxf(v1.x, v1.y), fmaxf(v1.z, v1.w)));
#pragma unroll
    for (int o = 16; o > 0; o >>= 1) m = fmaxf(m, __shfl_xor_sync(0xFFFFFFFFu, m, o));
    if ((tid & 31) == 0) red[tid >> 5] = m;
    __syncthreads();
    m = red[0];
#pragma unroll
    for (int w = 1; w < 8; w++) m = fmaxf(m, red[w]);
    __syncthreads();   // before reusing red for the sum

    float4 e0, e1;
    e0.x = __expf(v0.x - m); e0.y = __expf(v0.y - m);
    e0.z = __expf(v0.z - m); e0.w = __expf(v0.w - m);
    e1.x = __expf(v1.x - m); e1.y = __expf(v1.y - m);
    e1.z = __expf(v1.z - m); e1.w = __expf(v1.w - m);

    float sum = (e0.x + e0.y) + (e0.z + e0.w) + (e1.x + e1.y) + (e1.z + e1.w);
#pragma unroll
    for (int o = 16; o > 0; o >>= 1) sum += __shfl_xor_sync(0xFFFFFFFFu, sum, o);
    if ((tid & 31) == 0) red[tid >> 5] = sum;
    __syncthreads();
    float tot = red[0];
#pragma unroll
    for (int w = 1; w < 8; w++) tot += red[w];

    float inv = 1.0f / tot;
    e0.x *= inv; e0.y *= inv; e0.z *= inv; e0.w *= inv;
    e1.x *= inv; e1.y *= inv; e1.z *= inv; e1.w *= inv;
    *((float4*)p + tid) = e0;
    *((float4*)p + tid + 256) = e1;
}

// ---------------------------------------------------------------------------
// Kernel 3: output = P @ V.   Grid: (DIM/BN, SEQ/BM, BATCH), 256 threads.
// P: [SEQ, SEQ] (attn weights), V: [SEQ, DIM]. B operand(k,n) = V[k][n] direct.
// ---------------------------------------------------------------------------
__global__ __launch_bounds__(256)
void out_kernel(const float* __restrict__ p, const float* __restrict__ v,
                float* __restrict__ o)
{
    __shared__ float2 As[BM * SKA];
    __shared__ float2 Bs[BK * SNB];

    const int b  = blockIdx.z;
    const int m0 = blockIdx.y * BM;
    const int n0 = blockIdx.x * BN;
    const int tid  = threadIdx.x;
    const int lane = tid & 31;
    const int wid  = tid >> 5;
    const int wm = wid & 1;
    const int wn = wid >> 1;
    const int g  = lane >> 2;
    const int tq = lane & 3;

    const float* pb = p + (size_t)b * SEQ * SEQ;
    const float* vb = v + (size_t)b * SEQ * DIM;

    float acc[4][4][4];
#pragma unroll
    for (int im = 0; im < 4; im++)
#pragma unroll
        for (int in = 0; in < 4; in++)
#pragma unroll
            for (int c = 0; c < 4; c++) acc[im][in][c] = 0.0f;

    const int lrow = tid >> 2;
    const int lc4  = (tid & 3) * 4;
    const int bkr  = tid >> 5;          // 0..7
    const int bc   = (tid & 31) * 4;    // 0..124

    for (int k0 = 0; k0 < SEQ; k0 += BK) {
        // A tile: P[BM x BK]
#pragma unroll
        for (int r = 0; r < 2; r++) {
            int row = lrow + r * 64;
            float4 w = *(const float4*)(pb + (size_t)(m0 + row) * SEQ + k0 + lc4);
            As[row * SKA + lc4 + 0] = split_tf32(w.x);
            As[row * SKA + lc4 + 1] = split_tf32(w.y);
            As[row * SKA + lc4 + 2] = split_tf32(w.z);
            As[row * SKA + lc4 + 3] = split_tf32(w.w);
        }
        // B tile: V[BK x BN], already operand layout [k][n]
#pragma unroll
        for (int r = 0; r < 2; r++) {
            int kr = bkr + r * 8;
            float4 w = *(const float4*)(vb + (size_t)(k0 + kr) * DIM + n0 + bc);
            Bs[kr * SNB + bc + 0] = split_tf32(w.x);
            Bs[kr * SNB + bc + 1] = split_tf32(w.y);
            Bs[kr * SNB + bc + 2] = split_tf32(w.z);
            Bs[kr * SNB + bc + 3] = split_tf32(w.w);
        }
        __syncthreads();

#pragma unroll
        for (int kk = 0; kk < BK; kk += 8) {
            float2 af[4][4];
#pragma unroll
            for (int im = 0; im < 4; im++) {
                int R = wm * 64 + im * 16;
                af[im][0] = As[(R + g) * SKA + kk + tq];
                af[im][1] = As[(R + g + 8) * SKA + kk + tq];
                af[im][2] = As[(R + g) * SKA + kk + tq + 4];
                af[im][3] = As[(R + g + 8) * SKA + kk + tq + 4];
            }
            float2 bf[4][2];
#pragma unroll
            for (int in = 0; in < 4; in++) {
                int Cn = wn * 32 + in * 8;
                bf[in][0] = Bs[(kk + tq) * SNB + Cn + g];
                bf[in][1] = Bs[(kk + tq + 4) * SNB + Cn + g];
            }
#pragma unroll
            for (int im = 0; im < 4; im++)
#pragma unroll
                for (int in = 0; in < 4; in++) {
                    mma_tf32(acc[im][in],
                             f2u(af[im][0].x), f2u(af[im][1].x), f2u(af[im][2].x), f2u(af[im][3].x),
                             f2u(bf[in][0].x), f2u(bf[in][1].x));
                    mma_tf32(acc[im][in],
                             f2u(af[im][0].x), f2u(af[im][1].x), f2u(af[im][2].x), f2u(af[im][3].x),
                             f2u(bf[in][0].y), f2u(bf[in][1].y));
                    mma_tf32(acc[im][in],
                             f2u(af[im][0].y), f2u(af[im][1].y), f2u(af[im][2].y), f2u(af[im][3].y),
                             f2u(bf[in][0].x), f2u(bf[in][1].x));
                }
        }
        __syncthreads();
    }

    float* ob = o + (size_t)b * SEQ * DIM;
#pragma unroll
    for (int im = 0; im < 4; im++) {
        int Rbase = m0 + wm * 64 + im * 16;
#pragma unroll
        for (int in = 0; in < 4; in++) {
            int Cbase = n0 + wn * 32 + in * 8 + 2 * tq;
            int i0 = Rbase + g;
            int i1 = Rbase + g + 8;
            *(float2*)(ob + (size_t)i0 * DIM + Cbase) =
                make_float2(acc[im][in][0], acc[im][in][1]);
            *(float2*)(ob + (size_t)i1 * DIM + Cbase) =
                make_float2(acc[im][in][2], acc[im][in][3]);
        }
    }
}

// ---------------------------------------------------------------------------
extern "C" void kernel_launch(void* const* d_in, const int* in_sizes, int n_in,
                              void* d_out, int out_size)
{
    const float* q    = (const float*)d_in[0];
    const float* k    = (const float*)d_in[1];
    const float* v    = (const float*)d_in[2];
    const int*   mask = (const int*)d_in[3];

    float* out  = (float*)d_out;                          // [B, S, D]
    float* attn = out + (size_t)BATCH * SEQ * DIM;        // [B, S, S]

    dim3 blk(256);
    scores_kernel<<<dim3(SEQ / BN, SEQ / BM, BATCH), blk>>>(q, k, mask, attn);
    softmax_kernel<<<BATCH * SEQ, blk>>>(attn);
    out_kernel<<<dim3(DIM / BN, SEQ / BM, BATCH), blk>>>(attn, v, out);
}

// round 6
// speedup vs baseline: 2.4231x; 2.4199x over previous
#include <cuda_runtime.h>
#include <cuda_bf16.h>
#include <cstdint>

// Problem constants
#define BATCH 16
#define SEQ   2048
#define DIM   256
#define ATTN_SCALE 0.0625f   // 1/sqrt(256)

#define BKC 32      // K-chunk (elements)
#define SA  80      // [row][32 bf16] row stride bytes (64B data + 16B pad)
#define SV  272     // V tile [k][128 bf16] row stride bytes (256B + 16B pad)

// Stage offsets, scores kernel (A=Q, B=K, both [row][k])
#define SC_AHI 0
#define SC_ALO 10240
#define SC_BHI 20480
#define SC_BLO 30720
#define SC_STAGE 40960
#define SC_SMEM (2 * SC_STAGE)     // 81920

// Stage offsets, out kernel (A=P [row][k], B=V [k][n])
#define OU_AHI 0
#define OU_ALO 10240
#define OU_VHI 20480
#define OU_VLO 29184
#define OU_STAGE 37888
#define OU_SMEM (2 * OU_STAGE)     // 75776

// ---------------------------------------------------------------------------
__device__ __forceinline__ uint32_t smem_u32(const void* p) {
    uint32_t a;
    asm("{ .reg .u64 t; cvta.to.shared.u64 t, %1; cvt.u32.u64 %0, t; }" : "=r"(a) : "l"(p));
    return a;
}

__device__ __forceinline__ void ldmx4(uint32_t& r0, uint32_t& r1, uint32_t& r2,
                                      uint32_t& r3, uint32_t addr) {
    asm volatile("ldmatrix.sync.aligned.m8n8.x4.shared.b16 {%0,%1,%2,%3}, [%4];"
                 : "=r"(r0), "=r"(r1), "=r"(r2), "=r"(r3) : "r"(addr));
}
__device__ __forceinline__ void ldmx4t(uint32_t& r0, uint32_t& r1, uint32_t& r2,
                                       uint32_t& r3, uint32_t addr) {
    asm volatile("ldmatrix.sync.aligned.m8n8.x4.trans.shared.b16 {%0,%1,%2,%3}, [%4];"
                 : "=r"(r0), "=r"(r1), "=r"(r2), "=r"(r3) : "r"(addr));
}

// m16n8k16 bf16 mma, fp32 accumulate
__device__ __forceinline__ void mma_bf16(float c[4], const uint32_t a[4],
                                         uint32_t b0, uint32_t b1) {
    asm("mma.sync.aligned.m16n8k16.row.col.f32.bf16.bf16.f32 "
        "{%0,%1,%2,%3}, {%4,%5,%6,%7}, {%8,%9}, {%0,%1,%2,%3};"
        : "+f"(c[0]), "+f"(c[1]), "+f"(c[2]), "+f"(c[3])
        : "r"(a[0]), "r"(a[1]), "r"(a[2]), "r"(a[3]), "r"(b0), "r"(b1));
}

// Split float4 into packed bf16 hi (4 vals) + lo (4 vals)
__device__ __forceinline__ void split4(float4 v, uint2& h, uint2& l) {
    __nv_bfloat16 h0 = __float2bfloat16_rn(v.x);
    __nv_bfloat16 h1 = __float2bfloat16_rn(v.y);
    __nv_bfloat16 h2 = __float2bfloat16_rn(v.z);
    __nv_bfloat16 h3 = __float2bfloat16_rn(v.w);
    __nv_bfloat16 l0 = __float2bfloat16_rn(v.x - __bfloat162float(h0));
    __nv_bfloat16 l1 = __float2bfloat16_rn(v.y - __bfloat162float(h1));
    __nv_bfloat16 l2 = __float2bfloat16_rn(v.z - __bfloat162float(h2));
    __nv_bfloat16 l3 = __float2bfloat16_rn(v.w - __bfloat162float(h3));
    __nv_bfloat162 ph0 = __halves2bfloat162(h0, h1);
    __nv_bfloat162 ph1 = __halves2bfloat162(h2, h3);
    __nv_bfloat162 pl0 = __halves2bfloat162(l0, l1);
    __nv_bfloat162 pl1 = __halves2bfloat162(l2, l3);
    h.x = *(uint32_t*)&ph0; h.y = *(uint32_t*)&ph1;
    l.x = *(uint32_t*)&pl0; l.y = *(uint32_t*)&pl1;
}

// LDG a 128x32 fp32 tile (row_stride in elements) into 4 float4/thread
__device__ __forceinline__ void ldg32(const float* base, int row_stride, int k0,
                                      int tid, float4 st[4]) {
#pragma unroll
    for (int j = 0; j < 4; j++) {
        int idx = tid + j * 256;
        int row = idx >> 3, c4 = idx & 7;
        st[j] = *(const float4*)(base + (size_t)row * row_stride + k0 + c4 * 4);
    }
}
// STS that tile as split bf16 into hi/lo arrays with SA stride
__device__ __forceinline__ void sts32(char* hi, char* lo, int tid, const float4 st[4]) {
#pragma unroll
    for (int j = 0; j < 4; j++) {
        int idx = tid + j * 256;
        int row = idx >> 3, c4 = idx & 7;
        uint2 h, l; split4(st[j], h, l);
        *(uint2*)(hi + row * SA + c4 * 8) = h;
        *(uint2*)(lo + row * SA + c4 * 8) = l;
    }
}
// LDG a 32x128 fp32 V tile into 4 float4/thread
__device__ __forceinline__ void ldgV(const float* vb, int k0, int n0, int tid, float4 st[4]) {
#pragma unroll
    for (int j = 0; j < 4; j++) {
        int idx = tid + j * 256;
        int row = idx >> 5, c4 = idx & 31;
        st[j] = *(const float4*)(vb + (size_t)(k0 + row) * DIM + n0 + c4 * 4);
    }
}
__device__ __forceinline__ void stsV(char* hi, char* lo, int tid, const float4 st[4]) {
#pragma unroll
    for (int j = 0; j < 4; j++) {
        int idx = tid + j * 256;
        int row = idx >> 5, c4 = idx & 31;
        uint2 h, l; split4(st[j], h, l);
        *(uint2*)(hi + row * SV + c4 * 8) = h;
        *(uint2*)(lo + row * SV + c4 * 8) = l;
    }
}

// ---------------------------------------------------------------------------
// Kernel 1: masked raw scores = scale * Q @ K^T  (into attn region)
// Grid (16,16,BATCH), 256 threads, tile 128x128, BK=32, double buffered.
// ---------------------------------------------------------------------------
__global__ __launch_bounds__(256, 1)
void scores_tc(const float* __restrict__ q, const float* __restrict__ kk,
               const int* __restrict__ mask, float* __restrict__ s)
{
    extern __shared__ char smem[];
    const uint32_t sbase = smem_u32(smem);
    const int tid  = threadIdx.x;
    const int lane = tid & 31;
    const int wid  = tid >> 5;
    const int wm = wid & 1, wn = wid >> 1;
    const int g = lane >> 2, t = lane & 3;
    const int b  = blockIdx.z;
    const int m0 = blockIdx.y * 128;
    const int n0 = blockIdx.x * 128;

    const float* qb = q  + (size_t)b * SEQ * DIM + (size_t)m0 * DIM;
    const float* kb = kk + (size_t)b * SEQ * DIM + (size_t)n0 * DIM;

    const int mBase = wm * 64;
    const int nBase = wn * 32;
    // ldmatrix address components
    const uint32_t aRowOff = (uint32_t)(mBase + (lane & 15)) * SA + ((lane >> 4) << 4);
    const uint32_t bRowOff = (uint32_t)(nBase + (lane & 7) + ((lane >> 4) << 3)) * SA
                           + (((lane >> 3) & 1) << 4);

    float acc[4][4][4];
#pragma unroll
    for (int i = 0; i < 4; i++)
#pragma unroll
        for (int j = 0; j < 4; j++)
#pragma unroll
            for (int c = 0; c < 4; c++) acc[i][j][c] = 0.0f;

    float4 stA[4], stB[4];
    ldg32(qb, DIM, 0, tid, stA);
    ldg32(kb, DIM, 0, tid, stB);
    sts32(smem + SC_AHI, smem + SC_ALO, tid, stA);
    sts32(smem + SC_BHI, smem + SC_BLO, tid, stB);
    __syncthreads();

    const int NC = DIM / BKC;   // 8
    for (int c = 0; c < NC; c++) {
        const int ss = c & 1;
        const uint32_t stg = sbase + ss * SC_STAGE;
        if (c + 1 < NC) {
            ldg32(qb, DIM, (c + 1) * BKC, tid, stA);
            ldg32(kb, DIM, (c + 1) * BKC, tid, stB);
        }
#pragma unroll
        for (int ks = 0; ks < 2; ks++) {
            const uint32_t kByte = (uint32_t)(ks * 32);
            uint32_t bh[4][2], bl[4][2];
#pragma unroll
            for (int np = 0; np < 2; np++) {
                uint32_t addr = stg + SC_BHI + bRowOff + np * 16 * SA + kByte;
                uint32_t r0, r1, r2, r3;
                ldmx4(r0, r1, r2, r3, addr);
                bh[2*np][0] = r0; bh[2*np][1] = r1;
                bh[2*np+1][0] = r2; bh[2*np+1][1] = r3;
                ldmx4(r0, r1, r2, r3, addr + (SC_BLO - SC_BHI));
                bl[2*np][0] = r0; bl[2*np][1] = r1;
                bl[2*np+1][0] = r2; bl[2*np+1][1] = r3;
            }
#pragma unroll
            for (int mt = 0; mt < 4; mt++) {
                uint32_t addr = stg + SC_AHI + aRowOff + mt * 16 * SA + kByte;
                uint32_t ah[4], al[4];
                ldmx4(ah[0], ah[1], ah[2], ah[3], addr);
                ldmx4(al[0], al[1], al[2], al[3], addr + (SC_ALO - SC_AHI));
#pragma unroll
                for (int nt = 0; nt < 4; nt++) {
                    mma_bf16(acc[mt][nt], ah, bh[nt][0], bh[nt][1]);
                    mma_bf16(acc[mt][nt], ah, bl[nt][0], bl[nt][1]);
                    mma_bf16(acc[mt][nt], al, bh[nt][0], bh[nt][1]);
                }
            }
        }
        if (c + 1 < NC) {
            char* nx = smem + (ss ^ 1) * SC_STAGE;
            sts32(nx + SC_AHI, nx + SC_ALO, tid, stA);
            sts32(nx + SC_BHI, nx + SC_BLO, tid, stB);
        }
        __syncthreads();
    }

    // Epilogue: scale + mask -> raw masked scores
    float* sb = s + (size_t)b * SEQ * SEQ;
#pragma unroll
    for (int mt = 0; mt < 4; mt++) {
        int r0 = m0 + mBase + mt * 16 + g;
#pragma unroll
        for (int nt = 0; nt < 4; nt++) {
            int col = n0 + nBase + nt * 8 + 2 * t;
            int2 mv0 = *(const int2*)(mask + (size_t)r0 * SEQ + col);
            int2 mv1 = *(const int2*)(mask + (size_t)(r0 + 8) * SEQ + col);
            float2 o0, o1;
            o0.x = mv0.x ? acc[mt][nt][0] * ATTN_SCALE : -1e30f;
            o0.y = mv0.y ? acc[mt][nt][1] * ATTN_SCALE : -1e30f;
            o1.x = mv1.x ? acc[mt][nt][2] * ATTN_SCALE : -1e30f;
            o1.y = mv1.y ? acc[mt][nt][3] * ATTN_SCALE : -1e30f;
            *(float2*)(sb + (size_t)r0 * SEQ + col) = o0;
            *(float2*)(sb + (size_t)(r0 + 8) * SEQ + col) = o1;
        }
    }
}

// ---------------------------------------------------------------------------
// Kernel 2: row softmax in place (proven baseline).
// ---------------------------------------------------------------------------
__global__ __launch_bounds__(256)
void softmax_kernel(float* __restrict__ s)
{
    __shared__ float red[8];
    float* p = s + (size_t)blockIdx.x * SEQ;
    const int tid = threadIdx.x;

    float4 v0 = *((const float4*)p + tid);
    float4 v1 = *((const float4*)p + tid + 256);

    float m = fmaxf(fmaxf(fmaxf(v0.x, v0.y), fmaxf(v0.z, v0.w)),
                    fmaxf(fmaxf(v1.x, v1.y), fmaxf(v1.z, v1.w)));
#pragma unroll
    for (int o = 16; o > 0; o >>= 1) m = fmaxf(m, __shfl_xor_sync(0xFFFFFFFFu, m, o));
    if ((tid & 31) == 0) red[tid >> 5] = m;
    __syncthreads();
    m = red[0];
#pragma unroll
    for (int w = 1; w < 8; w++) m = fmaxf(m, red[w]);
    __syncthreads();

    float4 e0, e1;
    e0.x = __expf(v0.x - m); e0.y = __expf(v0.y - m);
    e0.z = __expf(v0.z - m); e0.w = __expf(v0.w - m);
    e1.x = __expf(v1.x - m); e1.y = __expf(v1.y - m);
    e1.z = __expf(v1.z - m); e1.w = __expf(v1.w - m);

    float sum = (e0.x + e0.y) + (e0.z + e0.w) + (e1.x + e1.y) + (e1.z + e1.w);
#pragma unroll
    for (int o = 16; o > 0; o >>= 1) sum += __shfl_xor_sync(0xFFFFFFFFu, sum, o);
    if ((tid & 31) == 0) red[tid >> 5] = sum;
    __syncthreads();
    float tot = red[0];
#pragma unroll
    for (int w = 1; w < 8; w++) tot += red[w];

    float inv = 1.0f / tot;
    e0.x *= inv; e0.y *= inv; e0.z *= inv; e0.w *= inv;
    e1.x *= inv; e1.y *= inv; e1.z *= inv; e1.w *= inv;
    *((float4*)p + tid) = e0;
    *((float4*)p + tid + 256) = e1;
}

// ---------------------------------------------------------------------------
// Kernel 3: output = P @ V.  Grid (2,16,BATCH), 256 threads, tile 128x128.
// V kept [k][n]; B fragments via ldmatrix.x4.trans.
// ---------------------------------------------------------------------------
__global__ __launch_bounds__(256, 1)
void out_tc(const float* __restrict__ p, const float* __restrict__ v,
            float* __restrict__ o)
{
    extern __shared__ char smem[];
    const uint32_t sbase = smem_u32(smem);
    const int tid  = threadIdx.x;
    const int lane = tid & 31;
    const int wid  = tid >> 5;
    const int wm = wid & 1, wn = wid >> 1;
    const int g = lane >> 2, t = lane & 3;
    const int b  = blockIdx.z;
    const int m0 = blockIdx.y * 128;
    const int n0 = blockIdx.x * 128;

    const float* pb = p + (size_t)b * SEQ * SEQ + (size_t)m0 * SEQ;
    const float* vb = v + (size_t)b * SEQ * DIM;

    const int mBase = wm * 64;
    const int nBase = wn * 32;
    const uint32_t aRowOff = (uint32_t)(mBase + (lane & 15)) * SA + ((lane >> 4) << 4);
    // V trans addresses: row(k) within 16-step, col = n
    const uint32_t vRow = (uint32_t)((lane & 7) + (((lane >> 3) & 1) << 3));
    const uint32_t vNOff = (uint32_t)(nBase + ((lane >> 4) << 3)) * 2;

    float acc[4][4][4];
#pragma unroll
    for (int i = 0; i < 4; i++)
#pragma unroll
        for (int j = 0; j < 4; j++)
#pragma unroll
            for (int c = 0; c < 4; c++) acc[i][j][c] = 0.0f;

    float4 stA[4], stB[4];
    ldg32(pb, SEQ, 0, tid, stA);
    ldgV(vb, 0, n0, tid, stB);
    sts32(smem + OU_AHI, smem + OU_ALO, tid, stA);
    stsV(smem + OU_VHI, smem + OU_VLO, tid, stB);
    __syncthreads();

    const int NC = SEQ / BKC;   // 64
    for (int c = 0; c < NC; c++) {
        const int ss = c & 1;
        const uint32_t stg = sbase + ss * OU_STAGE;
        if (c + 1 < NC) {
            ldg32(pb, SEQ, (c + 1) * BKC, tid, stA);
            ldgV(vb, (c + 1) * BKC, n0, tid, stB);
        }
#pragma unroll
        for (int ks = 0; ks < 2; ks++) {
            uint32_t bh[4][2], bl[4][2];
#pragma unroll
            for (int np = 0; np < 2; np++) {
                uint32_t addr = stg + OU_VHI + (ks * 16 + vRow) * SV + vNOff + np * 32;
                uint32_t r0, r1, r2, r3;
                ldmx4t(r0, r1, r2, r3, addr);
                bh[2*np][0] = r0; bh[2*np][1] = r1;
                bh[2*np+1][0] = r2; bh[2*np+1][1] = r3;
                ldmx4t(r0, r1, r2, r3, addr + (OU_VLO - OU_VHI));
                bl[2*np][0] = r0; bl[2*np][1] = r1;
                bl[2*np+1][0] = r2; bl[2*np+1][1] = r3;
            }
#pragma unroll
            for (int mt = 0; mt < 4; mt++) {
                uint32_t addr = stg + OU_AHI + aRowOff + mt * 16 * SA + ks * 32;
                uint32_t ah[4], al[4];
                ldmx4(ah[0], ah[1], ah[2], ah[3], addr);
                ldmx4(al[0], al[1], al[2], al[3], addr + (OU_ALO - OU_AHI));
#pragma unroll
                for (int nt = 0; nt < 4; nt++) {
                    mma_bf16(acc[mt][nt], ah, bh[nt][0], bh[nt][1]);
                    mma_bf16(acc[mt][nt], ah, bl[nt][0], bl[nt][1]);
                    mma_bf16(acc[mt][nt], al, bh[nt][0], bh[nt][1]);
                }
            }
        }
        if (c + 1 < NC) {
            char* nx = smem + (ss ^ 1) * OU_STAGE;
            sts32(nx + OU_AHI, nx + OU_ALO, tid, stA);
            stsV(nx + OU_VHI, nx + OU_VLO, tid, stB);
        }
        __syncthreads();
    }

    float* ob = o + (size_t)b * SEQ * DIM;
#pragma unroll
    for (int mt = 0; mt < 4; mt++) {
        int r0 = m0 + mBase + mt * 16 + g;
#pragma unroll
        for (int nt = 0; nt < 4; nt++) {
            int col = n0 + nBase + nt * 8 + 2 * t;
            *(float2*)(ob + (size_t)r0 * DIM + col) =
                make_float2(acc[mt][nt][0], acc[mt][nt][1]);
            *(float2*)(ob + (size_t)(r0 + 8) * DIM + col) =
                make_float2(acc[mt][nt][2], acc[mt][nt][3]);
        }
    }
}

// ---------------------------------------------------------------------------
extern "C" void kernel_launch(void* const* d_in, const int* in_sizes, int n_in,
                              void* d_out, int out_size)
{
    const float* q    = (const float*)d_in[0];
    const float* k    = (const float*)d_in[1];
    const float* v    = (const float*)d_in[2];
    const int*   mask = (const int*)d_in[3];

    float* out  = (float*)d_out;                      // [B, S, D]
    float* attn = out + (size_t)BATCH * SEQ * DIM;    // [B, S, S]

    cudaFuncSetAttribute(scores_tc, cudaFuncAttributeMaxDynamicSharedMemorySize, SC_SMEM);
    cudaFuncSetAttribute(out_tc,    cudaFuncAttributeMaxDynamicSharedMemorySize, OU_SMEM);

    dim3 blk(256);
    scores_tc<<<dim3(SEQ / 128, SEQ / 128, BATCH), blk, SC_SMEM>>>(q, k, mask, attn);
    softmax_kernel<<<BATCH * SEQ, blk>>>(attn);
    out_tc<<<dim3(DIM / 128, SEQ / 128, BATCH), blk, OU_SMEM>>>(attn, v, out);
}

// round 7
// speedup vs baseline: 2.5774x; 1.0637x over previous
#include <cuda_runtime.h>
#include <cuda_bf16.h>
#include <cstdint>

// Problem constants
#define BATCH 16
#define SEQ   2048
#define DIM   256
#define ATTN_SCALE 0.0625f   // 1/sqrt(256)

#define BKC 32      // K-chunk (elements)
#define SA  80      // [row][32 bf16] row stride bytes (64B data + 16B pad)
#define SV  272     // V tile [k][128 bf16] row stride bytes (256B + 16B pad)

// Stage offsets, scores kernel (A=Q, B=K, both [row][k])
#define SC_AHI 0
#define SC_ALO 10240
#define SC_BHI 20480
#define SC_BLO 30720
#define SC_STAGE 40960
#define SC_SMEM (2 * SC_STAGE)     // 81920

// Stage offsets, out kernel (A=P [row][k], B=V [k][n])
#define OU_AHI 0
#define OU_ALO 10240
#define OU_VHI 20480
#define OU_VLO 29184
#define OU_STAGE 37888
#define OU_SMEM (2 * OU_STAGE)     // 75776

// ---------------------------------------------------------------------------
__device__ __forceinline__ uint32_t smem_u32(const void* p) {
    uint32_t a;
    asm("{ .reg .u64 t; cvta.to.shared.u64 t, %1; cvt.u32.u64 %0, t; }" : "=r"(a) : "l"(p));
    return a;
}

__device__ __forceinline__ void ldmx4(uint32_t& r0, uint32_t& r1, uint32_t& r2,
                                      uint32_t& r3, uint32_t addr) {
    asm volatile("ldmatrix.sync.aligned.m8n8.x4.shared.b16 {%0,%1,%2,%3}, [%4];"
                 : "=r"(r0), "=r"(r1), "=r"(r2), "=r"(r3) : "r"(addr));
}
__device__ __forceinline__ void ldmx4t(uint32_t& r0, uint32_t& r1, uint32_t& r2,
                                       uint32_t& r3, uint32_t addr) {
    asm volatile("ldmatrix.sync.aligned.m8n8.x4.trans.shared.b16 {%0,%1,%2,%3}, [%4];"
                 : "=r"(r0), "=r"(r1), "=r"(r2), "=r"(r3) : "r"(addr));
}

// m16n8k16 bf16 mma, fp32 accumulate
__device__ __forceinline__ void mma_bf16(float c[4], const uint32_t a[4],
                                         uint32_t b0, uint32_t b1) {
    asm("mma.sync.aligned.m16n8k16.row.col.f32.bf16.bf16.f32 "
        "{%0,%1,%2,%3}, {%4,%5,%6,%7}, {%8,%9}, {%0,%1,%2,%3};"
        : "+f"(c[0]), "+f"(c[1]), "+f"(c[2]), "+f"(c[3])
        : "r"(a[0]), "r"(a[1]), "r"(a[2]), "r"(a[3]), "r"(b0), "r"(b1));
}

// Split float4 into packed bf16 hi (4 vals) + lo (4 vals)
__device__ __forceinline__ void split4(float4 v, uint2& h, uint2& l) {
    __nv_bfloat16 h0 = __float2bfloat16_rn(v.x);
    __nv_bfloat16 h1 = __float2bfloat16_rn(v.y);
    __nv_bfloat16 h2 = __float2bfloat16_rn(v.z);
    __nv_bfloat16 h3 = __float2bfloat16_rn(v.w);
    __nv_bfloat16 l0 = __float2bfloat16_rn(v.x - __bfloat162float(h0));
    __nv_bfloat16 l1 = __float2bfloat16_rn(v.y - __bfloat162float(h1));
    __nv_bfloat16 l2 = __float2bfloat16_rn(v.z - __bfloat162float(h2));
    __nv_bfloat16 l3 = __float2bfloat16_rn(v.w - __bfloat162float(h3));
    __nv_bfloat162 ph0 = __halves2bfloat162(h0, h1);
    __nv_bfloat162 ph1 = __halves2bfloat162(h2, h3);
    __nv_bfloat162 pl0 = __halves2bfloat162(l0, l1);
    __nv_bfloat162 pl1 = __halves2bfloat162(l2, l3);
    h.x = *(uint32_t*)&ph0; h.y = *(uint32_t*)&ph1;
    l.x = *(uint32_t*)&pl0; l.y = *(uint32_t*)&pl1;
}

// LDG a 128x32 fp32 tile, split, STS into hi/lo (short-lived staging regs)
__device__ __forceinline__ void load32(const float* base, int row_stride, int k0,
                                       int tid, char* hi, char* lo) {
    float4 st[4];
#pragma unroll
    for (int j = 0; j < 4; j++) {
        int idx = tid + j * 256;
        int row = idx >> 3, c4 = idx & 7;
        st[j] = *(const float4*)(base + (size_t)row * row_stride + k0 + c4 * 4);
    }
#pragma unroll
    for (int j = 0; j < 4; j++) {
        int idx = tid + j * 256;
        int row = idx >> 3, c4 = idx & 7;
        uint2 h, l; split4(st[j], h, l);
        *(uint2*)(hi + row * SA + c4 * 8) = h;
        *(uint2*)(lo + row * SA + c4 * 8) = l;
    }
}
// LDG a 32x128 fp32 V tile, split, STS with SV stride
__device__ __forceinline__ void loadV(const float* vb, int k0, int n0, int tid,
                                      char* hi, char* lo) {
    float4 st[4];
#pragma unroll
    for (int j = 0; j < 4; j++) {
        int idx = tid + j * 256;
        int row = idx >> 5, c4 = idx & 31;
        st[j] = *(const float4*)(vb + (size_t)(k0 + row) * DIM + n0 + c4 * 4);
    }
#pragma unroll
    for (int j = 0; j < 4; j++) {
        int idx = tid + j * 256;
        int row = idx >> 5, c4 = idx & 31;
        uint2 h, l; split4(st[j], h, l);
        *(uint2*)(hi + row * SV + c4 * 8) = h;
        *(uint2*)(lo + row * SV + c4 * 8) = l;
    }
}

// ---------------------------------------------------------------------------
// Kernel 1: masked raw scores = scale * Q @ K^T  (into attn region)
// Grid (16,16,BATCH), 256 threads, tile 128x128, BK=32, double buffered,
// prefetch-at-top structure so staging regs are short-lived (2 CTAs/SM).
// ---------------------------------------------------------------------------
__global__ __launch_bounds__(256, 2)
void scores_tc(const float* __restrict__ q, const float* __restrict__ kk,
               const int* __restrict__ mask, float* __restrict__ s)
{
    extern __shared__ char smem[];
    const uint32_t sbase = smem_u32(smem);
    const int tid  = threadIdx.x;
    const int lane = tid & 31;
    const int wid  = tid >> 5;
    const int wm = wid & 1, wn = wid >> 1;
    const int g = lane >> 2, t = lane & 3;
    const int b  = blockIdx.z;
    const int m0 = blockIdx.y * 128;
    const int n0 = blockIdx.x * 128;

    const float* qb = q  + (size_t)b * SEQ * DIM + (size_t)m0 * DIM;
    const float* kb = kk + (size_t)b * SEQ * DIM + (size_t)n0 * DIM;

    const int mBase = wm * 64;
    const int nBase = wn * 32;
    const uint32_t aRowOff = (uint32_t)(mBase + (lane & 15)) * SA + ((lane >> 4) << 4);
    const uint32_t bRowOff = (uint32_t)(nBase + (lane & 7) + ((lane >> 4) << 3)) * SA
                           + (((lane >> 3) & 1) << 4);

    float acc[4][4][4];
#pragma unroll
    for (int i = 0; i < 4; i++)
#pragma unroll
        for (int j = 0; j < 4; j++)
#pragma unroll
            for (int c = 0; c < 4; c++) acc[i][j][c] = 0.0f;

    // Prologue: fill stage 0
    load32(qb, DIM, 0, tid, smem + SC_AHI, smem + SC_ALO);
    load32(kb, DIM, 0, tid, smem + SC_BHI, smem + SC_BLO);
    __syncthreads();

    const int NC = DIM / BKC;   // 8
    for (int c = 0; c < NC; c++) {
        const uint32_t stg = sbase + (c & 1) * SC_STAGE;
        // Prefetch next chunk into the other stage (free since last sync)
        if (c + 1 < NC) {
            char* nx = smem + ((c + 1) & 1) * SC_STAGE;
            load32(qb, DIM, (c + 1) * BKC, tid, nx + SC_AHI, nx + SC_ALO);
            load32(kb, DIM, (c + 1) * BKC, tid, nx + SC_BHI, nx + SC_BLO);
        }
#pragma unroll
        for (int ks = 0; ks < 2; ks++) {
            const uint32_t kByte = (uint32_t)(ks * 32);
            uint32_t bh[4][2], bl[4][2];
#pragma unroll
            for (int np = 0; np < 2; np++) {
                uint32_t addr = stg + SC_BHI + bRowOff + np * 16 * SA + kByte;
                uint32_t r0, r1, r2, r3;
                ldmx4(r0, r1, r2, r3, addr);
                bh[2*np][0] = r0; bh[2*np][1] = r1;
                bh[2*np+1][0] = r2; bh[2*np+1][1] = r3;
                ldmx4(r0, r1, r2, r3, addr + (SC_BLO - SC_BHI));
                bl[2*np][0] = r0; bl[2*np][1] = r1;
                bl[2*np+1][0] = r2; bl[2*np+1][1] = r3;
            }
#pragma unroll
            for (int mt = 0; mt < 4; mt++) {
                uint32_t addr = stg + SC_AHI + aRowOff + mt * 16 * SA + kByte;
                uint32_t ah[4], al[4];
                ldmx4(ah[0], ah[1], ah[2], ah[3], addr);
                ldmx4(al[0], al[1], al[2], al[3], addr + (SC_ALO - SC_AHI));
#pragma unroll
                for (int nt = 0; nt < 4; nt++) {
                    mma_bf16(acc[mt][nt], ah, bh[nt][0], bh[nt][1]);
                    mma_bf16(acc[mt][nt], ah, bl[nt][0], bl[nt][1]);
                    mma_bf16(acc[mt][nt], al, bh[nt][0], bh[nt][1]);
                }
            }
        }
        __syncthreads();
    }

    // Epilogue: scale + mask -> raw masked scores
    float* sb = s + (size_t)b * SEQ * SEQ;
#pragma unroll
    for (int mt = 0; mt < 4; mt++) {
        int r0 = m0 + mBase + mt * 16 + g;
#pragma unroll
        for (int nt = 0; nt < 4; nt++) {
            int col = n0 + nBase + nt * 8 + 2 * t;
            int2 mv0 = *(const int2*)(mask + (size_t)r0 * SEQ + col);
            int2 mv1 = *(const int2*)(mask + (size_t)(r0 + 8) * SEQ + col);
            float2 o0, o1;
            o0.x = mv0.x ? acc[mt][nt][0] * ATTN_SCALE : -1e30f;
            o0.y = mv0.y ? acc[mt][nt][1] * ATTN_SCALE : -1e30f;
            o1.x = mv1.x ? acc[mt][nt][2] * ATTN_SCALE : -1e30f;
            o1.y = mv1.y ? acc[mt][nt][3] * ATTN_SCALE : -1e30f;
            *(float2*)(sb + (size_t)r0 * SEQ + col) = o0;
            *(float2*)(sb + (size_t)(r0 + 8) * SEQ + col) = o1;
        }
    }
}

// ---------------------------------------------------------------------------
// Kernel 2: row softmax in place (proven baseline).
// ---------------------------------------------------------------------------
__global__ __launch_bounds__(256)
void softmax_kernel(float* __restrict__ s)
{
    __shared__ float red[8];
    float* p = s + (size_t)blockIdx.x * SEQ;
    const int tid = threadIdx.x;

    float4 v0 = *((const float4*)p + tid);
    float4 v1 = *((const float4*)p + tid + 256);

    float m = fmaxf(fmaxf(fmaxf(v0.x, v0.y), fmaxf(v0.z, v0.w)),
                    fmaxf(fmaxf(v1.x, v1.y), fmaxf(v1.z, v1.w)));
#pragma unroll
    for (int o = 16; o > 0; o >>= 1) m = fmaxf(m, __shfl_xor_sync(0xFFFFFFFFu, m, o));
    if ((tid & 31) == 0) red[tid >> 5] = m;
    __syncthreads();
    m = red[0];
#pragma unroll
    for (int w = 1; w < 8; w++) m = fmaxf(m, red[w]);
    __syncthreads();

    float4 e0, e1;
    e0.x = __expf(v0.x - m); e0.y = __expf(v0.y - m);
    e0.z = __expf(v0.z - m); e0.w = __expf(v0.w - m);
    e1.x = __expf(v1.x - m); e1.y = __expf(v1.y - m);
    e1.z = __expf(v1.z - m); e1.w = __expf(v1.w - m);

    float sum = (e0.x + e0.y) + (e0.z + e0.w) + (e1.x + e1.y) + (e1.z + e1.w);
#pragma unroll
    for (int o = 16; o > 0; o >>= 1) sum += __shfl_xor_sync(0xFFFFFFFFu, sum, o);
    if ((tid & 31) == 0) red[tid >> 5] = sum;
    __syncthreads();
    float tot = red[0];
#pragma unroll
    for (int w = 1; w < 8; w++) tot += red[w];

    float inv = 1.0f / tot;
    e0.x *= inv; e0.y *= inv; e0.z *= inv; e0.w *= inv;
    e1.x *= inv; e1.y *= inv; e1.z *= inv; e1.w *= inv;
    *((float4*)p + tid) = e0;
    *((float4*)p + tid + 256) = e1;
}

// ---------------------------------------------------------------------------
// Kernel 3: output = P @ V.  Grid (2,16,BATCH), 256 threads, tile 128x128.
// V kept [k][n]; B fragments via ldmatrix.x4.trans. Same pipeline structure.
// ---------------------------------------------------------------------------
__global__ __launch_bounds__(256, 2)
void out_tc(const float* __restrict__ p, const float* __restrict__ v,
            float* __restrict__ o)
{
    extern __shared__ char smem[];
    const uint32_t sbase = smem_u32(smem);
    const int tid  = threadIdx.x;
    const int lane = tid & 31;
    const int wid  = tid >> 5;
    const int wm = wid & 1, wn = wid >> 1;
    const int g = lane >> 2, t = lane & 3;
    const int b  = blockIdx.z;
    const int m0 = blockIdx.y * 128;
    const int n0 = blockIdx.x * 128;

    const float* pb = p + (size_t)b * SEQ * SEQ + (size_t)m0 * SEQ;
    const float* vb = v + (size_t)b * SEQ * DIM;

    const int mBase = wm * 64;
    const int nBase = wn * 32;
    const uint32_t aRowOff = (uint32_t)(mBase + (lane & 15)) * SA + ((lane >> 4) << 4);
    const uint32_t vRow = (uint32_t)((lane & 7) + (((lane >> 3) & 1) << 3));
    const uint32_t vNOff = (uint32_t)(nBase + ((lane >> 4) << 3)) * 2;

    float acc[4][4][4];
#pragma unroll
    for (int i = 0; i < 4; i++)
#pragma unroll
        for (int j = 0; j < 4; j++)
#pragma unroll
            for (int c = 0; c < 4; c++) acc[i][j][c] = 0.0f;

    load32(pb, SEQ, 0, tid, smem + OU_AHI, smem + OU_ALO);
    loadV(vb, 0, n0, tid, smem + OU_VHI, smem + OU_VLO);
    __syncthreads();

    const int NC = SEQ / BKC;   // 64
    for (int c = 0; c < NC; c++) {
        const uint32_t stg = sbase + (c & 1) * OU_STAGE;
        if (c + 1 < NC) {
            char* nx = smem + ((c + 1) & 1) * OU_STAGE;
            load32(pb, SEQ, (c + 1) * BKC, tid, nx + OU_AHI, nx + OU_ALO);
            loadV(vb, (c + 1) * BKC, n0, tid, nx + OU_VHI, nx + OU_VLO);
        }
#pragma unroll
        for (int ks = 0; ks < 2; ks++) {
            uint32_t bh[4][2], bl[4][2];
#pragma unroll
            for (int np = 0; np < 2; np++) {
                uint32_t addr = stg + OU_VHI + (ks * 16 + vRow) * SV + vNOff + np * 32;
                uint32_t r0, r1, r2, r3;
                ldmx4t(r0, r1, r2, r3, addr);
                bh[2*np][0] = r0; bh[2*np][1] = r1;
                bh[2*np+1][0] = r2; bh[2*np+1][1] = r3;
                ldmx4t(r0, r1, r2, r3, addr + (OU_VLO - OU_VHI));
                bl[2*np][0] = r0; bl[2*np][1] = r1;
                bl[2*np+1][0] = r2; bl[2*np+1][1] = r3;
            }
#pragma unroll
            for (int mt = 0; mt < 4; mt++) {
                uint32_t addr = stg + OU_AHI + aRowOff + mt * 16 * SA + ks * 32;
                uint32_t ah[4], al[4];
                ldmx4(ah[0], ah[1], ah[2], ah[3], addr);
                ldmx4(al[0], al[1], al[2], al[3], addr + (OU_ALO - OU_AHI));
#pragma unroll
                for (int nt = 0; nt < 4; nt++) {
                    mma_bf16(acc[mt][nt], ah, bh[nt][0], bh[nt][1]);
                    mma_bf16(acc[mt][nt], ah, bl[nt][0], bl[nt][1]);
                    mma_bf16(acc[mt][nt], al, bh[nt][0], bh[nt][1]);
                }
            }
        }
        __syncthreads();
    }

    float* ob = o + (size_t)b * SEQ * DIM;
#pragma unroll
    for (int mt = 0; mt < 4; mt++) {
        int r0 = m0 + mBase + mt * 16 + g;
#pragma unroll
        for (int nt = 0; nt < 4; nt++) {
            int col = n0 + nBase + nt * 8 + 2 * t;
            *(float2*)(ob + (size_t)r0 * DIM + col) =
                make_float2(acc[mt][nt][0], acc[mt][nt][1]);
            *(float2*)(ob + (size_t)(r0 + 8) * DIM + col) =
                make_float2(acc[mt][nt][2], acc[mt][nt][3]);
        }
    }
}

// ---------------------------------------------------------------------------
extern "C" void kernel_launch(void* const* d_in, const int* in_sizes, int n_in,
                              void* d_out, int out_size)
{
    const float* q    = (const float*)d_in[0];
    const float* k    = (const float*)d_in[1];
    const float* v    = (const float*)d_in[2];
    const int*   mask = (const int*)d_in[3];

    float* out  = (float*)d_out;                      // [B, S, D]
    float* attn = out + (size_t)BATCH * SEQ * DIM;    // [B, S, S]

    cudaFuncSetAttribute(scores_tc, cudaFuncAttributeMaxDynamicSharedMemorySize, SC_SMEM);
    cudaFuncSetAttribute(out_tc,    cudaFuncAttributeMaxDynamicSharedMemorySize, OU_SMEM);

    dim3 blk(256);
    scores_tc<<<dim3(SEQ / 128, SEQ / 128, BATCH), blk, SC_SMEM>>>(q, k, mask, attn);
    softmax_kernel<<<BATCH * SEQ, blk>>>(attn);
    out_tc<<<dim3(DIM / 128, SEQ / 128, BATCH), blk, OU_SMEM>>>(attn, v, out);
}

// round 8
// speedup vs baseline: 2.6964x; 1.0462x over previous
#include <cuda_runtime.h>
#include <cuda_bf16.h>
#include <cstdint>

// Problem constants
#define BATCH 16
#define SEQ   2048
#define DIM   256
#define ATTN_SCALE 0.0625f   // 1/sqrt(256)

#define BKC 32      // K-chunk (elements)
#define SA  80      // A tile row stride bytes (64B data + 16B pad)
#define SV  272     // 128-col V/B tile row stride (256B + 16B pad)
#define SV2 528     // 256-col V tile row stride (512B + 16B pad)

// Stage offsets, scores kernel (A=Q[128x32], B=K[128x32])
#define SC_AHI 0
#define SC_ALO 10240
#define SC_BHI 20480
#define SC_BLO 30720
#define SC_STAGE 40960
#define SC_SMEM (2 * SC_STAGE)     // 81920

// Stage offsets, fused out kernel (A=E[64x32], V[32x256])
#define OU_AHI 0
#define OU_ALO 5120
#define OU_VHI 10240
#define OU_VLO 27136
#define OU_STAGE 44032
#define OU_SMEM (2 * OU_STAGE)     // 88064

// Deterministic softmax-denominator scratch (device globals: allowed scratch)
__device__ float g_zpart[(size_t)BATCH * SEQ * 64];   // 8 MB
__device__ float g_invz[(size_t)BATCH * SEQ];         // 128 KB

// ---------------------------------------------------------------------------
__device__ __forceinline__ uint32_t smem_u32(const void* p) {
    uint32_t a;
    asm("{ .reg .u64 t; cvta.to.shared.u64 t, %1; cvt.u32.u64 %0, t; }" : "=r"(a) : "l"(p));
    return a;
}

__device__ __forceinline__ void ldmx4(uint32_t& r0, uint32_t& r1, uint32_t& r2,
                                      uint32_t& r3, uint32_t addr) {
    asm volatile("ldmatrix.sync.aligned.m8n8.x4.shared.b16 {%0,%1,%2,%3}, [%4];"
                 : "=r"(r0), "=r"(r1), "=r"(r2), "=r"(r3) : "r"(addr));
}
__device__ __forceinline__ void ldmx4t(uint32_t& r0, uint32_t& r1, uint32_t& r2,
                                       uint32_t& r3, uint32_t addr) {
    asm volatile("ldmatrix.sync.aligned.m8n8.x4.trans.shared.b16 {%0,%1,%2,%3}, [%4];"
                 : "=r"(r0), "=r"(r1), "=r"(r2), "=r"(r3) : "r"(addr));
}

// m16n8k16 bf16 mma, fp32 accumulate
__device__ __forceinline__ void mma_bf16(float c[4], const uint32_t a[4],
                                         uint32_t b0, uint32_t b1) {
    asm("mma.sync.aligned.m16n8k16.row.col.f32.bf16.bf16.f32 "
        "{%0,%1,%2,%3}, {%4,%5,%6,%7}, {%8,%9}, {%0,%1,%2,%3};"
        : "+f"(c[0]), "+f"(c[1]), "+f"(c[2]), "+f"(c[3])
        : "r"(a[0]), "r"(a[1]), "r"(a[2]), "r"(a[3]), "r"(b0), "r"(b1));
}

// Split float4 into packed bf16 hi (4 vals) + lo (4 vals)
__device__ __forceinline__ void split4(float4 v, uint2& h, uint2& l) {
    __nv_bfloat16 h0 = __float2bfloat16_rn(v.x);
    __nv_bfloat16 h1 = __float2bfloat16_rn(v.y);
    __nv_bfloat16 h2 = __float2bfloat16_rn(v.z);
    __nv_bfloat16 h3 = __float2bfloat16_rn(v.w);
    __nv_bfloat16 l0 = __float2bfloat16_rn(v.x - __bfloat162float(h0));
    __nv_bfloat16 l1 = __float2bfloat16_rn(v.y - __bfloat162float(h1));
    __nv_bfloat16 l2 = __float2bfloat16_rn(v.z - __bfloat162float(h2));
    __nv_bfloat16 l3 = __float2bfloat16_rn(v.w - __bfloat162float(h3));
    __nv_bfloat162 ph0 = __halves2bfloat162(h0, h1);
    __nv_bfloat162 ph1 = __halves2bfloat162(h2, h3);
    __nv_bfloat162 pl0 = __halves2bfloat162(l0, l1);
    __nv_bfloat162 pl1 = __halves2bfloat162(l2, l3);
    h.x = *(uint32_t*)&ph0; h.y = *(uint32_t*)&ph1;
    l.x = *(uint32_t*)&pl0; l.y = *(uint32_t*)&pl1;
}

// LDG a 128x32 fp32 tile, split, STS into hi/lo (short-lived staging regs)
__device__ __forceinline__ void load32(const float* base, int row_stride, int k0,
                                       int tid, char* hi, char* lo) {
    float4 st[4];
#pragma unroll
    for (int j = 0; j < 4; j++) {
        int idx = tid + j * 256;
        int row = idx >> 3, c4 = idx & 7;
        st[j] = *(const float4*)(base + (size_t)row * row_stride + k0 + c4 * 4);
    }
#pragma unroll
    for (int j = 0; j < 4; j++) {
        int idx = tid + j * 256;
        int row = idx >> 3, c4 = idx & 7;
        uint2 h, l; split4(st[j], h, l);
        *(uint2*)(hi + row * SA + c4 * 8) = h;
        *(uint2*)(lo + row * SA + c4 * 8) = l;
    }
}

// K3: LDG a 64x32 fp32 E tile, write normalized P back in place, split+STS.
__device__ __forceinline__ void loadE(const float* pb, float* pw, int k0, int tid,
                                      float iz0, float iz1, char* hi, char* lo) {
    float4 st[2];
#pragma unroll
    for (int j = 0; j < 2; j++) {
        int idx = tid + j * 256;
        int row = idx >> 3, c4 = idx & 7;
        st[j] = *(const float4*)(pb + (size_t)row * SEQ + k0 + c4 * 4);
    }
#pragma unroll
    for (int j = 0; j < 2; j++) {
        int idx = tid + j * 256;
        int row = idx >> 3, c4 = idx & 7;
        float iz = j ? iz1 : iz0;
        float4 p = make_float4(st[j].x * iz, st[j].y * iz, st[j].z * iz, st[j].w * iz);
        *(float4*)(pw + (size_t)row * SEQ + k0 + c4 * 4) = p;
        uint2 h, l; split4(st[j], h, l);
        *(uint2*)(hi + row * SA + c4 * 8) = h;
        *(uint2*)(lo + row * SA + c4 * 8) = l;
    }
}

// K3: LDG a 32x256 fp32 V tile, split, STS (two 4-float4 batches to cap regs)
__device__ __forceinline__ void loadV256(const float* vb, int k0, int tid,
                                         char* hi, char* lo) {
#pragma unroll
    for (int half = 0; half < 2; half++) {
        float4 st[4];
#pragma unroll
        for (int j = 0; j < 4; j++) {
            int idx = tid + (half * 4 + j) * 256;
            int row = idx >> 6, c4 = idx & 63;
            st[j] = *(const float4*)(vb + (size_t)(k0 + row) * DIM + c4 * 4);
        }
#pragma unroll
        for (int j = 0; j < 4; j++) {
            int idx = tid + (half * 4 + j) * 256;
            int row = idx >> 6, c4 = idx & 63;
            uint2 h, l; split4(st[j], h, l);
            *(uint2*)(hi + row * SV2 + c4 * 8) = h;
            *(uint2*)(lo + row * SV2 + c4 * 8) = l;
        }
    }
}

// ---------------------------------------------------------------------------
// Kernel 1: E = mask ? exp(scale * Q@K^T) : 0   (into attn region)
// + deterministic partial row sums into g_zpart[b][row][x*4+wn].
// Grid (16,16,BATCH), 256 threads, tile 128x128.
// ---------------------------------------------------------------------------
__global__ __launch_bounds__(256, 2)
void scores_tc(const float* __restrict__ q, const float* __restrict__ kk,
               const int* __restrict__ mask, float* __restrict__ s)
{
    extern __shared__ char smem[];
    const uint32_t sbase = smem_u32(smem);
    const int tid  = threadIdx.x;
    const int lane = tid & 31;
    const int wid  = tid >> 5;
    const int wm = wid & 1, wn = wid >> 1;
    const int g = lane >> 2, t = lane & 3;
    const int b  = blockIdx.z;
    const int m0 = blockIdx.y * 128;
    const int n0 = blockIdx.x * 128;

    const float* qb = q  + (size_t)b * SEQ * DIM + (size_t)m0 * DIM;
    const float* kb = kk + (size_t)b * SEQ * DIM + (size_t)n0 * DIM;

    const int mBase = wm * 64;
    const int nBase = wn * 32;
    const uint32_t aRowOff = (uint32_t)(mBase + (lane & 15)) * SA + ((lane >> 4) << 4);
    const uint32_t bRowOff = (uint32_t)(nBase + (lane & 7) + ((lane >> 4) << 3)) * SA
                           + (((lane >> 3) & 1) << 4);

    float acc[4][4][4];
#pragma unroll
    for (int i = 0; i < 4; i++)
#pragma unroll
        for (int j = 0; j < 4; j++)
#pragma unroll
            for (int c = 0; c < 4; c++) acc[i][j][c] = 0.0f;

    load32(qb, DIM, 0, tid, smem + SC_AHI, smem + SC_ALO);
    load32(kb, DIM, 0, tid, smem + SC_BHI, smem + SC_BLO);
    __syncthreads();

    const int NC = DIM / BKC;   // 8
    for (int c = 0; c < NC; c++) {
        const uint32_t stg = sbase + (c & 1) * SC_STAGE;
        if (c + 1 < NC) {
            char* nx = smem + ((c + 1) & 1) * SC_STAGE;
            load32(qb, DIM, (c + 1) * BKC, tid, nx + SC_AHI, nx + SC_ALO);
            load32(kb, DIM, (c + 1) * BKC, tid, nx + SC_BHI, nx + SC_BLO);
        }
#pragma unroll
        for (int ks = 0; ks < 2; ks++) {
            const uint32_t kByte = (uint32_t)(ks * 32);
            uint32_t bh[4][2], bl[4][2];
#pragma unroll
            for (int np = 0; np < 2; np++) {
                uint32_t addr = stg + SC_BHI + bRowOff + np * 16 * SA + kByte;
                uint32_t r0, r1, r2, r3;
                ldmx4(r0, r1, r2, r3, addr);
                bh[2*np][0] = r0; bh[2*np][1] = r1;
                bh[2*np+1][0] = r2; bh[2*np+1][1] = r3;
                ldmx4(r0, r1, r2, r3, addr + (SC_BLO - SC_BHI));
                bl[2*np][0] = r0; bl[2*np][1] = r1;
                bl[2*np+1][0] = r2; bl[2*np+1][1] = r3;
            }
#pragma unroll
            for (int mt = 0; mt < 4; mt++) {
                uint32_t addr = stg + SC_AHI + aRowOff + mt * 16 * SA + kByte;
                uint32_t ah[4], al[4];
                ldmx4(ah[0], ah[1], ah[2], ah[3], addr);
                ldmx4(al[0], al[1], al[2], al[3], addr + (SC_ALO - SC_AHI));
#pragma unroll
                for (int nt = 0; nt < 4; nt++) {
                    mma_bf16(acc[mt][nt], ah, bh[nt][0], bh[nt][1]);
                    mma_bf16(acc[mt][nt], ah, bl[nt][0], bl[nt][1]);
                    mma_bf16(acc[mt][nt], al, bh[nt][0], bh[nt][1]);
                }
            }
        }
        __syncthreads();
    }

    // Epilogue: E = mask ? exp(scale*s) : 0, plus partial row sums.
    float* sb = s + (size_t)b * SEQ * SEQ;
    const int ztile = blockIdx.x * 4 + wn;
#pragma unroll
    for (int mt = 0; mt < 4; mt++) {
        int r0 = m0 + mBase + mt * 16 + g;
        float sum0 = 0.0f, sum1 = 0.0f;
#pragma unroll
        for (int nt = 0; nt < 4; nt++) {
            int col = n0 + nBase + nt * 8 + 2 * t;
            int2 mv0 = *(const int2*)(mask + (size_t)r0 * SEQ + col);
            int2 mv1 = *(const int2*)(mask + (size_t)(r0 + 8) * SEQ + col);
            float2 o0, o1;
            o0.x = mv0.x ? __expf(acc[mt][nt][0] * ATTN_SCALE) : 0.0f;
            o0.y = mv0.y ? __expf(acc[mt][nt][1] * ATTN_SCALE) : 0.0f;
            o1.x = mv1.x ? __expf(acc[mt][nt][2] * ATTN_SCALE) : 0.0f;
            o1.y = mv1.y ? __expf(acc[mt][nt][3] * ATTN_SCALE) : 0.0f;
            sum0 += o0.x + o0.y;
            sum1 += o1.x + o1.y;
            *(float2*)(sb + (size_t)r0 * SEQ + col) = o0;
            *(float2*)(sb + (size_t)(r0 + 8) * SEQ + col) = o1;
        }
        // quad reduce over t (lanes 4g..4g+3)
        sum0 += __shfl_xor_sync(0xFFFFFFFFu, sum0, 1);
        sum0 += __shfl_xor_sync(0xFFFFFFFFu, sum0, 2);
        sum1 += __shfl_xor_sync(0xFFFFFFFFu, sum1, 1);
        sum1 += __shfl_xor_sync(0xFFFFFFFFu, sum1, 2);
        if (t == 0) {
            g_zpart[((size_t)b * SEQ + r0) * 64 + ztile]       = sum0;
            g_zpart[((size_t)b * SEQ + r0 + 8) * 64 + ztile]   = sum1;
        }
    }
}

// ---------------------------------------------------------------------------
// Kernel 2: invZ[row] = 1 / sum(zpart[row][0..63]).  Grid 128 x 256.
// ---------------------------------------------------------------------------
__global__ __launch_bounds__(256)
void zreduce_kernel()
{
    int i = blockIdx.x * 256 + threadIdx.x;   // 0..32767
    const float4* zp = (const float4*)(g_zpart + (size_t)i * 64);
    float s = 0.0f;
#pragma unroll
    for (int j = 0; j < 16; j++) {
        float4 v = zp[j];
        s += (v.x + v.y) + (v.z + v.w);
    }
    g_invz[i] = 1.0f / s;
}

// ---------------------------------------------------------------------------
// Kernel 3: O = (E @ V) * invZ, and rewrite P = E * invZ in place.
// Grid (1, 32, BATCH): CTA tile 64 rows x 256 cols, warps 1x8 (64x32 each).
// Each row-block's E is read by exactly one CTA -> in-place normalize is safe.
// ---------------------------------------------------------------------------
__global__ __launch_bounds__(256, 2)
void out_fused(float* __restrict__ attn, const float* __restrict__ v,
               float* __restrict__ o)
{
    extern __shared__ char smem[];
    const uint32_t sbase = smem_u32(smem);
    const int tid  = threadIdx.x;
    const int lane = tid & 31;
    const int wid  = tid >> 5;           // 0..7 = n-tile
    const int g = lane >> 2, t = lane & 3;
    const int b  = blockIdx.z;
    const int m0 = blockIdx.y * 64;

    float* pb = attn + (size_t)b * SEQ * SEQ + (size_t)m0 * SEQ;
    const float* vb = v + (size_t)b * SEQ * DIM;

    const int nBase = wid * 32;
    const uint32_t aRowOff = (uint32_t)(lane & 15) * SA + ((lane >> 4) << 4);
    const uint32_t vRow = (uint32_t)((lane & 7) + (((lane >> 3) & 1) << 3));
    const uint32_t vNOff = (uint32_t)(nBase + ((lane >> 4) << 3)) * 2;

    // invZ for this thread's two A-load rows (row0 = tid>>3, row1 = row0+32)
    const int lrow0 = tid >> 3;
    const float iz0 = g_invz[(size_t)b * SEQ + m0 + lrow0];
    const float iz1 = g_invz[(size_t)b * SEQ + m0 + lrow0 + 32];

    float acc[4][4][4];
#pragma unroll
    for (int i = 0; i < 4; i++)
#pragma unroll
        for (int j = 0; j < 4; j++)
#pragma unroll
            for (int c = 0; c < 4; c++) acc[i][j][c] = 0.0f;

    loadE(pb, pb, 0, tid, iz0, iz1, smem + OU_AHI, smem + OU_ALO);
    loadV256(vb, 0, tid, smem + OU_VHI, smem + OU_VLO);
    __syncthreads();

    const int NC = SEQ / BKC;   // 64
    for (int c = 0; c < NC; c++) {
        const uint32_t stg = sbase + (c & 1) * OU_STAGE;
        if (c + 1 < NC) {
            char* nx = smem + ((c + 1) & 1) * OU_STAGE;
            loadE(pb, pb, (c + 1) * BKC, tid, iz0, iz1, nx + OU_AHI, nx + OU_ALO);
            loadV256(vb, (c + 1) * BKC, tid, nx + OU_VHI, nx + OU_VLO);
        }
#pragma unroll
        for (int ks = 0; ks < 2; ks++) {
            uint32_t bh[4][2], bl[4][2];
#pragma unroll
            for (int np = 0; np < 2; np++) {
                uint32_t addr = stg + OU_VHI + (ks * 16 + vRow) * SV2 + vNOff + np * 32;
                uint32_t r0, r1, r2, r3;
                ldmx4t(r0, r1, r2, r3, addr);
                bh[2*np][0] = r0; bh[2*np][1] = r1;
                bh[2*np+1][0] = r2; bh[2*np+1][1] = r3;
                ldmx4t(r0, r1, r2, r3, addr + (OU_VLO - OU_VHI));
                bl[2*np][0] = r0; bl[2*np][1] = r1;
                bl[2*np+1][0] = r2; bl[2*np+1][1] = r3;
            }
#pragma unroll
            for (int mt = 0; mt < 4; mt++) {
                uint32_t addr = stg + OU_AHI + aRowOff + mt * 16 * SA + ks * 32;
                uint32_t ah[4], al[4];
                ldmx4(ah[0], ah[1], ah[2], ah[3], addr);
                ldmx4(al[0], al[1], al[2], al[3], addr + (OU_ALO - OU_AHI));
#pragma unroll
                for (int nt = 0; nt < 4; nt++) {
                    mma_bf16(acc[mt][nt], ah, bh[nt][0], bh[nt][1]);
                    mma_bf16(acc[mt][nt], ah, bl[nt][0], bl[nt][1]);
                    mma_bf16(acc[mt][nt], al, bh[nt][0], bh[nt][1]);
                }
            }
        }
        __syncthreads();
    }

    // Epilogue: O = acc * invZ[row]
    float* ob = o + (size_t)b * SEQ * DIM;
#pragma unroll
    for (int mt = 0; mt < 4; mt++) {
        int r0 = m0 + mt * 16 + g;
        float z0 = g_invz[(size_t)b * SEQ + r0];
        float z1 = g_invz[(size_t)b * SEQ + r0 + 8];
#pragma unroll
        for (int nt = 0; nt < 4; nt++) {
            int col = nBase + nt * 8 + 2 * t;
            *(float2*)(ob + (size_t)r0 * DIM + col) =
                make_float2(acc[mt][nt][0] * z0, acc[mt][nt][1] * z0);
            *(float2*)(ob + (size_t)(r0 + 8) * DIM + col) =
                make_float2(acc[mt][nt][2] * z1, acc[mt][nt][3] * z1);
        }
    }
}

// ---------------------------------------------------------------------------
extern "C" void kernel_launch(void* const* d_in, const int* in_sizes, int n_in,
                              void* d_out, int out_size)
{
    const float* q    = (const float*)d_in[0];
    const float* k    = (const float*)d_in[1];
    const float* v    = (const float*)d_in[2];
    const int*   mask = (const int*)d_in[3];

    float* out  = (float*)d_out;                      // [B, S, D]
    float* attn = out + (size_t)BATCH * SEQ * DIM;    // [B, S, S]

    cudaFuncSetAttribute(scores_tc, cudaFuncAttributeMaxDynamicSharedMemorySize, SC_SMEM);
    cudaFuncSetAttribute(out_fused, cudaFuncAttributeMaxDynamicSharedMemorySize, OU_SMEM);

    dim3 blk(256);
    scores_tc<<<dim3(SEQ / 128, SEQ / 128, BATCH), blk, SC_SMEM>>>(q, k, mask, attn);
    zreduce_kernel<<<BATCH * SEQ / 256, blk>>>();
    out_fused<<<dim3(1, SEQ / 64, BATCH), blk, OU_SMEM>>>(attn, v, out);
}

// round 9
// speedup vs baseline: 3.1913x; 1.1835x over previous
#include <cuda_runtime.h>
#include <cuda_fp16.h>
#include <cstdint>

// Problem constants
#define BATCH 16
#define SEQ   2048
#define DIM   256
#define ATTN_SCALE 0.0625f   // 1/sqrt(256)

#define BKC 32      // K-chunk (elements)
#define SA  80      // A tile row stride bytes (64B data + 16B pad)
#define SV2 528     // 256-col V tile row stride (512B + 16B pad)

// Stage offsets, scores kernel (A=Qhi[128x32], B=Khi/Klo[128x32])
#define SC_AHI 0
#define SC_BHI 10240
#define SC_BLO 20480
#define SC_STAGE 30720
#define SC_SMEM (2 * SC_STAGE)     // 61440

// Stage offsets, fused out kernel (A=Ehi[64x32], V hi/lo[32x256])
#define OU_AHI 0
#define OU_VHI 5120
#define OU_VLO 22016
#define OU_STAGE 38912
#define OU_SMEM (2 * OU_STAGE)     // 77824

// Deterministic softmax-denominator scratch
__device__ float g_zpart[(size_t)BATCH * SEQ * 64];   // 8 MB
__device__ float g_invz[(size_t)BATCH * SEQ];         // 128 KB

// ---------------------------------------------------------------------------
__device__ __forceinline__ uint32_t smem_u32(const void* p) {
    uint32_t a;
    asm("{ .reg .u64 t; cvta.to.shared.u64 t, %1; cvt.u32.u64 %0, t; }" : "=r"(a) : "l"(p));
    return a;
}

__device__ __forceinline__ void ldmx4(uint32_t& r0, uint32_t& r1, uint32_t& r2,
                                      uint32_t& r3, uint32_t addr) {
    asm volatile("ldmatrix.sync.aligned.m8n8.x4.shared.b16 {%0,%1,%2,%3}, [%4];"
                 : "=r"(r0), "=r"(r1), "=r"(r2), "=r"(r3) : "r"(addr));
}
__device__ __forceinline__ void ldmx4t(uint32_t& r0, uint32_t& r1, uint32_t& r2,
                                       uint32_t& r3, uint32_t addr) {
    asm volatile("ldmatrix.sync.aligned.m8n8.x4.trans.shared.b16 {%0,%1,%2,%3}, [%4];"
                 : "=r"(r0), "=r"(r1), "=r"(r2), "=r"(r3) : "r"(addr));
}

// m16n8k16 fp16 mma, fp32 accumulate
__device__ __forceinline__ void mma_f16(float c[4], const uint32_t a[4],
                                        uint32_t b0, uint32_t b1) {
    asm("mma.sync.aligned.m16n8k16.row.col.f32.f16.f16.f32 "
        "{%0,%1,%2,%3}, {%4,%5,%6,%7}, {%8,%9}, {%0,%1,%2,%3};"
        : "+f"(c[0]), "+f"(c[1]), "+f"(c[2]), "+f"(c[3])
        : "r"(a[0]), "r"(a[1]), "r"(a[2]), "r"(a[3]), "r"(b0), "r"(b1));
}

// Convert float4 -> 4 packed fp16 (hi only)
__device__ __forceinline__ void cvt4(float4 v, uint2& h) {
    __half2 a = __floats2half2_rn(v.x, v.y);
    __half2 b = __floats2half2_rn(v.z, v.w);
    h.x = *(uint32_t*)&a; h.y = *(uint32_t*)&b;
}
// Split float4 into fp16 hi + lo
__device__ __forceinline__ void split4(float4 v, uint2& h, uint2& l) {
    __half h0 = __float2half_rn(v.x), h1 = __float2half_rn(v.y);
    __half h2 = __float2half_rn(v.z), h3 = __float2half_rn(v.w);
    __half l0 = __float2half_rn(v.x - __half2float(h0));
    __half l1 = __float2half_rn(v.y - __half2float(h1));
    __half l2 = __float2half_rn(v.z - __half2float(h2));
    __half l3 = __float2half_rn(v.w - __half2float(h3));
    __half2 ph0 = __halves2half2(h0, h1), ph1 = __halves2half2(h2, h3);
    __half2 pl0 = __halves2half2(l0, l1), pl1 = __halves2half2(l2, l3);
    h.x = *(uint32_t*)&ph0; h.y = *(uint32_t*)&ph1;
    l.x = *(uint32_t*)&pl0; l.y = *(uint32_t*)&pl1;
}

// LDG a 128x32 fp32 tile, hi-only convert, STS
__device__ __forceinline__ void loadHi128(const float* base, int row_stride, int k0,
                                          int tid, char* hi) {
    float4 st[4];
#pragma unroll
    for (int j = 0; j < 4; j++) {
        int idx = tid + j * 256;
        int row = idx >> 3, c4 = idx & 7;
        st[j] = *(const float4*)(base + (size_t)row * row_stride + k0 + c4 * 4);
    }
#pragma unroll
    for (int j = 0; j < 4; j++) {
        int idx = tid + j * 256;
        int row = idx >> 3, c4 = idx & 7;
        uint2 h; cvt4(st[j], h);
        *(uint2*)(hi + row * SA + c4 * 8) = h;
    }
}
// LDG a 128x32 fp32 tile, full split, STS hi+lo
__device__ __forceinline__ void loadSplit128(const float* base, int row_stride, int k0,
                                             int tid, char* hi, char* lo) {
    float4 st[4];
#pragma unroll
    for (int j = 0; j < 4; j++) {
        int idx = tid + j * 256;
        int row = idx >> 3, c4 = idx & 7;
        st[j] = *(const float4*)(base + (size_t)row * row_stride + k0 + c4 * 4);
    }
#pragma unroll
    for (int j = 0; j < 4; j++) {
        int idx = tid + j * 256;
        int row = idx >> 3, c4 = idx & 7;
        uint2 h, l; split4(st[j], h, l);
        *(uint2*)(hi + row * SA + c4 * 8) = h;
        *(uint2*)(lo + row * SA + c4 * 8) = l;
    }
}

// K3: LDG a 64x32 fp32 E tile, write normalized P back in place, hi-only STS.
__device__ __forceinline__ void loadE(const float* pb, float* pw, int k0, int tid,
                                      float iz0, float iz1, char* hi) {
    float4 st[2];
#pragma unroll
    for (int j = 0; j < 2; j++) {
        int idx = tid + j * 256;
        int row = idx >> 3, c4 = idx & 7;
        st[j] = *(const float4*)(pb + (size_t)row * SEQ + k0 + c4 * 4);
    }
#pragma unroll
    for (int j = 0; j < 2; j++) {
        int idx = tid + j * 256;
        int row = idx >> 3, c4 = idx & 7;
        float iz = j ? iz1 : iz0;
        float4 p = make_float4(st[j].x * iz, st[j].y * iz, st[j].z * iz, st[j].w * iz);
        *(float4*)(pw + (size_t)row * SEQ + k0 + c4 * 4) = p;
        uint2 h; cvt4(st[j], h);
        *(uint2*)(hi + row * SA + c4 * 8) = h;
    }
}

// K3: LDG a 32x256 fp32 V tile, split, STS (two 4-float4 batches to cap regs)
__device__ __forceinline__ void loadV256(const float* vb, int k0, int tid,
                                         char* hi, char* lo) {
#pragma unroll
    for (int half = 0; half < 2; half++) {
        float4 st[4];
#pragma unroll
        for (int j = 0; j < 4; j++) {
            int idx = tid + (half * 4 + j) * 256;
            int row = idx >> 6, c4 = idx & 63;
            st[j] = *(const float4*)(vb + (size_t)(k0 + row) * DIM + c4 * 4);
        }
#pragma unroll
        for (int j = 0; j < 4; j++) {
            int idx = tid + (half * 4 + j) * 256;
            int row = idx >> 6, c4 = idx & 63;
            uint2 h, l; split4(st[j], h, l);
            *(uint2*)(hi + row * SV2 + c4 * 8) = h;
            *(uint2*)(lo + row * SV2 + c4 * 8) = l;
        }
    }
}

// ---------------------------------------------------------------------------
// Kernel 1: E = mask ? exp(scale * Q@K^T) : 0   (into attn region)
// 2-term fp16: Qhi·Khi + Qhi·Klo. Grid (16,16,BATCH), 256 thr, tile 128x128.
// ---------------------------------------------------------------------------
__global__ __launch_bounds__(256, 2)
void scores_tc(const float* __restrict__ q, const float* __restrict__ kk,
               const int* __restrict__ mask, float* __restrict__ s)
{
    extern __shared__ char smem[];
    const uint32_t sbase = smem_u32(smem);
    const int tid  = threadIdx.x;
    const int lane = tid & 31;
    const int wid  = tid >> 5;
    const int wm = wid & 1, wn = wid >> 1;
    const int g = lane >> 2, t = lane & 3;
    const int b  = blockIdx.z;
    const int m0 = blockIdx.y * 128;
    const int n0 = blockIdx.x * 128;

    const float* qb = q  + (size_t)b * SEQ * DIM + (size_t)m0 * DIM;
    const float* kb = kk + (size_t)b * SEQ * DIM + (size_t)n0 * DIM;

    const int mBase = wm * 64;
    const int nBase = wn * 32;
    const uint32_t aRowOff = (uint32_t)(mBase + (lane & 15)) * SA + ((lane >> 4) << 4);
    const uint32_t bRowOff = (uint32_t)(nBase + (lane & 7) + ((lane >> 4) << 3)) * SA
                           + (((lane >> 3) & 1) << 4);

    float acc[4][4][4];
#pragma unroll
    for (int i = 0; i < 4; i++)
#pragma unroll
        for (int j = 0; j < 4; j++)
#pragma unroll
            for (int c = 0; c < 4; c++) acc[i][j][c] = 0.0f;

    loadHi128(qb, DIM, 0, tid, smem + SC_AHI);
    loadSplit128(kb, DIM, 0, tid, smem + SC_BHI, smem + SC_BLO);
    __syncthreads();

    const int NC = DIM / BKC;   // 8
    for (int c = 0; c < NC; c++) {
        const uint32_t stg = sbase + (c & 1) * SC_STAGE;
        if (c + 1 < NC) {
            char* nx = smem + ((c + 1) & 1) * SC_STAGE;
            loadHi128(qb, DIM, (c + 1) * BKC, tid, nx + SC_AHI);
            loadSplit128(kb, DIM, (c + 1) * BKC, tid, nx + SC_BHI, nx + SC_BLO);
        }
#pragma unroll
        for (int ks = 0; ks < 2; ks++) {
            const uint32_t kByte = (uint32_t)(ks * 32);
            uint32_t bh[4][2], bl[4][2];
#pragma unroll
            for (int np = 0; np < 2; np++) {
                uint32_t addr = stg + SC_BHI + bRowOff + np * 16 * SA + kByte;
                uint32_t r0, r1, r2, r3;
                ldmx4(r0, r1, r2, r3, addr);
                bh[2*np][0] = r0; bh[2*np][1] = r1;
                bh[2*np+1][0] = r2; bh[2*np+1][1] = r3;
                ldmx4(r0, r1, r2, r3, addr + (SC_BLO - SC_BHI));
                bl[2*np][0] = r0; bl[2*np][1] = r1;
                bl[2*np+1][0] = r2; bl[2*np+1][1] = r3;
            }
#pragma unroll
            for (int mt = 0; mt < 4; mt++) {
                uint32_t addr = stg + SC_AHI + aRowOff + mt * 16 * SA + kByte;
                uint32_t ah[4];
                ldmx4(ah[0], ah[1], ah[2], ah[3], addr);
#pragma unroll
                for (int nt = 0; nt < 4; nt++) {
                    mma_f16(acc[mt][nt], ah, bh[nt][0], bh[nt][1]);
                    mma_f16(acc[mt][nt], ah, bl[nt][0], bl[nt][1]);
                }
            }
        }
        __syncthreads();
    }

    // Epilogue: E = mask ? exp(scale*s) : 0, plus partial row sums.
    float* sb = s + (size_t)b * SEQ * SEQ;
    const int ztile = blockIdx.x * 4 + wn;
#pragma unroll
    for (int mt = 0; mt < 4; mt++) {
        int r0 = m0 + mBase + mt * 16 + g;
        float sum0 = 0.0f, sum1 = 0.0f;
#pragma unroll
        for (int nt = 0; nt < 4; nt++) {
            int col = n0 + nBase + nt * 8 + 2 * t;
            int2 mv0 = *(const int2*)(mask + (size_t)r0 * SEQ + col);
            int2 mv1 = *(const int2*)(mask + (size_t)(r0 + 8) * SEQ + col);
            float2 o0, o1;
            o0.x = mv0.x ? __expf(acc[mt][nt][0] * ATTN_SCALE) : 0.0f;
            o0.y = mv0.y ? __expf(acc[mt][nt][1] * ATTN_SCALE) : 0.0f;
            o1.x = mv1.x ? __expf(acc[mt][nt][2] * ATTN_SCALE) : 0.0f;
            o1.y = mv1.y ? __expf(acc[mt][nt][3] * ATTN_SCALE) : 0.0f;
            sum0 += o0.x + o0.y;
            sum1 += o1.x + o1.y;
            *(float2*)(sb + (size_t)r0 * SEQ + col) = o0;
            *(float2*)(sb + (size_t)(r0 + 8) * SEQ + col) = o1;
        }
        sum0 += __shfl_xor_sync(0xFFFFFFFFu, sum0, 1);
        sum0 += __shfl_xor_sync(0xFFFFFFFFu, sum0, 2);
        sum1 += __shfl_xor_sync(0xFFFFFFFFu, sum1, 1);
        sum1 += __shfl_xor_sync(0xFFFFFFFFu, sum1, 2);
        if (t == 0) {
            g_zpart[((size_t)b * SEQ + r0) * 64 + ztile]     = sum0;
            g_zpart[((size_t)b * SEQ + r0 + 8) * 64 + ztile] = sum1;
        }
    }
}

// ---------------------------------------------------------------------------
// Kernel 2: invZ[row] = 1 / sum(zpart[row][0..63]).
// ---------------------------------------------------------------------------
__global__ __launch_bounds__(256)
void zreduce_kernel()
{
    int i = blockIdx.x * 256 + threadIdx.x;
    const float4* zp = (const float4*)(g_zpart + (size_t)i * 64);
    float s = 0.0f;
#pragma unroll
    for (int j = 0; j < 16; j++) {
        float4 v = zp[j];
        s += (v.x + v.y) + (v.z + v.w);
    }
    g_invz[i] = 1.0f / s;
}

// ---------------------------------------------------------------------------
// Kernel 3: O = (E @ V) * invZ, rewrite P = E * invZ in place.
// 2-term fp16: Ehi·Vhi + Ehi·Vlo. Grid (1,32,BATCH), tile 64x256, warps 1x8.
// ---------------------------------------------------------------------------
__global__ __launch_bounds__(256, 2)
void out_fused(float* __restrict__ attn, const float* __restrict__ v,
               float* __restrict__ o)
{
    extern __shared__ char smem[];
    const uint32_t sbase = smem_u32(smem);
    const int tid  = threadIdx.x;
    const int lane = tid & 31;
    const int wid  = tid >> 5;           // 0..7 = n-tile
    const int g = lane >> 2, t = lane & 3;
    const int b  = blockIdx.z;
    const int m0 = blockIdx.y * 64;

    float* pb = attn + (size_t)b * SEQ * SEQ + (size_t)m0 * SEQ;
    const float* vb = v + (size_t)b * SEQ * DIM;

    const int nBase = wid * 32;
    const uint32_t aRowOff = (uint32_t)(lane & 15) * SA + ((lane >> 4) << 4);
    const uint32_t vRow = (uint32_t)((lane & 7) + (((lane >> 3) & 1) << 3));
    const uint32_t vNOff = (uint32_t)(nBase + ((lane >> 4) << 3)) * 2;

    const int lrow0 = tid >> 3;
    const float iz0 = g_invz[(size_t)b * SEQ + m0 + lrow0];
    const float iz1 = g_invz[(size_t)b * SEQ + m0 + lrow0 + 32];

    float acc[4][4][4];
#pragma unroll
    for (int i = 0; i < 4; i++)
#pragma unroll
        for (int j = 0; j < 4; j++)
#pragma unroll
            for (int c = 0; c < 4; c++) acc[i][j][c] = 0.0f;

    loadE(pb, pb, 0, tid, iz0, iz1, smem + OU_AHI);
    loadV256(vb, 0, tid, smem + OU_VHI, smem + OU_VLO);
    __syncthreads();

    const int NC = SEQ / BKC;   // 64
    for (int c = 0; c < NC; c++) {
        const uint32_t stg = sbase + (c & 1) * OU_STAGE;
        if (c + 1 < NC) {
            char* nx = smem + ((c + 1) & 1) * OU_STAGE;
            loadE(pb, pb, (c + 1) * BKC, tid, iz0, iz1, nx + OU_AHI);
            loadV256(vb, (c + 1) * BKC, tid, nx + OU_VHI, nx + OU_VLO);
        }
#pragma unroll
        for (int ks = 0; ks < 2; ks++) {
            uint32_t bh[4][2], bl[4][2];
#pragma unroll
            for (int np = 0; np < 2; np++) {
                uint32_t addr = stg + OU_VHI + (ks * 16 + vRow) * SV2 + vNOff + np * 32;
                uint32_t r0, r1, r2, r3;
                ldmx4t(r0, r1, r2, r3, addr);
                bh[2*np][0] = r0; bh[2*np][1] = r1;
                bh[2*np+1][0] = r2; bh[2*np+1][1] = r3;
                ldmx4t(r0, r1, r2, r3, addr + (OU_VLO - OU_VHI));
                bl[2*np][0] = r0; bl[2*np][1] = r1;
                bl[2*np+1][0] = r2; bl[2*np+1][1] = r3;
            }
#pragma unroll
            for (int mt = 0; mt < 4; mt++) {
                uint32_t addr = stg + OU_AHI + aRowOff + mt * 16 * SA + ks * 32;
                uint32_t ah[4];
                ldmx4(ah[0], ah[1], ah[2], ah[3], addr);
#pragma unroll
                for (int nt = 0; nt < 4; nt++) {
                    mma_f16(acc[mt][nt], ah, bh[nt][0], bh[nt][1]);
                    mma_f16(acc[mt][nt], ah, bl[nt][0], bl[nt][1]);
                }
            }
        }
        __syncthreads();
    }

    // Epilogue: O = acc * invZ[row]
    float* ob = o + (size_t)b * SEQ * DIM;
#pragma unroll
    for (int mt = 0; mt < 4; mt++) {
        int r0 = m0 + mt * 16 + g;
        float z0 = g_invz[(size_t)b * SEQ + r0];
        float z1 = g_invz[(size_t)b * SEQ + r0 + 8];
#pragma unroll
        for (int nt = 0; nt < 4; nt++) {
            int col = nBase + nt * 8 + 2 * t;
            *(float2*)(ob + (size_t)r0 * DIM + col) =
                make_float2(acc[mt][nt][0] * z0, acc[mt][nt][1] * z0);
            *(float2*)(ob + (size_t)(r0 + 8) * DIM + col) =
                make_float2(acc[mt][nt][2] * z1, acc[mt][nt][3] * z1);
        }
    }
}

// ---------------------------------------------------------------------------
extern "C" void kernel_launch(void* const* d_in, const int* in_sizes, int n_in,
                              void* d_out, int out_size)
{
    const float* q    = (const float*)d_in[0];
    const float* k    = (const float*)d_in[1];
    const float* v    = (const float*)d_in[2];
    const int*   mask = (const int*)d_in[3];

    float* out  = (float*)d_out;                      // [B, S, D]
    float* attn = out + (size_t)BATCH * SEQ * DIM;    // [B, S, S]

    cudaFuncSetAttribute(scores_tc, cudaFuncAttributeMaxDynamicSharedMemorySize, SC_SMEM);
    cudaFuncSetAttribute(out_fused, cudaFuncAttributeMaxDynamicSharedMemorySize, OU_SMEM);

    dim3 blk(256);
    scores_tc<<<dim3(SEQ / 128, SEQ / 128, BATCH), blk, SC_SMEM>>>(q, k, mask, attn);
    zreduce_kernel<<<BATCH * SEQ / 256, blk>>>();
    out_fused<<<dim3(1, SEQ / 64, BATCH), blk, OU_SMEM>>>(attn, v, out);
}

// round 10
// speedup vs baseline: 3.5946x; 1.1264x over previous
#include <cuda_runtime.h>
#include <cuda_fp16.h>
#include <cstdint>

// Problem constants
#define BATCH 16
#define SEQ   2048
#define DIM   256
#define ATTN_SCALE 0.0625f   // 1/sqrt(256)

#define BKC 32      // K-chunk (elements)
#define SA  80      // A/B tile row stride bytes (64B data + 16B pad)
#define SV2 528     // 256-col V tile row stride (512B + 16B pad)

// Stage offsets, scores kernel (Qhi[128x32], Khi[128x32], Klo[128x32])
#define SC_A   0
#define SC_BHI 10240
#define SC_BLO 20480
#define SC_STAGE 30720
#define SC_SMEM (2 * SC_STAGE)     // 61440

// Stage offsets, fused out kernel (E[128x32], Vhi[32x256], Vlo[32x256])
#define OU_A   0
#define OU_VHI 10240
#define OU_VLO 27136
#define OU_STAGE 44032
#define OU_SMEM (2 * OU_STAGE)     // 88064

// Pre-converted fp16 operand buffers + softmax scratch (device globals)
__device__ __align__(256) __half g_qh[(size_t)BATCH * SEQ * DIM];   // 16MB
__device__ __align__(256) __half g_kh[(size_t)BATCH * SEQ * DIM];
__device__ __align__(256) __half g_kl[(size_t)BATCH * SEQ * DIM];
__device__ __align__(256) __half g_vh[(size_t)BATCH * SEQ * DIM];
__device__ __align__(256) __half g_vl[(size_t)BATCH * SEQ * DIM];
__device__ __align__(256) __half g_e [(size_t)BATCH * SEQ * SEQ];   // 134MB
__device__ float g_zpart[(size_t)BATCH * SEQ * 64];                 // 8MB
__device__ float g_invz[(size_t)BATCH * SEQ];

// ---------------------------------------------------------------------------
__device__ __forceinline__ uint32_t smem_u32(const void* p) {
    uint32_t a;
    asm("{ .reg .u64 t; cvta.to.shared.u64 t, %1; cvt.u32.u64 %0, t; }" : "=r"(a) : "l"(p));
    return a;
}

__device__ __forceinline__ void cpa16(uint32_t saddr, const void* gptr) {
    asm volatile("cp.async.cg.shared.global [%0], [%1], 16;"
                 :: "r"(saddr), "l"(__cvta_generic_to_global(gptr)) : "memory");
}
__device__ __forceinline__ void cpcommit() {
    asm volatile("cp.async.commit_group;" ::: "memory");
}
template<int N> __device__ __forceinline__ void cpwait() {
    asm volatile("cp.async.wait_group %0;" :: "n"(N) : "memory");
}

__device__ __forceinline__ void ldmx4(uint32_t& r0, uint32_t& r1, uint32_t& r2,
                                      uint32_t& r3, uint32_t addr) {
    asm volatile("ldmatrix.sync.aligned.m8n8.x4.shared.b16 {%0,%1,%2,%3}, [%4];"
                 : "=r"(r0), "=r"(r1), "=r"(r2), "=r"(r3) : "r"(addr));
}
__device__ __forceinline__ void ldmx4t(uint32_t& r0, uint32_t& r1, uint32_t& r2,
                                       uint32_t& r3, uint32_t addr) {
    asm volatile("ldmatrix.sync.aligned.m8n8.x4.trans.shared.b16 {%0,%1,%2,%3}, [%4];"
                 : "=r"(r0), "=r"(r1), "=r"(r2), "=r"(r3) : "r"(addr));
}

// m16n8k16 fp16 mma, fp32 accumulate
__device__ __forceinline__ void mma_f16(float c[4], const uint32_t a[4],
                                        uint32_t b0, uint32_t b1) {
    asm("mma.sync.aligned.m16n8k16.row.col.f32.f16.f16.f32 "
        "{%0,%1,%2,%3}, {%4,%5,%6,%7}, {%8,%9}, {%0,%1,%2,%3};"
        : "+f"(c[0]), "+f"(c[1]), "+f"(c[2]), "+f"(c[3])
        : "r"(a[0]), "r"(a[1]), "r"(a[2]), "r"(a[3]), "r"(b0), "r"(b1));
}

__device__ __forceinline__ void cvt4(float4 v, uint2& h) {
    __half2 a = __floats2half2_rn(v.x, v.y);
    __half2 b = __floats2half2_rn(v.z, v.w);
    h.x = *(uint32_t*)&a; h.y = *(uint32_t*)&b;
}
__device__ __forceinline__ void split4(float4 v, uint2& h, uint2& l) {
    __half h0 = __float2half_rn(v.x), h1 = __float2half_rn(v.y);
    __half h2 = __float2half_rn(v.z), h3 = __float2half_rn(v.w);
    __half l0 = __float2half_rn(v.x - __half2float(h0));
    __half l1 = __float2half_rn(v.y - __half2float(h1));
    __half l2 = __float2half_rn(v.z - __half2float(h2));
    __half l3 = __float2half_rn(v.w - __half2float(h3));
    __half2 ph0 = __halves2half2(h0, h1), ph1 = __halves2half2(h2, h3);
    __half2 pl0 = __halves2half2(l0, l1), pl1 = __halves2half2(l2, l3);
    h.x = *(uint32_t*)&ph0; h.y = *(uint32_t*)&ph1;
    l.x = *(uint32_t*)&pl0; l.y = *(uint32_t*)&pl1;
}

// ---------------------------------------------------------------------------
// Kernel 0: convert Q -> Qhi; K -> Khi+Klo; V -> Vhi+Vlo.
// ---------------------------------------------------------------------------
__global__ __launch_bounds__(256)
void prep_kernel(const float* __restrict__ q, const float* __restrict__ k,
                 const float* __restrict__ v)
{
    size_t i = (size_t)blockIdx.x * 256 + threadIdx.x;   // float4 index
    float4 qv = ((const float4*)q)[i];
    uint2 qh; cvt4(qv, qh);
    ((uint2*)g_qh)[i] = qh;

    float4 kv = ((const float4*)k)[i];
    uint2 kh, kl; split4(kv, kh, kl);
    ((uint2*)g_kh)[i] = kh;
    ((uint2*)g_kl)[i] = kl;

    float4 vv = ((const float4*)v)[i];
    uint2 vh, vl; split4(vv, vh, vl);
    ((uint2*)g_vh)[i] = vh;
    ((uint2*)g_vl)[i] = vl;
}

// ---------------------------------------------------------------------------
// Kernel 1: E = mask ? exp(scale * Q@K^T) : 0  -> g_e (fp16) + partial sums.
// cp.async pipeline. Grid (16,16,BATCH), 256 threads, tile 128x128.
// ---------------------------------------------------------------------------
__device__ __forceinline__ void k1_issue(uint32_t stg, const __half* qrow,
                                         const __half* khrow, const __half* klrow,
                                         int k0, int tid) {
#pragma unroll
    for (int j = 0; j < 2; j++) {
        int o = tid + j * 256;
        int row = o >> 2, c = o & 3;
        size_t goff = (size_t)row * DIM + k0 + c * 8;
        uint32_t soff = (uint32_t)(row * SA + c * 16);
        cpa16(stg + SC_A   + soff, qrow  + goff);
        cpa16(stg + SC_BHI + soff, khrow + goff);
        cpa16(stg + SC_BLO + soff, klrow + goff);
    }
}

__global__ __launch_bounds__(256, 2)
void scores_tc(const int* __restrict__ mask)
{
    extern __shared__ char smem[];
    const uint32_t sbase = smem_u32(smem);
    const int tid  = threadIdx.x;
    const int lane = tid & 31;
    const int wid  = tid >> 5;
    const int wm = wid & 1, wn = wid >> 1;
    const int g = lane >> 2, t = lane & 3;
    const int b  = blockIdx.z;
    const int m0 = blockIdx.y * 128;
    const int n0 = blockIdx.x * 128;

    const __half* qb  = g_qh + (size_t)b * SEQ * DIM + (size_t)m0 * DIM;
    const __half* kbh = g_kh + (size_t)b * SEQ * DIM + (size_t)n0 * DIM;
    const __half* kbl = g_kl + (size_t)b * SEQ * DIM + (size_t)n0 * DIM;

    const int mBase = wm * 64;
    const int nBase = wn * 32;
    const uint32_t aRowOff = (uint32_t)(mBase + (lane & 15)) * SA + ((lane >> 4) << 4);
    const uint32_t bRowOff = (uint32_t)(nBase + (lane & 7) + ((lane >> 4) << 3)) * SA
                           + (((lane >> 3) & 1) << 4);

    float acc[4][4][4];
#pragma unroll
    for (int i = 0; i < 4; i++)
#pragma unroll
        for (int j = 0; j < 4; j++)
#pragma unroll
            for (int c = 0; c < 4; c++) acc[i][j][c] = 0.0f;

    k1_issue(sbase, qb, kbh, kbl, 0, tid); cpcommit();
    k1_issue(sbase + SC_STAGE, qb, kbh, kbl, BKC, tid); cpcommit();

    const int NC = DIM / BKC;   // 8
    for (int c = 0; c < NC; c++) {
        if (c == NC - 1) cpwait<0>(); else cpwait<1>();
        __syncthreads();
        const uint32_t stg = sbase + (c & 1) * SC_STAGE;
#pragma unroll
        for (int ks = 0; ks < 2; ks++) {
            const uint32_t kByte = (uint32_t)(ks * 32);
            uint32_t bh[4][2], bl[4][2];
#pragma unroll
            for (int np = 0; np < 2; np++) {
                uint32_t addr = stg + SC_BHI + bRowOff + np * 16 * SA + kByte;
                uint32_t r0, r1, r2, r3;
                ldmx4(r0, r1, r2, r3, addr);
                bh[2*np][0] = r0; bh[2*np][1] = r1;
                bh[2*np+1][0] = r2; bh[2*np+1][1] = r3;
                ldmx4(r0, r1, r2, r3, addr + (SC_BLO - SC_BHI));
                bl[2*np][0] = r0; bl[2*np][1] = r1;
                bl[2*np+1][0] = r2; bl[2*np+1][1] = r3;
            }
#pragma unroll
            for (int mt = 0; mt < 4; mt++) {
                uint32_t addr = stg + SC_A + aRowOff + mt * 16 * SA + kByte;
                uint32_t ah[4];
                ldmx4(ah[0], ah[1], ah[2], ah[3], addr);
#pragma unroll
                for (int nt = 0; nt < 4; nt++) {
                    mma_f16(acc[mt][nt], ah, bh[nt][0], bh[nt][1]);
                    mma_f16(acc[mt][nt], ah, bl[nt][0], bl[nt][1]);
                }
            }
        }
        __syncthreads();
        if (c + 2 < NC) {
            k1_issue(sbase + (c & 1) * SC_STAGE, qb, kbh, kbl, (c + 2) * BKC, tid);
            cpcommit();
        }
    }

    // Epilogue: E = mask ? exp(scale*s) : 0 (fp16), plus partial row sums.
    __half* eb = g_e + (size_t)b * SEQ * SEQ;
    const int ztile = blockIdx.x * 4 + wn;
#pragma unroll
    for (int mt = 0; mt < 4; mt++) {
        int r0 = m0 + mBase + mt * 16 + g;
        float sum0 = 0.0f, sum1 = 0.0f;
#pragma unroll
        for (int nt = 0; nt < 4; nt++) {
            int col = n0 + nBase + nt * 8 + 2 * t;
            int2 mv0 = *(const int2*)(mask + (size_t)r0 * SEQ + col);
            int2 mv1 = *(const int2*)(mask + (size_t)(r0 + 8) * SEQ + col);
            float e00 = mv0.x ? __expf(acc[mt][nt][0] * ATTN_SCALE) : 0.0f;
            float e01 = mv0.y ? __expf(acc[mt][nt][1] * ATTN_SCALE) : 0.0f;
            float e10 = mv1.x ? __expf(acc[mt][nt][2] * ATTN_SCALE) : 0.0f;
            float e11 = mv1.y ? __expf(acc[mt][nt][3] * ATTN_SCALE) : 0.0f;
            sum0 += e00 + e01;
            sum1 += e10 + e11;
            __half2 p0 = __floats2half2_rn(e00, e01);
            __half2 p1 = __floats2half2_rn(e10, e11);
            *(__half2*)(eb + (size_t)r0 * SEQ + col) = p0;
            *(__half2*)(eb + (size_t)(r0 + 8) * SEQ + col) = p1;
        }
        sum0 += __shfl_xor_sync(0xFFFFFFFFu, sum0, 1);
        sum0 += __shfl_xor_sync(0xFFFFFFFFu, sum0, 2);
        sum1 += __shfl_xor_sync(0xFFFFFFFFu, sum1, 1);
        sum1 += __shfl_xor_sync(0xFFFFFFFFu, sum1, 2);
        if (t == 0) {
            g_zpart[((size_t)b * SEQ + r0) * 64 + ztile]     = sum0;
            g_zpart[((size_t)b * SEQ + r0 + 8) * 64 + ztile] = sum1;
        }
    }
}

// ---------------------------------------------------------------------------
// Kernel 2: invZ[row] = 1 / sum(zpart[row][0..63]).
// ---------------------------------------------------------------------------
__global__ __launch_bounds__(256)
void zreduce_kernel()
{
    int i = blockIdx.x * 256 + threadIdx.x;
    const float4* zp = (const float4*)(g_zpart + (size_t)i * 64);
    float s = 0.0f;
#pragma unroll
    for (int j = 0; j < 16; j++) {
        float4 v = zp[j];
        s += (v.x + v.y) + (v.z + v.w);
    }
    g_invz[i] = 1.0f / s;
}

// ---------------------------------------------------------------------------
// Kernel 3: O = (E @ V) * invZ, attn = E * invZ.
// Grid (1,16,BATCH), 512 threads. CTA tile 128 x 256, warps 2m x 8n.
// E/V arrive pre-converted fp16 via cp.async; P written from smem.
// ---------------------------------------------------------------------------
__device__ __forceinline__ void k3_issue(uint32_t stg, const __half* eb,
                                         const __half* vbh, const __half* vbl,
                                         int k0, int tid) {
    {
        int row = tid >> 2, c = tid & 3;
        cpa16(stg + OU_A + row * SA + c * 16, eb + (size_t)row * SEQ + k0 + c * 8);
    }
#pragma unroll
    for (int j = 0; j < 2; j++) {
        int o = tid + j * 512;
        int row = o >> 5, c = o & 31;
        size_t goff = (size_t)(k0 + row) * DIM + c * 8;
        uint32_t soff = (uint32_t)(row * SV2 + c * 16);
        cpa16(stg + OU_VHI + soff, vbh + goff);
        cpa16(stg + OU_VLO + soff, vbl + goff);
    }
}

__global__ __launch_bounds__(512, 1)
void out_fused(float* __restrict__ attn, float* __restrict__ o)
{
    extern __shared__ char smem[];
    const uint32_t sbase = smem_u32(smem);
    const int tid  = threadIdx.x;
    const int lane = tid & 31;
    const int wid  = tid >> 5;           // 0..15
    const int wm = wid & 1, wn = wid >> 1;
    const int g = lane >> 2, t = lane & 3;
    const int b  = blockIdx.z;
    const int m0 = blockIdx.y * 128;

    const __half* eb  = g_e  + (size_t)b * SEQ * SEQ + (size_t)m0 * SEQ;
    const __half* vbh = g_vh + (size_t)b * SEQ * DIM;
    const __half* vbl = g_vl + (size_t)b * SEQ * DIM;
    float* pw = attn + (size_t)b * SEQ * SEQ + (size_t)m0 * SEQ;

    const int nBase = wn * 32;
    const uint32_t aRowOff = (uint32_t)(wm * 64 + (lane & 15)) * SA + ((lane >> 4) << 4);
    const uint32_t vRow = (uint32_t)((lane & 7) + (((lane >> 3) & 1) << 3));
    const uint32_t vNOff = (uint32_t)(nBase + ((lane >> 4) << 3)) * 2;

    const int prow = tid >> 2;           // 0..127: P-write row
    const int pc   = tid & 3;
    const float izp = g_invz[(size_t)b * SEQ + m0 + prow];

    float acc[4][4][4];
#pragma unroll
    for (int i = 0; i < 4; i++)
#pragma unroll
        for (int j = 0; j < 4; j++)
#pragma unroll
            for (int c = 0; c < 4; c++) acc[i][j][c] = 0.0f;

    k3_issue(sbase, eb, vbh, vbl, 0, tid); cpcommit();
    k3_issue(sbase + OU_STAGE, eb, vbh, vbl, BKC, tid); cpcommit();

    const int NC = SEQ / BKC;   // 64
    for (int c = 0; c < NC; c++) {
        if (c == NC - 1) cpwait<0>(); else cpwait<1>();
        __syncthreads();
        const uint32_t stg = sbase + (c & 1) * OU_STAGE;

        // Write normalized P for this chunk from smem E
        {
            uint4 e4 = *(uint4*)(smem + (c & 1) * OU_STAGE + OU_A + prow * SA + pc * 16);
            __half2* hp = (__half2*)&e4;
            float2 f0 = __half22float2(hp[0]);
            float2 f1 = __half22float2(hp[1]);
            float2 f2 = __half22float2(hp[2]);
            float2 f3 = __half22float2(hp[3]);
            float4 o0 = make_float4(f0.x * izp, f0.y * izp, f1.x * izp, f1.y * izp);
            float4 o1 = make_float4(f2.x * izp, f2.y * izp, f3.x * izp, f3.y * izp);
            float* dst = pw + (size_t)prow * SEQ + c * BKC + pc * 8;
            *(float4*)dst = o0;
            *(float4*)(dst + 4) = o1;
        }

#pragma unroll
        for (int ks = 0; ks < 2; ks++) {
            uint32_t bh[4][2], bl[4][2];
#pragma unroll
            for (int np = 0; np < 2; np++) {
                uint32_t addr = stg + OU_VHI + (ks * 16 + vRow) * SV2 + vNOff + np * 32;
                uint32_t r0, r1, r2, r3;
                ldmx4t(r0, r1, r2, r3, addr);
                bh[2*np][0] = r0; bh[2*np][1] = r1;
                bh[2*np+1][0] = r2; bh[2*np+1][1] = r3;
                ldmx4t(r0, r1, r2, r3, addr + (OU_VLO - OU_VHI));
                bl[2*np][0] = r0; bl[2*np][1] = r1;
                bl[2*np+1][0] = r2; bl[2*np+1][1] = r3;
            }
#pragma unroll
            for (int mt = 0; mt < 4; mt++) {
                uint32_t addr = stg + OU_A + aRowOff + mt * 16 * SA + ks * 32;
                uint32_t ah[4];
                ldmx4(ah[0], ah[1], ah[2], ah[3], addr);
#pragma unroll
                for (int nt = 0; nt < 4; nt++) {
                    mma_f16(acc[mt][nt], ah, bh[nt][0], bh[nt][1]);
                    mma_f16(acc[mt][nt], ah, bl[nt][0], bl[nt][1]);
                }
            }
        }
        __syncthreads();
        if (c + 2 < NC) {
            k3_issue(sbase + (c & 1) * OU_STAGE, eb, vbh, vbl, (c + 2) * BKC, tid);
            cpcommit();
        }
    }

    // Epilogue: O = acc * invZ[row]
    float* ob = o + (size_t)b * SEQ * DIM;
#pragma unroll
    for (int mt = 0; mt < 4; mt++) {
        int r0 = m0 + wm * 64 + mt * 16 + g;
        float z0 = g_invz[(size_t)b * SEQ + r0];
        float z1 = g_invz[(size_t)b * SEQ + r0 + 8];
#pragma unroll
        for (int nt = 0; nt < 4; nt++) {
            int col = nBase + nt * 8 + 2 * t;
            *(float2*)(ob + (size_t)r0 * DIM + col) =
                make_float2(acc[mt][nt][0] * z0, acc[mt][nt][1] * z0);
            *(float2*)(ob + (size_t)(r0 + 8) * DIM + col) =
                make_float2(acc[mt][nt][2] * z1, acc[mt][nt][3] * z1);
        }
    }
}

// ---------------------------------------------------------------------------
extern "C" void kernel_launch(void* const* d_in, const int* in_sizes, int n_in,
                              void* d_out, int out_size)
{
    const float* q    = (const float*)d_in[0];
    const float* k    = (const float*)d_in[1];
    const float* v    = (const float*)d_in[2];
    const int*   mask = (const int*)d_in[3];

    float* out  = (float*)d_out;                      // [B, S, D]
    float* attn = out + (size_t)BATCH * SEQ * DIM;    // [B, S, S]

    cudaFuncSetAttribute(scores_tc, cudaFuncAttributeMaxDynamicSharedMemorySize, SC_SMEM);
    cudaFuncSetAttribute(out_fused, cudaFuncAttributeMaxDynamicSharedMemorySize, OU_SMEM);

    prep_kernel<<<(BATCH * SEQ * DIM / 4) / 256, 256>>>(q, k, v);
    scores_tc<<<dim3(SEQ / 128, SEQ / 128, BATCH), 256, SC_SMEM>>>(mask);
    zreduce_kernel<<<BATCH * SEQ / 256, 256>>>();
    out_fused<<<dim3(1, SEQ / 128, BATCH), 512, OU_SMEM>>>(attn, out);
}

// round 11
// speedup vs baseline: 3.6860x; 1.0254x over previous
#include <cuda_runtime.h>
#include <cuda_fp16.h>
#include <cstdint>

// Problem constants
#define BATCH 16
#define SEQ   2048
#define DIM   256
#define ATTN_SCALE 0.0625f   // 1/sqrt(256)

#define BKC 32      // K-chunk (elements)
#define SA  80      // A/B tile row stride bytes (64B data + 16B pad)
#define SV2 528     // 256-col V tile row stride (512B + 16B pad)

// Stage offsets, scores kernel (Qhi[128x32], Khi[128x32], Klo[128x32])
#define SC_A   0
#define SC_BHI 10240
#define SC_BLO 20480
#define SC_STAGE 30720
#define SC_SMEM (3 * SC_STAGE)     // 92160 (3-stage)

// Stage offsets, fused out kernel (E[128x32], Vhi[32x256], Vlo[32x256])
#define OU_A   0
#define OU_VHI 10240
#define OU_VLO 27136
#define OU_STAGE 44032
#define OU_SMEM (3 * OU_STAGE)     // 132096 (3-stage)

// Pre-converted fp16 operand buffers + softmax scratch (device globals)
__device__ __align__(256) __half g_qh[(size_t)BATCH * SEQ * DIM];   // 16MB
__device__ __align__(256) __half g_kh[(size_t)BATCH * SEQ * DIM];
__device__ __align__(256) __half g_kl[(size_t)BATCH * SEQ * DIM];
__device__ __align__(256) __half g_vh[(size_t)BATCH * SEQ * DIM];
__device__ __align__(256) __half g_vl[(size_t)BATCH * SEQ * DIM];
__device__ __align__(256) __half g_e [(size_t)BATCH * SEQ * SEQ];   // 134MB
__device__ float g_zpart[(size_t)BATCH * SEQ * 64];                 // 8MB
__device__ float g_invz[(size_t)BATCH * SEQ];

// ---------------------------------------------------------------------------
__device__ __forceinline__ uint32_t smem_u32(const void* p) {
    uint32_t a;
    asm("{ .reg .u64 t; cvta.to.shared.u64 t, %1; cvt.u32.u64 %0, t; }" : "=r"(a) : "l"(p));
    return a;
}

__device__ __forceinline__ void cpa16(uint32_t saddr, const void* gptr) {
    asm volatile("cp.async.cg.shared.global [%0], [%1], 16;"
                 :: "r"(saddr), "l"(__cvta_generic_to_global(gptr)) : "memory");
}
__device__ __forceinline__ void cpcommit() {
    asm volatile("cp.async.commit_group;" ::: "memory");
}
template<int N> __device__ __forceinline__ void cpwait() {
    asm volatile("cp.async.wait_group %0;" :: "n"(N) : "memory");
}

__device__ __forceinline__ void ldmx4(uint32_t& r0, uint32_t& r1, uint32_t& r2,
                                      uint32_t& r3, uint32_t addr) {
    asm volatile("ldmatrix.sync.aligned.m8n8.x4.shared.b16 {%0,%1,%2,%3}, [%4];"
                 : "=r"(r0), "=r"(r1), "=r"(r2), "=r"(r3) : "r"(addr));
}
__device__ __forceinline__ void ldmx4t(uint32_t& r0, uint32_t& r1, uint32_t& r2,
                                       uint32_t& r3, uint32_t addr) {
    asm volatile("ldmatrix.sync.aligned.m8n8.x4.trans.shared.b16 {%0,%1,%2,%3}, [%4];"
                 : "=r"(r0), "=r"(r1), "=r"(r2), "=r"(r3) : "r"(addr));
}

// m16n8k16 fp16 mma, fp32 accumulate
__device__ __forceinline__ void mma_f16(float c[4], const uint32_t a[4],
                                        uint32_t b0, uint32_t b1) {
    asm("mma.sync.aligned.m16n8k16.row.col.f32.f16.f16.f32 "
        "{%0,%1,%2,%3}, {%4,%5,%6,%7}, {%8,%9}, {%0,%1,%2,%3};"
        : "+f"(c[0]), "+f"(c[1]), "+f"(c[2]), "+f"(c[3])
        : "r"(a[0]), "r"(a[1]), "r"(a[2]), "r"(a[3]), "r"(b0), "r"(b1));
}

__device__ __forceinline__ void cvt4(float4 v, uint2& h) {
    __half2 a = __floats2half2_rn(v.x, v.y);
    __half2 b = __floats2half2_rn(v.z, v.w);
    h.x = *(uint32_t*)&a; h.y = *(uint32_t*)&b;
}
__device__ __forceinline__ void split4(float4 v, uint2& h, uint2& l) {
    __half h0 = __float2half_rn(v.x), h1 = __float2half_rn(v.y);
    __half h2 = __float2half_rn(v.z), h3 = __float2half_rn(v.w);
    __half l0 = __float2half_rn(v.x - __half2float(h0));
    __half l1 = __float2half_rn(v.y - __half2float(h1));
    __half l2 = __float2half_rn(v.z - __half2float(h2));
    __half l3 = __float2half_rn(v.w - __half2float(h3));
    __half2 ph0 = __halves2half2(h0, h1), ph1 = __halves2half2(h2, h3);
    __half2 pl0 = __halves2half2(l0, l1), pl1 = __halves2half2(l2, l3);
    h.x = *(uint32_t*)&ph0; h.y = *(uint32_t*)&ph1;
    l.x = *(uint32_t*)&pl0; l.y = *(uint32_t*)&pl1;
}

// ---------------------------------------------------------------------------
// Kernel 0: convert Q -> Qhi; K -> Khi+Klo; V -> Vhi+Vlo.
// ---------------------------------------------------------------------------
__global__ __launch_bounds__(256)
void prep_kernel(const float* __restrict__ q, const float* __restrict__ k,
                 const float* __restrict__ v)
{
    size_t i = (size_t)blockIdx.x * 256 + threadIdx.x;   // float4 index
    float4 qv = ((const float4*)q)[i];
    uint2 qh; cvt4(qv, qh);
    ((uint2*)g_qh)[i] = qh;

    float4 kv = ((const float4*)k)[i];
    uint2 kh, kl; split4(kv, kh, kl);
    ((uint2*)g_kh)[i] = kh;
    ((uint2*)g_kl)[i] = kl;

    float4 vv = ((const float4*)v)[i];
    uint2 vh, vl; split4(vv, vh, vl);
    ((uint2*)g_vh)[i] = vh;
    ((uint2*)g_vl)[i] = vl;
}

// ---------------------------------------------------------------------------
// Kernel 1: E = mask ? exp(scale * Q@K^T) : 0  -> g_e (fp16) + partial sums.
// 3-stage cp.async pipeline, one barrier per chunk.
// Grid (16,16,BATCH), 256 threads, tile 128x128.
// ---------------------------------------------------------------------------
__device__ __forceinline__ void k1_issue(uint32_t stg, const __half* qrow,
                                         const __half* khrow, const __half* klrow,
                                         int k0, int tid) {
#pragma unroll
    for (int j = 0; j < 2; j++) {
        int o = tid + j * 256;
        int row = o >> 2, c = o & 3;
        size_t goff = (size_t)row * DIM + k0 + c * 8;
        uint32_t soff = (uint32_t)(row * SA + c * 16);
        cpa16(stg + SC_A   + soff, qrow  + goff);
        cpa16(stg + SC_BHI + soff, khrow + goff);
        cpa16(stg + SC_BLO + soff, klrow + goff);
    }
}

__global__ __launch_bounds__(256, 2)
void scores_tc(const int* __restrict__ mask)
{
    extern __shared__ char smem[];
    const uint32_t sbase = smem_u32(smem);
    const int tid  = threadIdx.x;
    const int lane = tid & 31;
    const int wid  = tid >> 5;
    const int wm = wid & 1, wn = wid >> 1;
    const int g = lane >> 2, t = lane & 3;
    const int b  = blockIdx.z;
    const int m0 = blockIdx.y * 128;
    const int n0 = blockIdx.x * 128;

    const __half* qb  = g_qh + (size_t)b * SEQ * DIM + (size_t)m0 * DIM;
    const __half* kbh = g_kh + (size_t)b * SEQ * DIM + (size_t)n0 * DIM;
    const __half* kbl = g_kl + (size_t)b * SEQ * DIM + (size_t)n0 * DIM;

    const int mBase = wm * 64;
    const int nBase = wn * 32;
    const uint32_t aRowOff = (uint32_t)(mBase + (lane & 15)) * SA + ((lane >> 4) << 4);
    const uint32_t bRowOff = (uint32_t)(nBase + (lane & 7) + ((lane >> 4) << 3)) * SA
                           + (((lane >> 3) & 1) << 4);

    float acc[4][4][4];
#pragma unroll
    for (int i = 0; i < 4; i++)
#pragma unroll
        for (int j = 0; j < 4; j++)
#pragma unroll
            for (int c = 0; c < 4; c++) acc[i][j][c] = 0.0f;

    k1_issue(sbase, qb, kbh, kbl, 0, tid); cpcommit();
    k1_issue(sbase + SC_STAGE, qb, kbh, kbl, BKC, tid); cpcommit();

    const int NC = DIM / BKC;   // 8
    int sc = 0;                  // stage of current chunk
    for (int c = 0; c < NC; c++) {
        if (c == NC - 1) cpwait<0>(); else cpwait<1>();
        __syncthreads();
        // Issue chunk c+2 into stage (c+2)%3 — its readers finished at the barrier.
        if (c + 2 < NC) {
            int sn = sc + 2; if (sn >= 3) sn -= 3;
            k1_issue(sbase + sn * SC_STAGE, qb, kbh, kbl, (c + 2) * BKC, tid);
            cpcommit();
        }
        const uint32_t stg = sbase + sc * SC_STAGE;
#pragma unroll
        for (int ks = 0; ks < 2; ks++) {
            const uint32_t kByte = (uint32_t)(ks * 32);
            uint32_t bh[4][2], bl[4][2];
#pragma unroll
            for (int np = 0; np < 2; np++) {
                uint32_t addr = stg + SC_BHI + bRowOff + np * 16 * SA + kByte;
                uint32_t r0, r1, r2, r3;
                ldmx4(r0, r1, r2, r3, addr);
                bh[2*np][0] = r0; bh[2*np][1] = r1;
                bh[2*np+1][0] = r2; bh[2*np+1][1] = r3;
                ldmx4(r0, r1, r2, r3, addr + (SC_BLO - SC_BHI));
                bl[2*np][0] = r0; bl[2*np][1] = r1;
                bl[2*np+1][0] = r2; bl[2*np+1][1] = r3;
            }
#pragma unroll
            for (int mt = 0; mt < 4; mt++) {
                uint32_t addr = stg + SC_A + aRowOff + mt * 16 * SA + kByte;
                uint32_t ah[4];
                ldmx4(ah[0], ah[1], ah[2], ah[3], addr);
#pragma unroll
                for (int nt = 0; nt < 4; nt++) {
                    mma_f16(acc[mt][nt], ah, bh[nt][0], bh[nt][1]);
                    mma_f16(acc[mt][nt], ah, bl[nt][0], bl[nt][1]);
                }
            }
        }
        sc++; if (sc == 3) sc = 0;
    }

    // Epilogue: E = mask ? exp(scale*s) : 0 (fp16), plus partial row sums.
    __half* eb = g_e + (size_t)b * SEQ * SEQ;
    const int ztile = blockIdx.x * 4 + wn;
#pragma unroll
    for (int mt = 0; mt < 4; mt++) {
        int r0 = m0 + mBase + mt * 16 + g;
        float sum0 = 0.0f, sum1 = 0.0f;
#pragma unroll
        for (int nt = 0; nt < 4; nt++) {
            int col = n0 + nBase + nt * 8 + 2 * t;
            int2 mv0 = *(const int2*)(mask + (size_t)r0 * SEQ + col);
            int2 mv1 = *(const int2*)(mask + (size_t)(r0 + 8) * SEQ + col);
            float e00 = mv0.x ? __expf(acc[mt][nt][0] * ATTN_SCALE) : 0.0f;
            float e01 = mv0.y ? __expf(acc[mt][nt][1] * ATTN_SCALE) : 0.0f;
            float e10 = mv1.x ? __expf(acc[mt][nt][2] * ATTN_SCALE) : 0.0f;
            float e11 = mv1.y ? __expf(acc[mt][nt][3] * ATTN_SCALE) : 0.0f;
            sum0 += e00 + e01;
            sum1 += e10 + e11;
            __half2 p0 = __floats2half2_rn(e00, e01);
            __half2 p1 = __floats2half2_rn(e10, e11);
            *(__half2*)(eb + (size_t)r0 * SEQ + col) = p0;
            *(__half2*)(eb + (size_t)(r0 + 8) * SEQ + col) = p1;
        }
        sum0 += __shfl_xor_sync(0xFFFFFFFFu, sum0, 1);
        sum0 += __shfl_xor_sync(0xFFFFFFFFu, sum0, 2);
        sum1 += __shfl_xor_sync(0xFFFFFFFFu, sum1, 1);
        sum1 += __shfl_xor_sync(0xFFFFFFFFu, sum1, 2);
        if (t == 0) {
            g_zpart[((size_t)b * SEQ + r0) * 64 + ztile]     = sum0;
            g_zpart[((size_t)b * SEQ + r0 + 8) * 64 + ztile] = sum1;
        }
    }
}

// ---------------------------------------------------------------------------
// Kernel 2: invZ[row] = 1 / sum(zpart[row][0..63]).
// ---------------------------------------------------------------------------
__global__ __launch_bounds__(256)
void zreduce_kernel()
{
    int i = blockIdx.x * 256 + threadIdx.x;
    const float4* zp = (const float4*)(g_zpart + (size_t)i * 64);
    float s = 0.0f;
#pragma unroll
    for (int j = 0; j < 16; j++) {
        float4 v = zp[j];
        s += (v.x + v.y) + (v.z + v.w);
    }
    g_invz[i] = 1.0f / s;
}

// ---------------------------------------------------------------------------
// Kernel 3: O = (E @ V) * invZ, attn = E * invZ.
// 3-stage cp.async pipeline, one barrier per chunk.
// Grid (1,16,BATCH), 512 threads. CTA tile 128 x 256, warps 2m x 8n.
// ---------------------------------------------------------------------------
__device__ __forceinline__ void k3_issue(uint32_t stg, const __half* eb,
                                         const __half* vbh, const __half* vbl,
                                         int k0, int tid) {
    {
        int row = tid >> 2, c = tid & 3;
        cpa16(stg + OU_A + row * SA + c * 16, eb + (size_t)row * SEQ + k0 + c * 8);
    }
#pragma unroll
    for (int j = 0; j < 2; j++) {
        int o = tid + j * 512;
        int row = o >> 5, c = o & 31;
        size_t goff = (size_t)(k0 + row) * DIM + c * 8;
        uint32_t soff = (uint32_t)(row * SV2 + c * 16);
        cpa16(stg + OU_VHI + soff, vbh + goff);
        cpa16(stg + OU_VLO + soff, vbl + goff);
    }
}

__global__ __launch_bounds__(512, 1)
void out_fused(float* __restrict__ attn, float* __restrict__ o)
{
    extern __shared__ char smem[];
    const uint32_t sbase = smem_u32(smem);
    const int tid  = threadIdx.x;
    const int lane = tid & 31;
    const int wid  = tid >> 5;           // 0..15
    const int wm = wid & 1, wn = wid >> 1;
    const int g = lane >> 2, t = lane & 3;
    const int b  = blockIdx.z;
    const int m0 = blockIdx.y * 128;

    const __half* eb  = g_e  + (size_t)b * SEQ * SEQ + (size_t)m0 * SEQ;
    const __half* vbh = g_vh + (size_t)b * SEQ * DIM;
    const __half* vbl = g_vl + (size_t)b * SEQ * DIM;
    float* pw = attn + (size_t)b * SEQ * SEQ + (size_t)m0 * SEQ;

    const int nBase = wn * 32;
    const uint32_t aRowOff = (uint32_t)(wm * 64 + (lane & 15)) * SA + ((lane >> 4) << 4);
    const uint32_t vRow = (uint32_t)((lane & 7) + (((lane >> 3) & 1) << 3));
    const uint32_t vNOff = (uint32_t)(nBase + ((lane >> 4) << 3)) * 2;

    const int prow = tid >> 2;           // 0..127: P-write row
    const int pc   = tid & 3;
    const float izp = g_invz[(size_t)b * SEQ + m0 + prow];

    float acc[4][4][4];
#pragma unroll
    for (int i = 0; i < 4; i++)
#pragma unroll
        for (int j = 0; j < 4; j++)
#pragma unroll
            for (int c = 0; c < 4; c++) acc[i][j][c] = 0.0f;

    k3_issue(sbase, eb, vbh, vbl, 0, tid); cpcommit();
    k3_issue(sbase + OU_STAGE, eb, vbh, vbl, BKC, tid); cpcommit();

    const int NC = SEQ / BKC;   // 64
    int sc = 0;
    for (int c = 0; c < NC; c++) {
        if (c == NC - 1) cpwait<0>(); else cpwait<1>();
        __syncthreads();
        if (c + 2 < NC) {
            int sn = sc + 2; if (sn >= 3) sn -= 3;
            k3_issue(sbase + sn * OU_STAGE, eb, vbh, vbl, (c + 2) * BKC, tid);
            cpcommit();
        }
        const uint32_t stg = sbase + sc * OU_STAGE;

        // Write normalized P for this chunk from smem E
        {
            uint4 e4 = *(uint4*)(smem + sc * OU_STAGE + OU_A + prow * SA + pc * 16);
            __half2* hp = (__half2*)&e4;
            float2 f0 = __half22float2(hp[0]);
            float2 f1 = __half22float2(hp[1]);
            float2 f2 = __half22float2(hp[2]);
            float2 f3 = __half22float2(hp[3]);
            float4 o0 = make_float4(f0.x * izp, f0.y * izp, f1.x * izp, f1.y * izp);
            float4 o1 = make_float4(f2.x * izp, f2.y * izp, f3.x * izp, f3.y * izp);
            float* dst = pw + (size_t)prow * SEQ + c * BKC + pc * 8;
            *(float4*)dst = o0;
            *(float4*)(dst + 4) = o1;
        }

#pragma unroll
        for (int ks = 0; ks < 2; ks++) {
            uint32_t bh[4][2], bl[4][2];
#pragma unroll
            for (int np = 0; np < 2; np++) {
                uint32_t addr = stg + OU_VHI + (ks * 16 + vRow) * SV2 + vNOff + np * 32;
                uint32_t r0, r1, r2, r3;
                ldmx4t(r0, r1, r2, r3, addr);
                bh[2*np][0] = r0; bh[2*np][1] = r1;
                bh[2*np+1][0] = r2; bh[2*np+1][1] = r3;
                ldmx4t(r0, r1, r2, r3, addr + (OU_VLO - OU_VHI));
                bl[2*np][0] = r0; bl[2*np][1] = r1;
                bl[2*np+1][0] = r2; bl[2*np+1][1] = r3;
            }
#pragma unroll
            for (int mt = 0; mt < 4; mt++) {
                uint32_t addr = stg + OU_A + aRowOff + mt * 16 * SA + ks * 32;
                uint32_t ah[4];
                ldmx4(ah[0], ah[1], ah[2], ah[3], addr);
#pragma unroll
                for (int nt = 0; nt < 4; nt++) {
                    mma_f16(acc[mt][nt], ah, bh[nt][0], bh[nt][1]);
                    mma_f16(acc[mt][nt], ah, bl[nt][0], bl[nt][1]);
                }
            }
        }
        sc++; if (sc == 3) sc = 0;
    }

    // Epilogue: O = acc * invZ[row]
    float* ob = o + (size_t)b * SEQ * DIM;
#pragma unroll
    for (int mt = 0; mt < 4; mt++) {
        int r0 = m0 + wm * 64 + mt * 16 + g;
        float z0 = g_invz[(size_t)b * SEQ + r0];
        float z1 = g_invz[(size_t)b * SEQ + r0 + 8];
#pragma unroll
        for (int nt = 0; nt < 4; nt++) {
            int col = nBase + nt * 8 + 2 * t;
            *(float2*)(ob + (size_t)r0 * DIM + col) =
                make_float2(acc[mt][nt][0] * z0, acc[mt][nt][1] * z0);
            *(float2*)(ob + (size_t)(r0 + 8) * DIM + col) =
                make_float2(acc[mt][nt][2] * z1, acc[mt][nt][3] * z1);
        }
    }
}

// ---------------------------------------------------------------------------
extern "C" void kernel_launch(void* const* d_in, const int* in_sizes, int n_in,
                              void* d_out, int out_size)
{
    const float* q    = (const float*)d_in[0];
    const float* k    = (const float*)d_in[1];
    const float* v    = (const float*)d_in[2];
    const int*   mask = (const int*)d_in[3];

    float* out  = (float*)d_out;                      // [B, S, D]
    float* attn = out + (size_t)BATCH * SEQ * DIM;    // [B, S, S]

    cudaFuncSetAttribute(scores_tc, cudaFuncAttributeMaxDynamicSharedMemorySize, SC_SMEM);
    cudaFuncSetAttribute(out_fused, cudaFuncAttributeMaxDynamicSharedMemorySize, OU_SMEM);

    prep_kernel<<<(BATCH * SEQ * DIM / 4) / 256, 256>>>(q, k, v);
    scores_tc<<<dim3(SEQ / 128, SEQ / 128, BATCH), 256, SC_SMEM>>>(mask);
    zreduce_kernel<<<BATCH * SEQ / 256, 256>>>();
    out_fused<<<dim3(1, SEQ / 128, BATCH), 512, OU_SMEM>>>(attn, out);
}

// round 12
// speedup vs baseline: 4.1140x; 1.1161x over previous
#include <cuda_runtime.h>
#include <cuda_fp16.h>
#include <cstdint>

// Problem constants
#define BATCH 16
#define SEQ   2048
#define DIM   256
#define ATTN_SCALE 0.0625f   // 1/sqrt(256)

#define BKC 32      // K-chunk (elements)
#define SA  80      // A/B tile row stride bytes (64B data + 16B pad)
#define SV  272     // 128-col V tile row stride bytes (256B + 16B pad)

// Stage offsets, scores kernel (Qhi[128x32], Khi[128x32], Klo[128x32])
#define SC_A   0
#define SC_BHI 10240
#define SC_BLO 20480
#define SC_STAGE 30720
#define SC_SMEM (3 * SC_STAGE)     // 92160 (3-stage)

// Stage offsets, out kernel (E[128x32], Vhi[32x128])
#define OV_A   0
#define OV_VHI 10240
#define OV_STAGE 18944
#define OV_SMEM (3 * OV_STAGE)     // 56832 (3-stage, 2 CTAs/SM)

// Pre-converted fp16 operand buffers + softmax scratch (device globals)
__device__ __align__(256) __half g_qh[(size_t)BATCH * SEQ * DIM];   // 16MB
__device__ __align__(256) __half g_kh[(size_t)BATCH * SEQ * DIM];
__device__ __align__(256) __half g_kl[(size_t)BATCH * SEQ * DIM];
__device__ __align__(256) __half g_vh[(size_t)BATCH * SEQ * DIM];
__device__ __align__(256) __half g_e [(size_t)BATCH * SEQ * SEQ];   // 134MB
__device__ float g_zpart[(size_t)BATCH * SEQ * 64];                 // 8MB
__device__ float g_invz[(size_t)BATCH * SEQ];

// ---------------------------------------------------------------------------
__device__ __forceinline__ uint32_t smem_u32(const void* p) {
    uint32_t a;
    asm("{ .reg .u64 t; cvta.to.shared.u64 t, %1; cvt.u32.u64 %0, t; }" : "=r"(a) : "l"(p));
    return a;
}

__device__ __forceinline__ void cpa16(uint32_t saddr, const void* gptr) {
    asm volatile("cp.async.cg.shared.global [%0], [%1], 16;"
                 :: "r"(saddr), "l"(__cvta_generic_to_global(gptr)) : "memory");
}
__device__ __forceinline__ void cpcommit() {
    asm volatile("cp.async.commit_group;" ::: "memory");
}
template<int N> __device__ __forceinline__ void cpwait() {
    asm volatile("cp.async.wait_group %0;" :: "n"(N) : "memory");
}

__device__ __forceinline__ void ldmx4(uint32_t& r0, uint32_t& r1, uint32_t& r2,
                                      uint32_t& r3, uint32_t addr) {
    asm volatile("ldmatrix.sync.aligned.m8n8.x4.shared.b16 {%0,%1,%2,%3}, [%4];"
                 : "=r"(r0), "=r"(r1), "=r"(r2), "=r"(r3) : "r"(addr));
}
__device__ __forceinline__ void ldmx4t(uint32_t& r0, uint32_t& r1, uint32_t& r2,
                                       uint32_t& r3, uint32_t addr) {
    asm volatile("ldmatrix.sync.aligned.m8n8.x4.trans.shared.b16 {%0,%1,%2,%3}, [%4];"
                 : "=r"(r0), "=r"(r1), "=r"(r2), "=r"(r3) : "r"(addr));
}

// m16n8k16 fp16 mma, fp32 accumulate
__device__ __forceinline__ void mma_f16(float c[4], const uint32_t a[4],
                                        uint32_t b0, uint32_t b1) {
    asm("mma.sync.aligned.m16n8k16.row.col.f32.f16.f16.f32 "
        "{%0,%1,%2,%3}, {%4,%5,%6,%7}, {%8,%9}, {%0,%1,%2,%3};"
        : "+f"(c[0]), "+f"(c[1]), "+f"(c[2]), "+f"(c[3])
        : "r"(a[0]), "r"(a[1]), "r"(a[2]), "r"(a[3]), "r"(b0), "r"(b1));
}

__device__ __forceinline__ void cvt4(float4 v, uint2& h) {
    __half2 a = __floats2half2_rn(v.x, v.y);
    __half2 b = __floats2half2_rn(v.z, v.w);
    h.x = *(uint32_t*)&a; h.y = *(uint32_t*)&b;
}
__device__ __forceinline__ void split4(float4 v, uint2& h, uint2& l) {
    __half h0 = __float2half_rn(v.x), h1 = __float2half_rn(v.y);
    __half h2 = __float2half_rn(v.z), h3 = __float2half_rn(v.w);
    __half l0 = __float2half_rn(v.x - __half2float(h0));
    __half l1 = __float2half_rn(v.y - __half2float(h1));
    __half l2 = __float2half_rn(v.z - __half2float(h2));
    __half l3 = __float2half_rn(v.w - __half2float(h3));
    __half2 ph0 = __halves2half2(h0, h1), ph1 = __halves2half2(h2, h3);
    __half2 pl0 = __halves2half2(l0, l1), pl1 = __halves2half2(l2, l3);
    h.x = *(uint32_t*)&ph0; h.y = *(uint32_t*)&ph1;
    l.x = *(uint32_t*)&pl0; l.y = *(uint32_t*)&pl1;
}

// ---------------------------------------------------------------------------
// Kernel 0: convert Q -> Qhi; K -> Khi+Klo; V -> Vhi.
// ---------------------------------------------------------------------------
__global__ __launch_bounds__(256)
void prep_kernel(const float* __restrict__ q, const float* __restrict__ k,
                 const float* __restrict__ v)
{
    size_t i = (size_t)blockIdx.x * 256 + threadIdx.x;   // float4 index
    float4 qv = ((const float4*)q)[i];
    uint2 qh; cvt4(qv, qh);
    ((uint2*)g_qh)[i] = qh;

    float4 kv = ((const float4*)k)[i];
    uint2 kh, kl; split4(kv, kh, kl);
    ((uint2*)g_kh)[i] = kh;
    ((uint2*)g_kl)[i] = kl;

    float4 vv = ((const float4*)v)[i];
    uint2 vh; cvt4(vv, vh);
    ((uint2*)g_vh)[i] = vh;
}

// ---------------------------------------------------------------------------
// Kernel 1: E = mask ? exp(scale * Q@K^T) : 0  -> g_e (fp16) + partial sums.
// 3-stage cp.async pipeline. Grid (16,16,BATCH), 256 threads, tile 128x128.
// ---------------------------------------------------------------------------
__device__ __forceinline__ void k1_issue(uint32_t stg, const __half* qrow,
                                         const __half* khrow, const __half* klrow,
                                         int k0, int tid) {
#pragma unroll
    for (int j = 0; j < 2; j++) {
        int o = tid + j * 256;
        int row = o >> 2, c = o & 3;
        size_t goff = (size_t)row * DIM + k0 + c * 8;
        uint32_t soff = (uint32_t)(row * SA + c * 16);
        cpa16(stg + SC_A   + soff, qrow  + goff);
        cpa16(stg + SC_BHI + soff, khrow + goff);
        cpa16(stg + SC_BLO + soff, klrow + goff);
    }
}

__global__ __launch_bounds__(256, 2)
void scores_tc(const int* __restrict__ mask)
{
    extern __shared__ char smem[];
    const uint32_t sbase = smem_u32(smem);
    const int tid  = threadIdx.x;
    const int lane = tid & 31;
    const int wid  = tid >> 5;
    const int wm = wid & 1, wn = wid >> 1;
    const int g = lane >> 2, t = lane & 3;
    const int b  = blockIdx.z;
    const int m0 = blockIdx.y * 128;
    const int n0 = blockIdx.x * 128;

    const __half* qb  = g_qh + (size_t)b * SEQ * DIM + (size_t)m0 * DIM;
    const __half* kbh = g_kh + (size_t)b * SEQ * DIM + (size_t)n0 * DIM;
    const __half* kbl = g_kl + (size_t)b * SEQ * DIM + (size_t)n0 * DIM;

    const int mBase = wm * 64;
    const int nBase = wn * 32;
    const uint32_t aRowOff = (uint32_t)(mBase + (lane & 15)) * SA + ((lane >> 4) << 4);
    const uint32_t bRowOff = (uint32_t)(nBase + (lane & 7) + ((lane >> 4) << 3)) * SA
                           + (((lane >> 3) & 1) << 4);

    float acc[4][4][4];
#pragma unroll
    for (int i = 0; i < 4; i++)
#pragma unroll
        for (int j = 0; j < 4; j++)
#pragma unroll
            for (int c = 0; c < 4; c++) acc[i][j][c] = 0.0f;

    k1_issue(sbase, qb, kbh, kbl, 0, tid); cpcommit();
    k1_issue(sbase + SC_STAGE, qb, kbh, kbl, BKC, tid); cpcommit();

    const int NC = DIM / BKC;   // 8
    int sc = 0;
    for (int c = 0; c < NC; c++) {
        if (c == NC - 1) cpwait<0>(); else cpwait<1>();
        __syncthreads();
        if (c + 2 < NC) {
            int sn = sc + 2; if (sn >= 3) sn -= 3;
            k1_issue(sbase + sn * SC_STAGE, qb, kbh, kbl, (c + 2) * BKC, tid);
            cpcommit();
        }
        const uint32_t stg = sbase + sc * SC_STAGE;
#pragma unroll
        for (int ks = 0; ks < 2; ks++) {
            const uint32_t kByte = (uint32_t)(ks * 32);
            uint32_t bh[4][2], bl[4][2];
#pragma unroll
            for (int np = 0; np < 2; np++) {
                uint32_t addr = stg + SC_BHI + bRowOff + np * 16 * SA + kByte;
                uint32_t r0, r1, r2, r3;
                ldmx4(r0, r1, r2, r3, addr);
                bh[2*np][0] = r0; bh[2*np][1] = r1;
                bh[2*np+1][0] = r2; bh[2*np+1][1] = r3;
                ldmx4(r0, r1, r2, r3, addr + (SC_BLO - SC_BHI));
                bl[2*np][0] = r0; bl[2*np][1] = r1;
                bl[2*np+1][0] = r2; bl[2*np+1][1] = r3;
            }
#pragma unroll
            for (int mt = 0; mt < 4; mt++) {
                uint32_t addr = stg + SC_A + aRowOff + mt * 16 * SA + kByte;
                uint32_t ah[4];
                ldmx4(ah[0], ah[1], ah[2], ah[3], addr);
#pragma unroll
                for (int nt = 0; nt < 4; nt++) {
                    mma_f16(acc[mt][nt], ah, bh[nt][0], bh[nt][1]);
                    mma_f16(acc[mt][nt], ah, bl[nt][0], bl[nt][1]);
                }
            }
        }
        sc++; if (sc == 3) sc = 0;
    }

    // Epilogue: E = mask ? exp(scale*s) : 0 (fp16), plus partial row sums.
    __half* eb = g_e + (size_t)b * SEQ * SEQ;
    const int ztile = blockIdx.x * 4 + wn;
#pragma unroll
    for (int mt = 0; mt < 4; mt++) {
        int r0 = m0 + mBase + mt * 16 + g;
        float sum0 = 0.0f, sum1 = 0.0f;
#pragma unroll
        for (int nt = 0; nt < 4; nt++) {
            int col = n0 + nBase + nt * 8 + 2 * t;
            int2 mv0 = *(const int2*)(mask + (size_t)r0 * SEQ + col);
            int2 mv1 = *(const int2*)(mask + (size_t)(r0 + 8) * SEQ + col);
            float e00 = mv0.x ? __expf(acc[mt][nt][0] * ATTN_SCALE) : 0.0f;
            float e01 = mv0.y ? __expf(acc[mt][nt][1] * ATTN_SCALE) : 0.0f;
            float e10 = mv1.x ? __expf(acc[mt][nt][2] * ATTN_SCALE) : 0.0f;
            float e11 = mv1.y ? __expf(acc[mt][nt][3] * ATTN_SCALE) : 0.0f;
            sum0 += e00 + e01;
            sum1 += e10 + e11;
            __half2 p0 = __floats2half2_rn(e00, e01);
            __half2 p1 = __floats2half2_rn(e10, e11);
            *(__half2*)(eb + (size_t)r0 * SEQ + col) = p0;
            *(__half2*)(eb + (size_t)(r0 + 8) * SEQ + col) = p1;
        }
        sum0 += __shfl_xor_sync(0xFFFFFFFFu, sum0, 1);
        sum0 += __shfl_xor_sync(0xFFFFFFFFu, sum0, 2);
        sum1 += __shfl_xor_sync(0xFFFFFFFFu, sum1, 1);
        sum1 += __shfl_xor_sync(0xFFFFFFFFu, sum1, 2);
        if (t == 0) {
            g_zpart[((size_t)b * SEQ + r0) * 64 + ztile]     = sum0;
            g_zpart[((size_t)b * SEQ + r0 + 8) * 64 + ztile] = sum1;
        }
    }
}

// ---------------------------------------------------------------------------
// Kernel 2: invZ[row] = 1 / sum(zpart[row][0..63]).
// ---------------------------------------------------------------------------
__global__ __launch_bounds__(256)
void zreduce_kernel()
{
    int i = blockIdx.x * 256 + threadIdx.x;
    const float4* zp = (const float4*)(g_zpart + (size_t)i * 64);
    float s = 0.0f;
#pragma unroll
    for (int j = 0; j < 16; j++) {
        float4 v = zp[j];
        s += (v.x + v.y) + (v.z + v.w);
    }
    g_invz[i] = 1.0f / s;
}

// ---------------------------------------------------------------------------
// Kernel 3: O = (E @ Vhi) * invZ; CTAs with blockIdx.x==0 also write
// attn = E * invZ. Single-term fp16 (E exact in fp16; only V quantized).
// Grid (2,16,BATCH), 256 threads, tile 128x128, 2 CTAs/SM, 3-stage pipeline.
// ---------------------------------------------------------------------------
__device__ __forceinline__ void k3_issue(uint32_t stg, const __half* eb,
                                         const __half* vbh, int k0, int tid) {
#pragma unroll
    for (int j = 0; j < 2; j++) {
        int o = tid + j * 256;
        int erow = o >> 2, ec = o & 3;
        cpa16(stg + OV_A + erow * SA + ec * 16,
              eb + (size_t)erow * SEQ + k0 + ec * 8);
        int vrow = o >> 4, vc = o & 15;
        cpa16(stg + OV_VHI + vrow * SV + vc * 16,
              vbh + (size_t)(k0 + vrow) * DIM + vc * 8);
    }
}

__global__ __launch_bounds__(256, 2)
void out_fused(float* __restrict__ attn, float* __restrict__ o)
{
    extern __shared__ char smem[];
    const uint32_t sbase = smem_u32(smem);
    const int tid  = threadIdx.x;
    const int lane = tid & 31;
    const int wid  = tid >> 5;
    const int wm = wid & 1, wn = wid >> 1;
    const int g = lane >> 2, t = lane & 3;
    const int b  = blockIdx.z;
    const int m0 = blockIdx.y * 128;
    const int n0 = blockIdx.x * 128;
    const bool writeP = (blockIdx.x == 0);

    const __half* eb  = g_e  + (size_t)b * SEQ * SEQ + (size_t)m0 * SEQ;
    const __half* vbh = g_vh + (size_t)b * SEQ * DIM + n0;
    float* pw = attn + (size_t)b * SEQ * SEQ + (size_t)m0 * SEQ;

    const int mBase = wm * 64;
    const int nBase = wn * 32;
    const uint32_t aRowOff = (uint32_t)(mBase + (lane & 15)) * SA + ((lane >> 4) << 4);
    const uint32_t vRow = (uint32_t)((lane & 7) + (((lane >> 3) & 1) << 3));
    const uint32_t vNOff = (uint32_t)(nBase + ((lane >> 4) << 3)) * 2;

    const int prow = tid >> 1;           // 0..127: P-write row (2 thr/row)
    const int ph   = tid & 1;            // which 16-col half of the chunk
    const float izp = g_invz[(size_t)b * SEQ + m0 + prow];

    float acc[4][4][4];
#pragma unroll
    for (int i = 0; i < 4; i++)
#pragma unroll
        for (int j = 0; j < 4; j++)
#pragma unroll
            for (int c = 0; c < 4; c++) acc[i][j][c] = 0.0f;

    k3_issue(sbase, eb, vbh, 0, tid); cpcommit();
    k3_issue(sbase + OV_STAGE, eb, vbh, BKC, tid); cpcommit();

    const int NC = SEQ / BKC;   // 64
    int sc = 0;
    for (int c = 0; c < NC; c++) {
        if (c == NC - 1) cpwait<0>(); else cpwait<1>();
        __syncthreads();
        if (c + 2 < NC) {
            int sn = sc + 2; if (sn >= 3) sn -= 3;
            k3_issue(sbase + sn * OV_STAGE, eb, vbh, (c + 2) * BKC, tid);
            cpcommit();
        }
        const uint32_t stg = sbase + sc * OV_STAGE;

        // blockIdx.x==0: write normalized P for this chunk from smem E
        if (writeP) {
            const char* ep = smem + sc * OV_STAGE + OV_A + prow * SA + ph * 32;
            uint4 e4a = *(const uint4*)ep;
            uint4 e4b = *(const uint4*)(ep + 16);
            float* dst = pw + (size_t)prow * SEQ + c * BKC + ph * 16;
            __half2* ha = (__half2*)&e4a;
            __half2* hb = (__half2*)&e4b;
#pragma unroll
            for (int u = 0; u < 4; u += 2) {
                float2 f0 = __half22float2(ha[u]);
                float2 f1 = __half22float2(ha[u + 1]);
                *(float4*)(dst + u * 2) =
                    make_float4(f0.x * izp, f0.y * izp, f1.x * izp, f1.y * izp);
                float2 f2 = __half22float2(hb[u]);
                float2 f3 = __half22float2(hb[u + 1]);
                *(float4*)(dst + 8 + u * 2) =
                    make_float4(f2.x * izp, f2.y * izp, f3.x * izp, f3.y * izp);
            }
        }

#pragma unroll
        for (int ks = 0; ks < 2; ks++) {
            uint32_t bh[4][2];
#pragma unroll
            for (int np = 0; np < 2; np++) {
                uint32_t addr = stg + OV_VHI + (ks * 16 + vRow) * SV + vNOff + np * 32;
                uint32_t r0, r1, r2, r3;
                ldmx4t(r0, r1, r2, r3, addr);
                bh[2*np][0] = r0; bh[2*np][1] = r1;
                bh[2*np+1][0] = r2; bh[2*np+1][1] = r3;
            }
#pragma unroll
            for (int mt = 0; mt < 4; mt++) {
                uint32_t addr = stg + OV_A + aRowOff + mt * 16 * SA + ks * 32;
                uint32_t ah[4];
                ldmx4(ah[0], ah[1], ah[2], ah[3], addr);
#pragma unroll
                for (int nt = 0; nt < 4; nt++) {
                    mma_f16(acc[mt][nt], ah, bh[nt][0], bh[nt][1]);
                }
            }
        }
        sc++; if (sc == 3) sc = 0;
    }

    // Epilogue: O = acc * invZ[row]
    float* ob = o + (size_t)b * SEQ * DIM;
#pragma unroll
    for (int mt = 0; mt < 4; mt++) {
        int r0 = m0 + mBase + mt * 16 + g;
        float z0 = g_invz[(size_t)b * SEQ + r0];
        float z1 = g_invz[(size_t)b * SEQ + r0 + 8];
#pragma unroll
        for (int nt = 0; nt < 4; nt++) {
            int col = n0 + nBase + nt * 8 + 2 * t;
            *(float2*)(ob + (size_t)r0 * DIM + col) =
                make_float2(acc[mt][nt][0] * z0, acc[mt][nt][1] * z0);
            *(float2*)(ob + (size_t)(r0 + 8) * DIM + col) =
                make_float2(acc[mt][nt][2] * z1, acc[mt][nt][3] * z1);
        }
    }
}

// ---------------------------------------------------------------------------
extern "C" void kernel_launch(void* const* d_in, const int* in_sizes, int n_in,
                              void* d_out, int out_size)
{
    const float* q    = (const float*)d_in[0];
    const float* k    = (const float*)d_in[1];
    const float* v    = (const float*)d_in[2];
    const int*   mask = (const int*)d_in[3];

    float* out  = (float*)d_out;                      // [B, S, D]
    float* attn = out + (size_t)BATCH * SEQ * DIM;    // [B, S, S]

    cudaFuncSetAttribute(scores_tc, cudaFuncAttributeMaxDynamicSharedMemorySize, SC_SMEM);
    cudaFuncSetAttribute(out_fused, cudaFuncAttributeMaxDynamicSharedMemorySize, OV_SMEM);

    prep_kernel<<<(BATCH * SEQ * DIM / 4) / 256, 256>>>(q, k, v);
    scores_tc<<<dim3(SEQ / 128, SEQ / 128, BATCH), 256, SC_SMEM>>>(mask);
    zreduce_kernel<<<BATCH * SEQ / 256, 256>>>();
    out_fused<<<dim3(2, SEQ / 128, BATCH), 256, OV_SMEM>>>(attn, out);
}

// round 13
// speedup vs baseline: 4.6779x; 1.1371x over previous
#include <cuda_runtime.h>
#include <cuda_fp16.h>
#include <cstdint>

// Problem constants
#define BATCH 16
#define SEQ   2048
#define DIM   256
#define ATTN_SCALE 0.0625f   // 1/sqrt(256)

#define BKC 32      // K-chunk (elements)
#define SA  80      // A/B tile row stride bytes (64B data + 16B pad)
#define SV  272     // 128-col V tile row stride bytes (256B + 16B pad)

// Stage offsets, scores kernel (Qhi[128x32], Khi[128x32])
#define SC_A   0
#define SC_BHI 10240
#define SC_STAGE 20480
#define SC_SMEM (3 * SC_STAGE)     // 61440 (3-stage, 2 CTAs/SM)

// Stage offsets, out kernel (E[128x32], Vhi[32x128])
#define OV_A   0
#define OV_VHI 10240
#define OV_STAGE 18944
#define OV_SMEM (3 * OV_STAGE)     // 56832 (3-stage, 2 CTAs/SM)

// Pre-converted fp16 operand buffers + softmax scratch (device globals)
__device__ __align__(256) __half g_qh[(size_t)BATCH * SEQ * DIM];   // 16MB
__device__ __align__(256) __half g_kh[(size_t)BATCH * SEQ * DIM];
__device__ __align__(256) __half g_vh[(size_t)BATCH * SEQ * DIM];
__device__ __align__(256) __half g_e [(size_t)BATCH * SEQ * SEQ];   // 134MB
__device__ float g_zpart[(size_t)BATCH * SEQ * 64];                 // 8MB
__device__ float g_invz[(size_t)BATCH * SEQ];

// ---------------------------------------------------------------------------
__device__ __forceinline__ uint32_t smem_u32(const void* p) {
    uint32_t a;
    asm("{ .reg .u64 t; cvta.to.shared.u64 t, %1; cvt.u32.u64 %0, t; }" : "=r"(a) : "l"(p));
    return a;
}

__device__ __forceinline__ void cpa16(uint32_t saddr, const void* gptr) {
    asm volatile("cp.async.cg.shared.global [%0], [%1], 16;"
                 :: "r"(saddr), "l"(__cvta_generic_to_global(gptr)) : "memory");
}
__device__ __forceinline__ void cpcommit() {
    asm volatile("cp.async.commit_group;" ::: "memory");
}
template<int N> __device__ __forceinline__ void cpwait() {
    asm volatile("cp.async.wait_group %0;" :: "n"(N) : "memory");
}

__device__ __forceinline__ void ldmx4(uint32_t& r0, uint32_t& r1, uint32_t& r2,
                                      uint32_t& r3, uint32_t addr) {
    asm volatile("ldmatrix.sync.aligned.m8n8.x4.shared.b16 {%0,%1,%2,%3}, [%4];"
                 : "=r"(r0), "=r"(r1), "=r"(r2), "=r"(r3) : "r"(addr));
}
__device__ __forceinline__ void ldmx4t(uint32_t& r0, uint32_t& r1, uint32_t& r2,
                                       uint32_t& r3, uint32_t addr) {
    asm volatile("ldmatrix.sync.aligned.m8n8.x4.trans.shared.b16 {%0,%1,%2,%3}, [%4];"
                 : "=r"(r0), "=r"(r1), "=r"(r2), "=r"(r3) : "r"(addr));
}

// m16n8k16 fp16 mma, fp32 accumulate
__device__ __forceinline__ void mma_f16(float c[4], const uint32_t a[4],
                                        uint32_t b0, uint32_t b1) {
    asm("mma.sync.aligned.m16n8k16.row.col.f32.f16.f16.f32 "
        "{%0,%1,%2,%3}, {%4,%5,%6,%7}, {%8,%9}, {%0,%1,%2,%3};"
        : "+f"(c[0]), "+f"(c[1]), "+f"(c[2]), "+f"(c[3])
        : "r"(a[0]), "r"(a[1]), "r"(a[2]), "r"(a[3]), "r"(b0), "r"(b1));
}

__device__ __forceinline__ void cvt4(float4 v, uint2& h) {
    __half2 a = __floats2half2_rn(v.x, v.y);
    __half2 b = __floats2half2_rn(v.z, v.w);
    h.x = *(uint32_t*)&a; h.y = *(uint32_t*)&b;
}

// ---------------------------------------------------------------------------
// Kernel 0: convert Q -> Qhi; K -> Khi; V -> Vhi (single fp16 each).
// ---------------------------------------------------------------------------
__global__ __launch_bounds__(256)
void prep_kernel(const float* __restrict__ q, const float* __restrict__ k,
                 const float* __restrict__ v)
{
    size_t i = (size_t)blockIdx.x * 256 + threadIdx.x;   // float4 index
    float4 qv = ((const float4*)q)[i];
    uint2 qh; cvt4(qv, qh);
    ((uint2*)g_qh)[i] = qh;

    float4 kv = ((const float4*)k)[i];
    uint2 kh; cvt4(kv, kh);
    ((uint2*)g_kh)[i] = kh;

    float4 vv = ((const float4*)v)[i];
    uint2 vh; cvt4(vv, vh);
    ((uint2*)g_vh)[i] = vh;
}

// ---------------------------------------------------------------------------
// Kernel 1: E = mask ? exp(scale * Q@K^T) : 0  -> g_e (fp16) + partial sums.
// Single-pass fp16. 3-stage cp.async pipeline.
// Grid (16,16,BATCH), 256 threads, tile 128x128, 2 CTAs/SM.
// ---------------------------------------------------------------------------
__device__ __forceinline__ void k1_issue(uint32_t stg, const __half* qrow,
                                         const __half* khrow, int k0, int tid) {
#pragma unroll
    for (int j = 0; j < 2; j++) {
        int o = tid + j * 256;
        int row = o >> 2, c = o & 3;
        size_t goff = (size_t)row * DIM + k0 + c * 8;
        uint32_t soff = (uint32_t)(row * SA + c * 16);
        cpa16(stg + SC_A   + soff, qrow  + goff);
        cpa16(stg + SC_BHI + soff, khrow + goff);
    }
}

__global__ __launch_bounds__(256, 2)
void scores_tc(const int* __restrict__ mask)
{
    extern __shared__ char smem[];
    const uint32_t sbase = smem_u32(smem);
    const int tid  = threadIdx.x;
    const int lane = tid & 31;
    const int wid  = tid >> 5;
    const int wm = wid & 1, wn = wid >> 1;
    const int g = lane >> 2, t = lane & 3;
    const int b  = blockIdx.z;
    const int m0 = blockIdx.y * 128;
    const int n0 = blockIdx.x * 128;

    const __half* qb  = g_qh + (size_t)b * SEQ * DIM + (size_t)m0 * DIM;
    const __half* kbh = g_kh + (size_t)b * SEQ * DIM + (size_t)n0 * DIM;

    const int mBase = wm * 64;
    const int nBase = wn * 32;
    const uint32_t aRowOff = (uint32_t)(mBase + (lane & 15)) * SA + ((lane >> 4) << 4);
    const uint32_t bRowOff = (uint32_t)(nBase + (lane & 7) + ((lane >> 4) << 3)) * SA
                           + (((lane >> 3) & 1) << 4);

    float acc[4][4][4];
#pragma unroll
    for (int i = 0; i < 4; i++)
#pragma unroll
        for (int j = 0; j < 4; j++)
#pragma unroll
            for (int c = 0; c < 4; c++) acc[i][j][c] = 0.0f;

    k1_issue(sbase, qb, kbh, 0, tid); cpcommit();
    k1_issue(sbase + SC_STAGE, qb, kbh, BKC, tid); cpcommit();

    const int NC = DIM / BKC;   // 8
    int sc = 0;
    for (int c = 0; c < NC; c++) {
        if (c == NC - 1) cpwait<0>(); else cpwait<1>();
        __syncthreads();
        if (c + 2 < NC) {
            int sn = sc + 2; if (sn >= 3) sn -= 3;
            k1_issue(sbase + sn * SC_STAGE, qb, kbh, (c + 2) * BKC, tid);
            cpcommit();
        }
        const uint32_t stg = sbase + sc * SC_STAGE;
#pragma unroll
        for (int ks = 0; ks < 2; ks++) {
            const uint32_t kByte = (uint32_t)(ks * 32);
            uint32_t bh[4][2];
#pragma unroll
            for (int np = 0; np < 2; np++) {
                uint32_t addr = stg + SC_BHI + bRowOff + np * 16 * SA + kByte;
                uint32_t r0, r1, r2, r3;
                ldmx4(r0, r1, r2, r3, addr);
                bh[2*np][0] = r0; bh[2*np][1] = r1;
                bh[2*np+1][0] = r2; bh[2*np+1][1] = r3;
            }
#pragma unroll
            for (int mt = 0; mt < 4; mt++) {
                uint32_t addr = stg + SC_A + aRowOff + mt * 16 * SA + kByte;
                uint32_t ah[4];
                ldmx4(ah[0], ah[1], ah[2], ah[3], addr);
#pragma unroll
                for (int nt = 0; nt < 4; nt++) {
                    mma_f16(acc[mt][nt], ah, bh[nt][0], bh[nt][1]);
                }
            }
        }
        sc++; if (sc == 3) sc = 0;
    }

    // Epilogue: E = mask ? exp(scale*s) : 0 (fp16), plus partial row sums.
    __half* eb = g_e + (size_t)b * SEQ * SEQ;
    const int ztile = blockIdx.x * 4 + wn;
#pragma unroll
    for (int mt = 0; mt < 4; mt++) {
        int r0 = m0 + mBase + mt * 16 + g;
        float sum0 = 0.0f, sum1 = 0.0f;
#pragma unroll
        for (int nt = 0; nt < 4; nt++) {
            int col = n0 + nBase + nt * 8 + 2 * t;
            int2 mv0 = *(const int2*)(mask + (size_t)r0 * SEQ + col);
            int2 mv1 = *(const int2*)(mask + (size_t)(r0 + 8) * SEQ + col);
            float e00 = mv0.x ? __expf(acc[mt][nt][0] * ATTN_SCALE) : 0.0f;
            float e01 = mv0.y ? __expf(acc[mt][nt][1] * ATTN_SCALE) : 0.0f;
            float e10 = mv1.x ? __expf(acc[mt][nt][2] * ATTN_SCALE) : 0.0f;
            float e11 = mv1.y ? __expf(acc[mt][nt][3] * ATTN_SCALE) : 0.0f;
            sum0 += e00 + e01;
            sum1 += e10 + e11;
            __half2 p0 = __floats2half2_rn(e00, e01);
            __half2 p1 = __floats2half2_rn(e10, e11);
            *(__half2*)(eb + (size_t)r0 * SEQ + col) = p0;
            *(__half2*)(eb + (size_t)(r0 + 8) * SEQ + col) = p1;
        }
        sum0 += __shfl_xor_sync(0xFFFFFFFFu, sum0, 1);
        sum0 += __shfl_xor_sync(0xFFFFFFFFu, sum0, 2);
        sum1 += __shfl_xor_sync(0xFFFFFFFFu, sum1, 1);
        sum1 += __shfl_xor_sync(0xFFFFFFFFu, sum1, 2);
        if (t == 0) {
            g_zpart[((size_t)b * SEQ + r0) * 64 + ztile]     = sum0;
            g_zpart[((size_t)b * SEQ + r0 + 8) * 64 + ztile] = sum1;
        }
    }
}

// ---------------------------------------------------------------------------
// Kernel 2: invZ[row] = 1 / sum(zpart[row][0..63]).
// ---------------------------------------------------------------------------
__global__ __launch_bounds__(256)
void zreduce_kernel()
{
    int i = blockIdx.x * 256 + threadIdx.x;
    const float4* zp = (const float4*)(g_zpart + (size_t)i * 64);
    float s = 0.0f;
#pragma unroll
    for (int j = 0; j < 16; j++) {
        float4 v = zp[j];
        s += (v.x + v.y) + (v.z + v.w);
    }
    g_invz[i] = 1.0f / s;
}

// ---------------------------------------------------------------------------
// Kernel 3: O = (E @ Vhi) * invZ; CTAs with blockIdx.x==0 also write
// attn = E * invZ. Grid (2,16,BATCH), 256 threads, tile 128x128,
// 2 CTAs/SM, 3-stage pipeline.
// ---------------------------------------------------------------------------
__device__ __forceinline__ void k3_issue(uint32_t stg, const __half* eb,
                                         const __half* vbh, int k0, int tid) {
#pragma unroll
    for (int j = 0; j < 2; j++) {
        int o = tid + j * 256;
        int erow = o >> 2, ec = o & 3;
        cpa16(stg + OV_A + erow * SA + ec * 16,
              eb + (size_t)erow * SEQ + k0 + ec * 8);
        int vrow = o >> 4, vc = o & 15;
        cpa16(stg + OV_VHI + vrow * SV + vc * 16,
              vbh + (size_t)(k0 + vrow) * DIM + vc * 8);
    }
}

__global__ __launch_bounds__(256, 2)
void out_fused(float* __restrict__ attn, float* __restrict__ o)
{
    extern __shared__ char smem[];
    const uint32_t sbase = smem_u32(smem);
    const int tid  = threadIdx.x;
    const int lane = tid & 31;
    const int wid  = tid >> 5;
    const int wm = wid & 1, wn = wid >> 1;
    const int g = lane >> 2, t = lane & 3;
    const int b  = blockIdx.z;
    const int m0 = blockIdx.y * 128;
    const int n0 = blockIdx.x * 128;
    const bool writeP = (blockIdx.x == 0);

    const __half* eb  = g_e  + (size_t)b * SEQ * SEQ + (size_t)m0 * SEQ;
    const __half* vbh = g_vh + (size_t)b * SEQ * DIM + n0;
    float* pw = attn + (size_t)b * SEQ * SEQ + (size_t)m0 * SEQ;

    const int mBase = wm * 64;
    const int nBase = wn * 32;
    const uint32_t aRowOff = (uint32_t)(mBase + (lane & 15)) * SA + ((lane >> 4) << 4);
    const uint32_t vRow = (uint32_t)((lane & 7) + (((lane >> 3) & 1) << 3));
    const uint32_t vNOff = (uint32_t)(nBase + ((lane >> 4) << 3)) * 2;

    const int prow = tid >> 1;           // 0..127: P-write row (2 thr/row)
    const int ph   = tid & 1;            // which 16-col half of the chunk
    const float izp = g_invz[(size_t)b * SEQ + m0 + prow];

    float acc[4][4][4];
#pragma unroll
    for (int i = 0; i < 4; i++)
#pragma unroll
        for (int j = 0; j < 4; j++)
#pragma unroll
            for (int c = 0; c < 4; c++) acc[i][j][c] = 0.0f;

    k3_issue(sbase, eb, vbh, 0, tid); cpcommit();
    k3_issue(sbase + OV_STAGE, eb, vbh, BKC, tid); cpcommit();

    const int NC = SEQ / BKC;   // 64
    int sc = 0;
    for (int c = 0; c < NC; c++) {
        if (c == NC - 1) cpwait<0>(); else cpwait<1>();
        __syncthreads();
        if (c + 2 < NC) {
            int sn = sc + 2; if (sn >= 3) sn -= 3;
            k3_issue(sbase + sn * OV_STAGE, eb, vbh, (c + 2) * BKC, tid);
            cpcommit();
        }
        const uint32_t stg = sbase + sc * OV_STAGE;

        // blockIdx.x==0: write normalized P for this chunk from smem E
        if (writeP) {
            const char* ep = smem + sc * OV_STAGE + OV_A + prow * SA + ph * 32;
            uint4 e4a = *(const uint4*)ep;
            uint4 e4b = *(const uint4*)(ep + 16);
            float* dst = pw + (size_t)prow * SEQ + c * BKC + ph * 16;
            __half2* ha = (__half2*)&e4a;
            __half2* hb = (__half2*)&e4b;
#pragma unroll
            for (int u = 0; u < 4; u += 2) {
                float2 f0 = __half22float2(ha[u]);
                float2 f1 = __half22float2(ha[u + 1]);
                *(float4*)(dst + u * 2) =
                    make_float4(f0.x * izp, f0.y * izp, f1.x * izp, f1.y * izp);
                float2 f2 = __half22float2(hb[u]);
                float2 f3 = __half22float2(hb[u + 1]);
                *(float4*)(dst + 8 + u * 2) =
                    make_float4(f2.x * izp, f2.y * izp, f3.x * izp, f3.y * izp);
            }
        }

#pragma unroll
        for (int ks = 0; ks < 2; ks++) {
            uint32_t bh[4][2];
#pragma unroll
            for (int np = 0; np < 2; np++) {
                uint32_t addr = stg + OV_VHI + (ks * 16 + vRow) * SV + vNOff + np * 32;
                uint32_t r0, r1, r2, r3;
                ldmx4t(r0, r1, r2, r3, addr);
                bh[2*np][0] = r0; bh[2*np][1] = r1;
                bh[2*np+1][0] = r2; bh[2*np+1][1] = r3;
            }
#pragma unroll
            for (int mt = 0; mt < 4; mt++) {
                uint32_t addr = stg + OV_A + aRowOff + mt * 16 * SA + ks * 32;
                uint32_t ah[4];
                ldmx4(ah[0], ah[1], ah[2], ah[3], addr);
#pragma unroll
                for (int nt = 0; nt < 4; nt++) {
                    mma_f16(acc[mt][nt], ah, bh[nt][0], bh[nt][1]);
                }
            }
        }
        sc++; if (sc == 3) sc = 0;
    }

    // Epilogue: O = acc * invZ[row]
    float* ob = o + (size_t)b * SEQ * DIM;
#pragma unroll
    for (int mt = 0; mt < 4; mt++) {
        int r0 = m0 + mBase + mt * 16 + g;
        float z0 = g_invz[(size_t)b * SEQ + r0];
        float z1 = g_invz[(size_t)b * SEQ + r0 + 8];
#pragma unroll
        for (int nt = 0; nt < 4; nt++) {
            int col = n0 + nBase + nt * 8 + 2 * t;
            *(float2*)(ob + (size_t)r0 * DIM + col) =
                make_float2(acc[mt][nt][0] * z0, acc[mt][nt][1] * z0);
            *(float2*)(ob + (size_t)(r0 + 8) * DIM + col) =
                make_float2(acc[mt][nt][2] * z1, acc[mt][nt][3] * z1);
        }
    }
}

// ---------------------------------------------------------------------------
extern "C" void kernel_launch(void* const* d_in, const int* in_sizes, int n_in,
                              void* d_out, int out_size)
{
    const float* q    = (const float*)d_in[0];
    const float* k    = (const float*)d_in[1];
    const float* v    = (const float*)d_in[2];
    const int*   mask = (const int*)d_in[3];

    float* out  = (float*)d_out;                      // [B, S, D]
    float* attn = out + (size_t)BATCH * SEQ * DIM;    // [B, S, S]

    cudaFuncSetAttribute(scores_tc, cudaFuncAttributeMaxDynamicSharedMemorySize, SC_SMEM);
    cudaFuncSetAttribute(out_fused, cudaFuncAttributeMaxDynamicSharedMemorySize, OV_SMEM);

    prep_kernel<<<(BATCH * SEQ * DIM / 4) / 256, 256>>>(q, k, v);
    scores_tc<<<dim3(SEQ / 128, SEQ / 128, BATCH), 256, SC_SMEM>>>(mask);
    zreduce_kernel<<<BATCH * SEQ / 256, 256>>>();
    out_fused<<<dim3(2, SEQ / 128, BATCH), 256, OV_SMEM>>>(attn, out);
}

// round 14
// speedup vs baseline: 5.1818x; 1.1077x over previous
#include <cuda_runtime.h>
#include <cuda_fp16.h>
#include <cstdint>

// Problem constants
#define BATCH 16
#define SEQ   2048
#define DIM   256
#define ATTN_SCALE 0.0625f   // 1/sqrt(256)

#define BKC 32      // K-chunk (elements)
#define SA  80      // A/B tile row stride bytes (64B data + 16B pad)
#define SV  272     // 128-col V tile row stride bytes (256B + 16B pad)

// Stage offsets, scores kernel (Qhi[128x32], Khi[128x32])
#define SC_A   0
#define SC_BHI 10240
#define SC_STAGE 20480
#define SC_SMEM (3 * SC_STAGE)     // 61440 (3-stage, 2 CTAs/SM)

// Stage offsets, out kernel (E[128x32], Vhi[32x128])
#define OV_A   0
#define OV_VHI 10240
#define OV_STAGE 18944
#define OV_SMEM (3 * OV_STAGE)     // 56832 (3-stage, 2 CTAs/SM)

// Pre-converted fp16 operand buffers + softmax scratch (device globals)
__device__ __align__(256) __half g_qh[(size_t)BATCH * SEQ * DIM];   // 16MB
__device__ __align__(256) __half g_kh[(size_t)BATCH * SEQ * DIM];
__device__ __align__(256) __half g_vh[(size_t)BATCH * SEQ * DIM];
__device__ __align__(256) __half g_e [(size_t)BATCH * SEQ * SEQ];   // 134MB
__device__ float g_zpart[(size_t)BATCH * SEQ * 64];                 // 8MB
__device__ float g_invz[(size_t)BATCH * SEQ];
__device__ uint32_t g_mbits[(size_t)SEQ * 64];                      // 512KB bit mask

// ---------------------------------------------------------------------------
__device__ __forceinline__ uint32_t smem_u32(const void* p) {
    uint32_t a;
    asm("{ .reg .u64 t; cvta.to.shared.u64 t, %1; cvt.u32.u64 %0, t; }" : "=r"(a) : "l"(p));
    return a;
}

__device__ __forceinline__ void cpa16(uint32_t saddr, const void* gptr) {
    asm volatile("cp.async.cg.shared.global [%0], [%1], 16;"
                 :: "r"(saddr), "l"(__cvta_generic_to_global(gptr)) : "memory");
}
__device__ __forceinline__ void cpcommit() {
    asm volatile("cp.async.commit_group;" ::: "memory");
}
template<int N> __device__ __forceinline__ void cpwait() {
    asm volatile("cp.async.wait_group %0;" :: "n"(N) : "memory");
}

__device__ __forceinline__ void ldmx4(uint32_t& r0, uint32_t& r1, uint32_t& r2,
                                      uint32_t& r3, uint32_t addr) {
    asm volatile("ldmatrix.sync.aligned.m8n8.x4.shared.b16 {%0,%1,%2,%3}, [%4];"
                 : "=r"(r0), "=r"(r1), "=r"(r2), "=r"(r3) : "r"(addr));
}
__device__ __forceinline__ void ldmx4t(uint32_t& r0, uint32_t& r1, uint32_t& r2,
                                       uint32_t& r3, uint32_t addr) {
    asm volatile("ldmatrix.sync.aligned.m8n8.x4.trans.shared.b16 {%0,%1,%2,%3}, [%4];"
                 : "=r"(r0), "=r"(r1), "=r"(r2), "=r"(r3) : "r"(addr));
}

// m16n8k16 fp16 mma, fp32 accumulate
__device__ __forceinline__ void mma_f16(float c[4], const uint32_t a[4],
                                        uint32_t b0, uint32_t b1) {
    asm("mma.sync.aligned.m16n8k16.row.col.f32.f16.f16.f32 "
        "{%0,%1,%2,%3}, {%4,%5,%6,%7}, {%8,%9}, {%0,%1,%2,%3};"
        : "+f"(c[0]), "+f"(c[1]), "+f"(c[2]), "+f"(c[3])
        : "r"(a[0]), "r"(a[1]), "r"(a[2]), "r"(a[3]), "r"(b0), "r"(b1));
}

__device__ __forceinline__ void cvt4(float4 v, uint2& h) {
    __half2 a = __floats2half2_rn(v.x, v.y);
    __half2 b = __floats2half2_rn(v.z, v.w);
    h.x = *(uint32_t*)&a; h.y = *(uint32_t*)&b;
}

// ---------------------------------------------------------------------------
// Kernel 0a: convert Q -> Qhi; K -> Khi; V -> Vhi (single fp16 each).
// ---------------------------------------------------------------------------
__global__ __launch_bounds__(256)
void prep_kernel(const float* __restrict__ q, const float* __restrict__ k,
                 const float* __restrict__ v)
{
    size_t i = (size_t)blockIdx.x * 256 + threadIdx.x;   // float4 index
    float4 qv = ((const float4*)q)[i];
    uint2 qh; cvt4(qv, qh);
    ((uint2*)g_qh)[i] = qh;

    float4 kv = ((const float4*)k)[i];
    uint2 kh; cvt4(kv, kh);
    ((uint2*)g_kh)[i] = kh;

    float4 vv = ((const float4*)v)[i];
    uint2 vh; cvt4(vv, vh);
    ((uint2*)g_vh)[i] = vh;
}

// ---------------------------------------------------------------------------
// Kernel 0b: pack mask (1,S,S) int32 0/1 -> bit table [S][64] uint32.
// Bit j of word w for row r = mask[r][w*32 + j].
// ---------------------------------------------------------------------------
__global__ __launch_bounds__(256)
void maskpack_kernel(const int* __restrict__ mask)
{
    int w = blockIdx.x * 256 + threadIdx.x;     // 0 .. SEQ*64-1
    int row = w >> 6, wc = w & 63;
    const int4* mp = (const int4*)(mask + (size_t)row * SEQ + wc * 32);
    uint32_t bits = 0;
#pragma unroll
    for (int j = 0; j < 8; j++) {
        int4 v = mp[j];
        bits |= ((uint32_t)(v.x != 0)) << (j * 4 + 0);
        bits |= ((uint32_t)(v.y != 0)) << (j * 4 + 1);
        bits |= ((uint32_t)(v.z != 0)) << (j * 4 + 2);
        bits |= ((uint32_t)(v.w != 0)) << (j * 4 + 3);
    }
    g_mbits[w] = bits;
}

// ---------------------------------------------------------------------------
// Kernel 1: E = mask ? exp(scale * Q@K^T) : 0  -> g_e (fp16) + partial sums.
// Single-pass fp16, 3-stage cp.async pipeline, bit-mask epilogue.
// Grid (16,16,BATCH), 256 threads, tile 128x128, 2 CTAs/SM.
// ---------------------------------------------------------------------------
__device__ __forceinline__ void k1_issue(uint32_t stg, const __half* qrow,
                                         const __half* khrow, int k0, int tid) {
#pragma unroll
    for (int j = 0; j < 2; j++) {
        int o = tid + j * 256;
        int row = o >> 2, c = o & 3;
        size_t goff = (size_t)row * DIM + k0 + c * 8;
        uint32_t soff = (uint32_t)(row * SA + c * 16);
        cpa16(stg + SC_A   + soff, qrow  + goff);
        cpa16(stg + SC_BHI + soff, khrow + goff);
    }
}

__global__ __launch_bounds__(256, 2)
void scores_tc()
{
    extern __shared__ char smem[];
    const uint32_t sbase = smem_u32(smem);
    const int tid  = threadIdx.x;
    const int lane = tid & 31;
    const int wid  = tid >> 5;
    const int wm = wid & 1, wn = wid >> 1;
    const int g = lane >> 2, t = lane & 3;
    const int b  = blockIdx.z;
    const int m0 = blockIdx.y * 128;
    const int n0 = blockIdx.x * 128;

    const __half* qb  = g_qh + (size_t)b * SEQ * DIM + (size_t)m0 * DIM;
    const __half* kbh = g_kh + (size_t)b * SEQ * DIM + (size_t)n0 * DIM;

    const int mBase = wm * 64;
    const int nBase = wn * 32;
    const uint32_t aRowOff = (uint32_t)(mBase + (lane & 15)) * SA + ((lane >> 4) << 4);
    const uint32_t bRowOff = (uint32_t)(nBase + (lane & 7) + ((lane >> 4) << 3)) * SA
                           + (((lane >> 3) & 1) << 4);

    float acc[4][4][4];
#pragma unroll
    for (int i = 0; i < 4; i++)
#pragma unroll
        for (int j = 0; j < 4; j++)
#pragma unroll
            for (int c = 0; c < 4; c++) acc[i][j][c] = 0.0f;

    k1_issue(sbase, qb, kbh, 0, tid); cpcommit();
    k1_issue(sbase + SC_STAGE, qb, kbh, BKC, tid); cpcommit();

    const int NC = DIM / BKC;   // 8
    int sc = 0;
    for (int c = 0; c < NC; c++) {
        if (c == NC - 1) cpwait<0>(); else cpwait<1>();
        __syncthreads();
        if (c + 2 < NC) {
            int sn = sc + 2; if (sn >= 3) sn -= 3;
            k1_issue(sbase + sn * SC_STAGE, qb, kbh, (c + 2) * BKC, tid);
            cpcommit();
        }
        const uint32_t stg = sbase + sc * SC_STAGE;
#pragma unroll
        for (int ks = 0; ks < 2; ks++) {
            const uint32_t kByte = (uint32_t)(ks * 32);
            uint32_t bh[4][2];
#pragma unroll
            for (int np = 0; np < 2; np++) {
                uint32_t addr = stg + SC_BHI + bRowOff + np * 16 * SA + kByte;
                uint32_t r0, r1, r2, r3;
                ldmx4(r0, r1, r2, r3, addr);
                bh[2*np][0] = r0; bh[2*np][1] = r1;
                bh[2*np+1][0] = r2; bh[2*np+1][1] = r3;
            }
#pragma unroll
            for (int mt = 0; mt < 4; mt++) {
                uint32_t addr = stg + SC_A + aRowOff + mt * 16 * SA + kByte;
                uint32_t ah[4];
                ldmx4(ah[0], ah[1], ah[2], ah[3], addr);
#pragma unroll
                for (int nt = 0; nt < 4; nt++) {
                    mma_f16(acc[mt][nt], ah, bh[nt][0], bh[nt][1]);
                }
            }
        }
        sc++; if (sc == 3) sc = 0;
    }

    // Epilogue: E = maskbit ? exp(scale*s) : 0 (fp16), plus partial row sums.
    __half* eb = g_e + (size_t)b * SEQ * SEQ;
    const int ztile = blockIdx.x * 4 + wn;
    const int word = (n0 + nBase) >> 5;        // one 32-bit mask word per warp col
#pragma unroll
    for (int mt = 0; mt < 4; mt++) {
        int r0 = m0 + mBase + mt * 16 + g;
        uint32_t w0 = g_mbits[r0 * 64 + word];
        uint32_t w1 = g_mbits[(r0 + 8) * 64 + word];
        float sum0 = 0.0f, sum1 = 0.0f;
#pragma unroll
        for (int nt = 0; nt < 4; nt++) {
            int col = n0 + nBase + nt * 8 + 2 * t;
            int bit = nt * 8 + 2 * t;
            float e00 = ((w0 >> bit) & 1u)       ? __expf(acc[mt][nt][0] * ATTN_SCALE) : 0.0f;
            float e01 = ((w0 >> (bit + 1)) & 1u) ? __expf(acc[mt][nt][1] * ATTN_SCALE) : 0.0f;
            float e10 = ((w1 >> bit) & 1u)       ? __expf(acc[mt][nt][2] * ATTN_SCALE) : 0.0f;
            float e11 = ((w1 >> (bit + 1)) & 1u) ? __expf(acc[mt][nt][3] * ATTN_SCALE) : 0.0f;
            sum0 += e00 + e01;
            sum1 += e10 + e11;
            __half2 p0 = __floats2half2_rn(e00, e01);
            __half2 p1 = __floats2half2_rn(e10, e11);
            *(__half2*)(eb + (size_t)r0 * SEQ + col) = p0;
            *(__half2*)(eb + (size_t)(r0 + 8) * SEQ + col) = p1;
        }
        sum0 += __shfl_xor_sync(0xFFFFFFFFu, sum0, 1);
        sum0 += __shfl_xor_sync(0xFFFFFFFFu, sum0, 2);
        sum1 += __shfl_xor_sync(0xFFFFFFFFu, sum1, 1);
        sum1 += __shfl_xor_sync(0xFFFFFFFFu, sum1, 2);
        if (t == 0) {
            g_zpart[((size_t)b * SEQ + r0) * 64 + ztile]     = sum0;
            g_zpart[((size_t)b * SEQ + r0 + 8) * 64 + ztile] = sum1;
        }
    }
}

// ---------------------------------------------------------------------------
// Kernel 2: invZ[row] = 1 / sum(zpart[row][0..63]).
// ---------------------------------------------------------------------------
__global__ __launch_bounds__(256)
void zreduce_kernel()
{
    int i = blockIdx.x * 256 + threadIdx.x;
    const float4* zp = (const float4*)(g_zpart + (size_t)i * 64);
    float s = 0.0f;
#pragma unroll
    for (int j = 0; j < 16; j++) {
        float4 v = zp[j];
        s += (v.x + v.y) + (v.z + v.w);
    }
    g_invz[i] = 1.0f / s;
}

// ---------------------------------------------------------------------------
// Kernel 3: O = (E @ Vhi) * invZ; BOTH x-CTAs write their 16-col half of
// attn = E * invZ per chunk, AFTER the mma block (drains in pipeline shadow).
// Grid (2,16,BATCH), 256 threads, tile 128x128, 2 CTAs/SM, 3-stage pipeline.
// ---------------------------------------------------------------------------
__device__ __forceinline__ void k3_issue(uint32_t stg, const __half* eb,
                                         const __half* vbh, int k0, int tid) {
#pragma unroll
    for (int j = 0; j < 2; j++) {
        int o = tid + j * 256;
        int erow = o >> 2, ec = o & 3;
        cpa16(stg + OV_A + erow * SA + ec * 16,
              eb + (size_t)erow * SEQ + k0 + ec * 8);
        int vrow = o >> 4, vc = o & 15;
        cpa16(stg + OV_VHI + vrow * SV + vc * 16,
              vbh + (size_t)(k0 + vrow) * DIM + vc * 8);
    }
}

__global__ __launch_bounds__(256, 2)
void out_fused(float* __restrict__ attn, float* __restrict__ o)
{
    extern __shared__ char smem[];
    const uint32_t sbase = smem_u32(smem);
    const int tid  = threadIdx.x;
    const int lane = tid & 31;
    const int wid  = tid >> 5;
    const int wm = wid & 1, wn = wid >> 1;
    const int g = lane >> 2, t = lane & 3;
    const int b  = blockIdx.z;
    const int m0 = blockIdx.y * 128;
    const int n0 = blockIdx.x * 128;
    const int phalf = blockIdx.x * 16;   // this CTA's 16-col half of each chunk

    const __half* eb  = g_e  + (size_t)b * SEQ * SEQ + (size_t)m0 * SEQ;
    const __half* vbh = g_vh + (size_t)b * SEQ * DIM + n0;
    float* pw = attn + (size_t)b * SEQ * SEQ + (size_t)m0 * SEQ;

    const int mBase = wm * 64;
    const int nBase = wn * 32;
    const uint32_t aRowOff = (uint32_t)(mBase + (lane & 15)) * SA + ((lane >> 4) << 4);
    const uint32_t vRow = (uint32_t)((lane & 7) + (((lane >> 3) & 1) << 3));
    const uint32_t vNOff = (uint32_t)(nBase + ((lane >> 4) << 3)) * 2;

    const int prow = tid >> 1;           // 0..127: P-write row (2 thr/row)
    const int ph   = tid & 1;            // 8-col quarter within this CTA's half
    const float izp = g_invz[(size_t)b * SEQ + m0 + prow];

    float acc[4][4][4];
#pragma unroll
    for (int i = 0; i < 4; i++)
#pragma unroll
        for (int j = 0; j < 4; j++)
#pragma unroll
            for (int c = 0; c < 4; c++) acc[i][j][c] = 0.0f;

    k3_issue(sbase, eb, vbh, 0, tid); cpcommit();
    k3_issue(sbase + OV_STAGE, eb, vbh, BKC, tid); cpcommit();

    const int NC = SEQ / BKC;   // 64
    int sc = 0;
    for (int c = 0; c < NC; c++) {
        if (c == NC - 1) cpwait<0>(); else cpwait<1>();
        __syncthreads();
        if (c + 2 < NC) {
            int sn = sc + 2; if (sn >= 3) sn -= 3;
            k3_issue(sbase + sn * OV_STAGE, eb, vbh, (c + 2) * BKC, tid);
            cpcommit();
        }
        const uint32_t stg = sbase + sc * OV_STAGE;

#pragma unroll
        for (int ks = 0; ks < 2; ks++) {
            uint32_t bh[4][2];
#pragma unroll
            for (int np = 0; np < 2; np++) {
                uint32_t addr = stg + OV_VHI + (ks * 16 + vRow) * SV + vNOff + np * 32;
                uint32_t r0, r1, r2, r3;
                ldmx4t(r0, r1, r2, r3, addr);
                bh[2*np][0] = r0; bh[2*np][1] = r1;
                bh[2*np+1][0] = r2; bh[2*np+1][1] = r3;
            }
#pragma unroll
            for (int mt = 0; mt < 4; mt++) {
                uint32_t addr = stg + OV_A + aRowOff + mt * 16 * SA + ks * 32;
                uint32_t ah[4];
                ldmx4(ah[0], ah[1], ah[2], ah[3], addr);
#pragma unroll
                for (int nt = 0; nt < 4; nt++) {
                    mma_f16(acc[mt][nt], ah, bh[nt][0], bh[nt][1]);
                }
            }
        }

        // Write this CTA's 16-col half of normalized P for chunk c (deferred:
        // stage sc stays valid until the issue after the NEXT barrier, and the
        // LDS below completes before that barrier).
        {
            const char* ep = smem + sc * OV_STAGE + OV_A + prow * SA
                           + (phalf + ph * 8) * 2;
            uint4 e4 = *(const uint4*)ep;           // 8 halfs
            __half2* hp = (__half2*)&e4;
            float2 f0 = __half22float2(hp[0]);
            float2 f1 = __half22float2(hp[1]);
            float2 f2 = __half22float2(hp[2]);
            float2 f3 = __half22float2(hp[3]);
            float* dst = pw + (size_t)prow * SEQ + c * BKC + phalf + ph * 8;
            *(float4*)dst =
                make_float4(f0.x * izp, f0.y * izp, f1.x * izp, f1.y * izp);
            *(float4*)(dst + 4) =
                make_float4(f2.x * izp, f2.y * izp, f3.x * izp, f3.y * izp);
        }

        sc++; if (sc == 3) sc = 0;
    }

    // Epilogue: O = acc * invZ[row]
    float* ob = o + (size_t)b * SEQ * DIM;
#pragma unroll
    for (int mt = 0; mt < 4; mt++) {
        int r0 = m0 + mBase + mt * 16 + g;
        float z0 = g_invz[(size_t)b * SEQ + r0];
        float z1 = g_invz[(size_t)b * SEQ + r0 + 8];
#pragma unroll
        for (int nt = 0; nt < 4; nt++) {
            int col = n0 + nBase + nt * 8 + 2 * t;
            *(float2*)(ob + (size_t)r0 * DIM + col) =
                make_float2(acc[mt][nt][0] * z0, acc[mt][nt][1] * z0);
            *(float2*)(ob + (size_t)(r0 + 8) * DIM + col) =
                make_float2(acc[mt][nt][2] * z1, acc[mt][nt][3] * z1);
        }
    }
}

// ---------------------------------------------------------------------------
extern "C" void kernel_launch(void* const* d_in, const int* in_sizes, int n_in,
                              void* d_out, int out_size)
{
    const float* q    = (const float*)d_in[0];
    const float* k    = (const float*)d_in[1];
    const float* v    = (const float*)d_in[2];
    const int*   mask = (const int*)d_in[3];

    float* out  = (float*)d_out;                      // [B, S, D]
    float* attn = out + (size_t)BATCH * SEQ * DIM;    // [B, S, S]

    cudaFuncSetAttribute(scores_tc, cudaFuncAttributeMaxDynamicSharedMemorySize, SC_SMEM);
    cudaFuncSetAttribute(out_fused, cudaFuncAttributeMaxDynamicSharedMemorySize, OV_SMEM);

    prep_kernel<<<(BATCH * SEQ * DIM / 4) / 256, 256>>>(q, k, v);
    maskpack_kernel<<<SEQ * 64 / 256, 256>>>(mask);
    scores_tc<<<dim3(SEQ / 128, SEQ / 128, BATCH), 256, SC_SMEM>>>();
    zreduce_kernel<<<BATCH * SEQ / 256, 256>>>();
    out_fused<<<dim3(2, SEQ / 128, BATCH), 256, OV_SMEM>>>(attn, out);
}